// round 2
// baseline (speedup 1.0000x reference)
#include <cuda_runtime.h>
#include <math.h>

// ---------------------------------------------------------------------------
// DeltaNet layer, B=8, T=2048, D=512, fp32.
//  1. Q = x@Wq^T+bq, Kraw = x@Wk^T+bk, V = x@Wv^T+bv      (gemm_bias x3)
//  2. K = l2norm(Kraw); Beta = sigmoid(K@Wbeta^T+bbeta)    (norm_beta)
//  3. per (batch,chunk=64): A[t][j]=beta_t*(k_t.k_j) j<t;
//                           G[t][j]=(q_t.k_j) j<=t          (chunk_ag)
//  4. chunked delta-rule scan, S slice (32x512) in smem,
//     grid = 8 batches x 16 V-tiles                         (scan)
//  5. out = O@Wo^T + bo                                     (gemm_bias)
// ---------------------------------------------------------------------------

namespace {
constexpr int Bb  = 8;
constexpr int Tt  = 2048;
constexpr int Dd  = 512;
constexpr int BT  = Bb * Tt;
constexpr int CH  = 64;
constexpr int NCH = Tt / CH;   // 32
constexpr int DV  = 32;
constexpr int NVT = Dd / DV;   // 16
// scan smem layout (float offsets)
constexpr int SM_S    = 0;
constexpr int SM_KT   = SM_S  + 32 * 512;
constexpr int SM_QT   = SM_KT + 64 * 129;
constexpr int SM_A    = SM_QT + 64 * 129;
constexpr int SM_G    = SM_A  + 64 * 65;
constexpr int SM_U    = SM_G  + 64 * 65;
constexpr int SM_QS   = SM_U  + 64 * 33;
constexpr int SM_VB   = SM_QS + 64 * 33;
constexpr int SM_BETA = SM_VB + 64 * 33;
constexpr int SM_TOT  = SM_BETA + 64;
constexpr int SMEM_BYTES = SM_TOT * 4;   // 190464 bytes
}

// static scratch (no cudaMalloc allowed)
__device__ float g_Q[BT * Dd];
__device__ float g_K[BT * Dd];
__device__ float g_V[BT * Dd];
__device__ float g_O[BT * Dd];
__device__ float g_Beta[BT];
__device__ float g_A[Bb * NCH * CH * CH];
__device__ float g_G[Bb * NCH * CH * CH];

// ---------------------------------------------------------------------------
// C[m][n] = sum_k A[m][k]*W[n][k] + bias[n]   (NT GEMM) BM=BN=128, BK=8
// ---------------------------------------------------------------------------
__global__ __launch_bounds__(256) void gemm_bias_kernel(
    const float* __restrict__ A, const float* __restrict__ W,
    const float* __restrict__ bias, float* __restrict__ C,
    int M, int N, int K)
{
    constexpr int BK = 8;
    __shared__ float As[BK][128];
    __shared__ float Bs[BK][128];

    const int tid = threadIdx.x;
    const int bm = blockIdx.y * 128;
    const int bn = blockIdx.x * 128;
    const int tx = tid & 15;
    const int ty = tid >> 4;

    float acc[8][8];
#pragma unroll
    for (int i = 0; i < 8; i++)
#pragma unroll
        for (int j = 0; j < 8; j++) acc[i][j] = 0.f;

    const int lrow = tid >> 1;
    const int lcol = (tid & 1) * 4;
    const float* Aptr = A + (size_t)(bm + lrow) * K + lcol;
    const float* Wptr = W + (size_t)(bn + lrow) * K + lcol;

    for (int k0 = 0; k0 < K; k0 += BK) {
        float4 av = *(const float4*)(Aptr + k0);
        float4 wv = *(const float4*)(Wptr + k0);
        __syncthreads();
        As[lcol + 0][lrow] = av.x; As[lcol + 1][lrow] = av.y;
        As[lcol + 2][lrow] = av.z; As[lcol + 3][lrow] = av.w;
        Bs[lcol + 0][lrow] = wv.x; Bs[lcol + 1][lrow] = wv.y;
        Bs[lcol + 2][lrow] = wv.z; Bs[lcol + 3][lrow] = wv.w;
        __syncthreads();
#pragma unroll
        for (int kk = 0; kk < BK; kk++) {
            float ar[8], br[8];
            *(float4*)&ar[0] = *(const float4*)&As[kk][ty * 8];
            *(float4*)&ar[4] = *(const float4*)&As[kk][ty * 8 + 4];
            *(float4*)&br[0] = *(const float4*)&Bs[kk][tx * 8];
            *(float4*)&br[4] = *(const float4*)&Bs[kk][tx * 8 + 4];
#pragma unroll
            for (int i = 0; i < 8; i++)
#pragma unroll
                for (int j = 0; j < 8; j++)
                    acc[i][j] += ar[i] * br[j];
        }
    }

#pragma unroll
    for (int i = 0; i < 8; i++) {
        const int row = bm + ty * 8 + i;
#pragma unroll
        for (int j = 0; j < 8; j += 4) {
            float4 o;
            o.x = acc[i][j + 0] + bias[bn + tx * 8 + j + 0];
            o.y = acc[i][j + 1] + bias[bn + tx * 8 + j + 1];
            o.z = acc[i][j + 2] + bias[bn + tx * 8 + j + 2];
            o.w = acc[i][j + 3] + bias[bn + tx * 8 + j + 3];
            *(float4*)&C[(size_t)row * N + bn + tx * 8 + j] = o;
        }
    }
}

// ---------------------------------------------------------------------------
// in-place l2-normalize rows of K; Beta = sigmoid(Knorm . wbeta + bb)
// ---------------------------------------------------------------------------
__global__ __launch_bounds__(128) void norm_beta_kernel(
    float* __restrict__ Kd, const float* __restrict__ wb,
    const float* __restrict__ bb, float* __restrict__ Beta)
{
    const int row = blockIdx.x;
    const int tid = threadIdx.x;
    float4 v = ((const float4*)(Kd + (size_t)row * Dd))[tid];

    float ss = v.x * v.x + v.y * v.y + v.z * v.z + v.w * v.w;
#pragma unroll
    for (int o = 16; o; o >>= 1) ss += __shfl_xor_sync(0xffffffffu, ss, o);
    __shared__ float red1[4];
    if ((tid & 31) == 0) red1[tid >> 5] = ss;
    __syncthreads();
    const float tot = red1[0] + red1[1] + red1[2] + red1[3];
    const float inv = 1.0f / fmaxf(sqrtf(tot), 1e-12f);

    float4 w = ((const float4*)wb)[tid];
    float bd = v.x * w.x + v.y * w.y + v.z * w.z + v.w * w.w;
#pragma unroll
    for (int o = 16; o; o >>= 1) bd += __shfl_xor_sync(0xffffffffu, bd, o);
    __shared__ float red2[4];
    if ((tid & 31) == 0) red2[tid >> 5] = bd;
    __syncthreads();

    v.x *= inv; v.y *= inv; v.z *= inv; v.w *= inv;
    ((float4*)(Kd + (size_t)row * Dd))[tid] = v;

    if (tid == 0) {
        const float z = (red2[0] + red2[1] + red2[2] + red2[3]) * inv + bb[0];
        Beta[row] = 1.0f / (1.0f + expf(-z));
    }
}

// ---------------------------------------------------------------------------
// per (batch, chunk): A[t][j]=beta_t*(k_t.k_j) j<t; G[t][j]=(q_t.k_j) j<=t
// grid (NCH, Bb), 256 threads, 4x4 per thread, d tiled by 64
// ---------------------------------------------------------------------------
__global__ __launch_bounds__(256) void chunk_ag_kernel(
    const float* __restrict__ Qd, const float* __restrict__ Kd,
    const float* __restrict__ Beta, float* __restrict__ Ag,
    float* __restrict__ Gg)
{
    const int c = blockIdx.x, b = blockIdx.y;
    const int r0 = b * Tt + c * CH;
    __shared__ float Ks[64 * 65];
    __shared__ float Qs[64 * 65];

    const int tid = threadIdx.x;
    const int t0 = (tid >> 4) * 4;
    const int j0 = (tid & 15) * 4;

    float accA[4][4], accG[4][4];
#pragma unroll
    for (int i = 0; i < 4; i++)
#pragma unroll
        for (int j = 0; j < 4; j++) { accA[i][j] = 0.f; accG[i][j] = 0.f; }

    for (int dt = 0; dt < 8; dt++) {
        __syncthreads();
#pragma unroll
        for (int n = 0; n < 4; n++) {
            const int f4 = tid + n * 256;
            const int row = f4 >> 4, col = (f4 & 15) * 4;
            float4 kv = *(const float4*)&Kd[(size_t)(r0 + row) * Dd + dt * 64 + col];
            float4 qv = *(const float4*)&Qd[(size_t)(r0 + row) * Dd + dt * 64 + col];
            const int so = row * 65 + col;
            Ks[so] = kv.x; Ks[so + 1] = kv.y; Ks[so + 2] = kv.z; Ks[so + 3] = kv.w;
            Qs[so] = qv.x; Qs[so + 1] = qv.y; Qs[so + 2] = qv.z; Qs[so + 3] = qv.w;
        }
        __syncthreads();
#pragma unroll 4
        for (int dd = 0; dd < 64; dd++) {
            float kt[4], kj[4], qt[4];
#pragma unroll
            for (int i = 0; i < 4; i++) {
                kt[i] = Ks[(t0 + i) * 65 + dd];
                qt[i] = Qs[(t0 + i) * 65 + dd];
                kj[i] = Ks[(j0 + i) * 65 + dd];
            }
#pragma unroll
            for (int i = 0; i < 4; i++)
#pragma unroll
                for (int j = 0; j < 4; j++) {
                    accA[i][j] += kt[i] * kj[j];
                    accG[i][j] += qt[i] * kj[j];
                }
        }
    }

    const size_t base = ((size_t)(b * NCH) + c) * (CH * CH);
#pragma unroll
    for (int i = 0; i < 4; i++) {
        const int t = t0 + i;
        const float bt = Beta[r0 + t];
#pragma unroll
        for (int j = 0; j < 4; j++) {
            const int jj = j0 + j;
            Ag[base + t * CH + jj] = (jj < t) ? bt * accA[i][j] : 0.f;
            Gg[base + t * CH + jj] = (jj <= t) ? accG[i][j] : 0.f;
        }
    }
}

// ---------------------------------------------------------------------------
// chunked delta-rule scan. grid (NVT, Bb), 256 threads, dyn smem.
// ---------------------------------------------------------------------------
__global__ __launch_bounds__(256) void scan_kernel(
    const float* __restrict__ Qd, const float* __restrict__ Kd,
    const float* __restrict__ Vd, const float* __restrict__ Betad,
    const float* __restrict__ Ag, const float* __restrict__ Gg,
    float* __restrict__ Od)
{
    extern __shared__ float sm[];
    float* S     = sm + SM_S;     // [32][512]
    float* Kt    = sm + SM_KT;    // [64][129]
    float* Qt    = sm + SM_QT;    // [64][129]
    float* As    = sm + SM_A;     // [64][65]
    float* Gs    = sm + SM_G;     // [64][65]
    float* Um    = sm + SM_U;     // [64][33]
    float* QSm   = sm + SM_QS;    // [64][33]
    float* Vb    = sm + SM_VB;    // [64][33]
    float* betas = sm + SM_BETA;  // [64]

    const int b = blockIdx.y;
    const int i0 = blockIdx.x * DV;
    const int tid = threadIdx.x;
    const int lane = tid & 31;
    const int wid = tid >> 5;

    for (int e = tid; e < 32 * 512; e += 256) S[e] = 0.f;
    __syncthreads();

    for (int c = 0; c < NCH; c++) {
        const int r0 = b * Tt + c * CH;
        const size_t agbase = ((size_t)(b * NCH) + c) * (CH * CH);

        // ---- stage A, G, V slice, beta ----
        for (int e = tid; e < CH * CH; e += 256) {
            const int t = e >> 6, j = e & 63;
            As[t * 65 + j] = Ag[agbase + e];
            Gs[t * 65 + j] = Gg[agbase + e];
        }
        for (int e = tid; e < CH * DV; e += 256) {
            const int t = e >> 5, i = e & 31;
            Vb[t * 33 + i] = Vd[(size_t)(r0 + t) * Dd + i0 + i];
        }
        if (tid < 64) betas[tid] = Betad[r0 + tid];
        __syncthreads();

        // ---- Phase A: KS = K@S^T, QS = Q@S^T (64 x 32 each) ----
        const int t0 = lane * 2;
        const int ii = wid * 4;
        float aKS[2][4], aQS[2][4];
#pragma unroll
        for (int r = 0; r < 2; r++)
#pragma unroll
            for (int i = 0; i < 4; i++) { aKS[r][i] = 0.f; aQS[r][i] = 0.f; }

        for (int jt = 0; jt < 4; jt++) {
            __syncthreads();
#pragma unroll
            for (int n = 0; n < 8; n++) {
                const int f4 = tid + n * 256;
                const int row = f4 >> 5;
                const int col = (f4 & 31) * 4;
                float4 kv = *(const float4*)&Kd[(size_t)(r0 + row) * Dd + jt * 128 + col];
                float4 qv = *(const float4*)&Qd[(size_t)(r0 + row) * Dd + jt * 128 + col];
                const int so = row * 129 + col;
                Kt[so] = kv.x; Kt[so + 1] = kv.y; Kt[so + 2] = kv.z; Kt[so + 3] = kv.w;
                Qt[so] = qv.x; Qt[so + 1] = qv.y; Qt[so + 2] = qv.z; Qt[so + 3] = qv.w;
            }
            __syncthreads();
            const float* Sp  = S + ii * 512 + jt * 128;
            const float* kp0 = Kt + t0 * 129;
            const float* kp1 = Kt + (t0 + 1) * 129;
            const float* qp0 = Qt + t0 * 129;
            const float* qp1 = Qt + (t0 + 1) * 129;
#pragma unroll 4
            for (int dd = 0; dd < 128; dd++) {
                const float k0 = kp0[dd], k1 = kp1[dd];
                const float q0 = qp0[dd], q1 = qp1[dd];
#pragma unroll
                for (int i = 0; i < 4; i++) {
                    const float sv = Sp[i * 512 + dd];
                    aKS[0][i] += k0 * sv;
                    aKS[1][i] += k1 * sv;
                    aQS[0][i] += q0 * sv;
                    aQS[1][i] += q1 * sv;
                }
            }
        }
        __syncthreads();
        // rhs for U and QS into smem
#pragma unroll
        for (int r = 0; r < 2; r++) {
            const int t = t0 + r;
            const float bt = betas[t];
#pragma unroll
            for (int i = 0; i < 4; i++) {
                Um[t * 33 + ii + i] = bt * (Vb[t * 33 + ii + i] - aKS[r][i]);
                QSm[t * 33 + ii + i] = aQS[r][i];
            }
        }
        __syncthreads();

        // ---- Phase B: blocked forward substitution (block 16) ----
#pragma unroll
        for (int blk = 0; blk < 4; blk++) {
            const int bt0 = blk * 16;
            if (wid == 0) {
                for (int t = bt0; t < bt0 + 16; t++) {
                    float s = Um[t * 33 + lane];
                    for (int j = bt0; j < t; j++)
                        s -= As[t * 65 + j] * Um[j * 33 + lane];
                    Um[t * 33 + lane] = s;
                }
            }
            __syncthreads();
            if (blk < 3) {
                const int rem = 64 - (blk + 1) * 16;
                for (int e = tid; e < rem * 32; e += 256) {
                    const int t = (blk + 1) * 16 + (e >> 5);
                    const int i = e & 31;
                    float s = Um[t * 33 + i];
#pragma unroll
                    for (int j = 0; j < 16; j++)
                        s -= As[t * 65 + bt0 + j] * Um[(bt0 + j) * 33 + i];
                    Um[t * 33 + i] = s;
                }
                __syncthreads();
            }
        }

        // ---- Phase C: O = QS + tril(G) @ U ----
        for (int e = tid; e < CH * DV; e += 256) {
            const int t = e >> 5, i = e & 31;
            float s = QSm[t * 33 + i];
            for (int j = 0; j <= t; j++)
                s += Gs[t * 65 + j] * Um[j * 33 + i];
            Od[(size_t)(r0 + t) * Dd + i0 + i] = s;
        }

        // ---- Phase D: S += U^T @ K  (rank-64 update) ----
        for (int jt = 0; jt < 4; jt++) {
            __syncthreads();
#pragma unroll
            for (int n = 0; n < 8; n++) {
                const int f4 = tid + n * 256;
                const int row = f4 >> 5;
                const int col = (f4 & 31) * 4;
                float4 kv = *(const float4*)&Kd[(size_t)(r0 + row) * Dd + jt * 128 + col];
                const int so = row * 129 + col;
                Kt[so] = kv.x; Kt[so + 1] = kv.y; Kt[so + 2] = kv.z; Kt[so + 3] = kv.w;
            }
            __syncthreads();
            float sacc[4][4];
#pragma unroll
            for (int ig = 0; ig < 4; ig++)
#pragma unroll
                for (int g = 0; g < 4; g++)
                    sacc[ig][g] = S[(ii + ig) * 512 + jt * 128 + g * 32 + lane];
#pragma unroll 4
            for (int t = 0; t < 64; t++) {
                float uu[4], kk[4];
#pragma unroll
                for (int ig = 0; ig < 4; ig++) uu[ig] = Um[t * 33 + ii + ig];
#pragma unroll
                for (int g = 0; g < 4; g++) kk[g] = Kt[t * 129 + g * 32 + lane];
#pragma unroll
                for (int ig = 0; ig < 4; ig++)
#pragma unroll
                    for (int g = 0; g < 4; g++)
                        sacc[ig][g] += uu[ig] * kk[g];
            }
#pragma unroll
            for (int ig = 0; ig < 4; ig++)
#pragma unroll
                for (int g = 0; g < 4; g++)
                    S[(ii + ig) * 512 + jt * 128 + g * 32 + lane] = sacc[ig][g];
        }
        __syncthreads();
    }
}

// ---------------------------------------------------------------------------
extern "C" void kernel_launch(void* const* d_in, const int* in_sizes, int n_in,
                              void* d_out, int out_size)
{
    const float* x     = (const float*)d_in[0];
    const float* Wq    = (const float*)d_in[1];
    const float* bq    = (const float*)d_in[2];
    const float* Wk    = (const float*)d_in[3];
    const float* bk    = (const float*)d_in[4];
    const float* Wv    = (const float*)d_in[5];
    const float* bv    = (const float*)d_in[6];
    const float* Wbeta = (const float*)d_in[7];
    const float* bbeta = (const float*)d_in[8];
    const float* Wo    = (const float*)d_in[9];
    const float* bo    = (const float*)d_in[10];
    float* out = (float*)d_out;

    float *pQ, *pK, *pV, *pO, *pBeta, *pA, *pG;
    cudaGetSymbolAddress((void**)&pQ, g_Q);
    cudaGetSymbolAddress((void**)&pK, g_K);
    cudaGetSymbolAddress((void**)&pV, g_V);
    cudaGetSymbolAddress((void**)&pO, g_O);
    cudaGetSymbolAddress((void**)&pBeta, g_Beta);
    cudaGetSymbolAddress((void**)&pA, g_A);
    cudaGetSymbolAddress((void**)&pG, g_G);

    cudaFuncSetAttribute(scan_kernel,
                         cudaFuncAttributeMaxDynamicSharedMemorySize, SMEM_BYTES);

    dim3 ggrid(Dd / 128, BT / 128);   // (4, 128)
    gemm_bias_kernel<<<ggrid, 256>>>(x, Wq, bq, pQ, BT, Dd, Dd);
    gemm_bias_kernel<<<ggrid, 256>>>(x, Wk, bk, pK, BT, Dd, Dd);
    gemm_bias_kernel<<<ggrid, 256>>>(x, Wv, bv, pV, BT, Dd, Dd);

    norm_beta_kernel<<<BT, 128>>>(pK, Wbeta, bbeta, pBeta);

    chunk_ag_kernel<<<dim3(NCH, Bb), 256>>>(pQ, pK, pBeta, pA, pG);

    scan_kernel<<<dim3(NVT, Bb), 256, SMEM_BYTES>>>(pQ, pK, pV, pBeta, pA, pG, pO);

    gemm_bias_kernel<<<ggrid, 256>>>(pO, Wo, bo, out, BT, Dd, Dd);
}

// round 3
// speedup vs baseline: 1.5922x; 1.5922x over previous
#include <cuda_runtime.h>
#include <math.h>

// ---------------------------------------------------------------------------
// DeltaNet layer, B=8, T=2048, D=512, fp32.
//  1. Q = x@Wq^T+bq, Kraw = x@Wk^T+bk, V = x@Wv^T+bv      (gemm_bias x3)
//  2. K = l2norm(Kraw); Beta = sigmoid(K@Wbeta^T+bbeta)    (norm_beta)
//  3. per (batch,chunk=64): A[t][j]=beta_t*(k_t.k_j) j<t;
//                           G[t][j]=(q_t.k_j) j<=t          (chunk_ag)
//  4. chunked delta-rule scan, S slice (32x512) in smem,
//     grid = 8 batches x 16 V-tiles                         (scan)
//  5. out = O@Wo^T + bo                                     (gemm_bias)
// ---------------------------------------------------------------------------

namespace {
constexpr int Bb  = 8;
constexpr int Tt  = 2048;
constexpr int Dd  = 512;
constexpr int BT  = Bb * Tt;
constexpr int CH  = 64;
constexpr int NCH = Tt / CH;   // 32
constexpr int DV  = 32;
constexpr int NVT = Dd / DV;   // 16
// scan smem layout (float offsets)
constexpr int SM_S    = 0;
constexpr int SM_KT   = SM_S  + 32 * 512;
constexpr int SM_QT   = SM_KT + 64 * 129;
constexpr int SM_A    = SM_QT + 64 * 129;
constexpr int SM_G    = SM_A  + 64 * 65;
constexpr int SM_U    = SM_G  + 64 * 65;
constexpr int SM_QS   = SM_U  + 64 * 33;
constexpr int SM_VB   = SM_QS + 64 * 33;
constexpr int SM_BETA = SM_VB + 64 * 33;
constexpr int SM_TOT  = SM_BETA + 64;
constexpr int SMEM_BYTES = SM_TOT * 4;   // 190464 bytes
}

// static scratch (no cudaMalloc allowed)
__device__ float g_Q[BT * Dd];
__device__ float g_K[BT * Dd];
__device__ float g_V[BT * Dd];
__device__ float g_O[BT * Dd];
__device__ float g_Beta[BT];
__device__ float g_A[Bb * NCH * CH * CH];
__device__ float g_G[Bb * NCH * CH * CH];

// ---------------------------------------------------------------------------
// C[m][n] = sum_k A[m][k]*W[n][k] + bias[n]   (NT GEMM) BM=BN=128, BK=8
// ---------------------------------------------------------------------------
__global__ __launch_bounds__(256) void gemm_bias_kernel(
    const float* __restrict__ A, const float* __restrict__ W,
    const float* __restrict__ bias, float* __restrict__ C,
    int M, int N, int K)
{
    constexpr int BK = 8;
    __shared__ float As[BK][128];
    __shared__ float Bs[BK][128];

    const int tid = threadIdx.x;
    const int bm = blockIdx.y * 128;
    const int bn = blockIdx.x * 128;
    const int tx = tid & 15;
    const int ty = tid >> 4;

    float acc[8][8];
#pragma unroll
    for (int i = 0; i < 8; i++)
#pragma unroll
        for (int j = 0; j < 8; j++) acc[i][j] = 0.f;

    const int lrow = tid >> 1;
    const int lcol = (tid & 1) * 4;
    const float* Aptr = A + (size_t)(bm + lrow) * K + lcol;
    const float* Wptr = W + (size_t)(bn + lrow) * K + lcol;

    for (int k0 = 0; k0 < K; k0 += BK) {
        float4 av = *(const float4*)(Aptr + k0);
        float4 wv = *(const float4*)(Wptr + k0);
        __syncthreads();
        As[lcol + 0][lrow] = av.x; As[lcol + 1][lrow] = av.y;
        As[lcol + 2][lrow] = av.z; As[lcol + 3][lrow] = av.w;
        Bs[lcol + 0][lrow] = wv.x; Bs[lcol + 1][lrow] = wv.y;
        Bs[lcol + 2][lrow] = wv.z; Bs[lcol + 3][lrow] = wv.w;
        __syncthreads();
#pragma unroll
        for (int kk = 0; kk < BK; kk++) {
            float ar[8], br[8];
            *(float4*)&ar[0] = *(const float4*)&As[kk][ty * 8];
            *(float4*)&ar[4] = *(const float4*)&As[kk][ty * 8 + 4];
            *(float4*)&br[0] = *(const float4*)&Bs[kk][tx * 8];
            *(float4*)&br[4] = *(const float4*)&Bs[kk][tx * 8 + 4];
#pragma unroll
            for (int i = 0; i < 8; i++)
#pragma unroll
                for (int j = 0; j < 8; j++)
                    acc[i][j] += ar[i] * br[j];
        }
    }

#pragma unroll
    for (int i = 0; i < 8; i++) {
        const int row = bm + ty * 8 + i;
#pragma unroll
        for (int j = 0; j < 8; j += 4) {
            float4 o;
            o.x = acc[i][j + 0] + bias[bn + tx * 8 + j + 0];
            o.y = acc[i][j + 1] + bias[bn + tx * 8 + j + 1];
            o.z = acc[i][j + 2] + bias[bn + tx * 8 + j + 2];
            o.w = acc[i][j + 3] + bias[bn + tx * 8 + j + 3];
            *(float4*)&C[(size_t)row * N + bn + tx * 8 + j] = o;
        }
    }
}

// ---------------------------------------------------------------------------
// in-place l2-normalize rows of K; Beta = sigmoid(Knorm . wbeta + bb)
// ---------------------------------------------------------------------------
__global__ __launch_bounds__(128) void norm_beta_kernel(
    float* __restrict__ Kd, const float* __restrict__ wb,
    const float* __restrict__ bb, float* __restrict__ Beta)
{
    const int row = blockIdx.x;
    const int tid = threadIdx.x;
    float4 v = ((const float4*)(Kd + (size_t)row * Dd))[tid];

    float ss = v.x * v.x + v.y * v.y + v.z * v.z + v.w * v.w;
#pragma unroll
    for (int o = 16; o; o >>= 1) ss += __shfl_xor_sync(0xffffffffu, ss, o);
    __shared__ float red1[4];
    if ((tid & 31) == 0) red1[tid >> 5] = ss;
    __syncthreads();
    const float tot = red1[0] + red1[1] + red1[2] + red1[3];
    const float inv = 1.0f / fmaxf(sqrtf(tot), 1e-12f);

    float4 w = ((const float4*)wb)[tid];
    float bd = v.x * w.x + v.y * w.y + v.z * w.z + v.w * w.w;
#pragma unroll
    for (int o = 16; o; o >>= 1) bd += __shfl_xor_sync(0xffffffffu, bd, o);
    __shared__ float red2[4];
    if ((tid & 31) == 0) red2[tid >> 5] = bd;
    __syncthreads();

    v.x *= inv; v.y *= inv; v.z *= inv; v.w *= inv;
    ((float4*)(Kd + (size_t)row * Dd))[tid] = v;

    if (tid == 0) {
        const float z = (red2[0] + red2[1] + red2[2] + red2[3]) * inv + bb[0];
        Beta[row] = 1.0f / (1.0f + expf(-z));
    }
}

// ---------------------------------------------------------------------------
// per (batch, chunk): A[t][j]=beta_t*(k_t.k_j) j<t; G[t][j]=(q_t.k_j) j<=t
// grid (NCH, Bb), 256 threads, 4x4 per thread, d tiled by 64
// ---------------------------------------------------------------------------
__global__ __launch_bounds__(256) void chunk_ag_kernel(
    const float* __restrict__ Qd, const float* __restrict__ Kd,
    const float* __restrict__ Beta, float* __restrict__ Ag,
    float* __restrict__ Gg)
{
    const int c = blockIdx.x, b = blockIdx.y;
    const int r0 = b * Tt + c * CH;
    __shared__ float Ks[64 * 65];
    __shared__ float Qs[64 * 65];

    const int tid = threadIdx.x;
    const int t0 = (tid >> 4) * 4;
    const int j0 = (tid & 15) * 4;

    float accA[4][4], accG[4][4];
#pragma unroll
    for (int i = 0; i < 4; i++)
#pragma unroll
        for (int j = 0; j < 4; j++) { accA[i][j] = 0.f; accG[i][j] = 0.f; }

    for (int dt = 0; dt < 8; dt++) {
        __syncthreads();
#pragma unroll
        for (int n = 0; n < 4; n++) {
            const int f4 = tid + n * 256;
            const int row = f4 >> 4, col = (f4 & 15) * 4;
            float4 kv = *(const float4*)&Kd[(size_t)(r0 + row) * Dd + dt * 64 + col];
            float4 qv = *(const float4*)&Qd[(size_t)(r0 + row) * Dd + dt * 64 + col];
            const int so = row * 65 + col;
            Ks[so] = kv.x; Ks[so + 1] = kv.y; Ks[so + 2] = kv.z; Ks[so + 3] = kv.w;
            Qs[so] = qv.x; Qs[so + 1] = qv.y; Qs[so + 2] = qv.z; Qs[so + 3] = qv.w;
        }
        __syncthreads();
#pragma unroll 4
        for (int dd = 0; dd < 64; dd++) {
            float kt[4], kj[4], qt[4];
#pragma unroll
            for (int i = 0; i < 4; i++) {
                kt[i] = Ks[(t0 + i) * 65 + dd];
                qt[i] = Qs[(t0 + i) * 65 + dd];
                kj[i] = Ks[(j0 + i) * 65 + dd];
            }
#pragma unroll
            for (int i = 0; i < 4; i++)
#pragma unroll
                for (int j = 0; j < 4; j++) {
                    accA[i][j] += kt[i] * kj[j];
                    accG[i][j] += qt[i] * kj[j];
                }
        }
    }

    const size_t base = ((size_t)(b * NCH) + c) * (CH * CH);
#pragma unroll
    for (int i = 0; i < 4; i++) {
        const int t = t0 + i;
        const float bt = Beta[r0 + t];
#pragma unroll
        for (int j = 0; j < 4; j++) {
            const int jj = j0 + j;
            Ag[base + t * CH + jj] = (jj < t) ? bt * accA[i][j] : 0.f;
            Gg[base + t * CH + jj] = (jj <= t) ? accG[i][j] : 0.f;
        }
    }
}

// ---------------------------------------------------------------------------
// chunked delta-rule scan. grid (NVT, Bb), 256 threads, dyn smem.
// ---------------------------------------------------------------------------
__global__ __launch_bounds__(256) void scan_kernel(
    const float* __restrict__ Qd, const float* __restrict__ Kd,
    const float* __restrict__ Vd, const float* __restrict__ Betad,
    const float* __restrict__ Ag, const float* __restrict__ Gg,
    float* __restrict__ Od)
{
    extern __shared__ float sm[];
    float* S     = sm + SM_S;     // [32][512]
    float* Kt    = sm + SM_KT;    // [64][129]
    float* Qt    = sm + SM_QT;    // [64][129]
    float* As    = sm + SM_A;     // [64][65]
    float* Gs    = sm + SM_G;     // [64][65]
    float* Um    = sm + SM_U;     // [64][33]
    float* QSm   = sm + SM_QS;    // [64][33]
    float* Vb    = sm + SM_VB;    // [64][33]
    float* betas = sm + SM_BETA;  // [64]

    const int b = blockIdx.y;
    const int i0 = blockIdx.x * DV;
    const int tid = threadIdx.x;
    const int lane = tid & 31;
    const int wid = tid >> 5;

    for (int e = tid; e < 32 * 512; e += 256) S[e] = 0.f;
    __syncthreads();

    for (int c = 0; c < NCH; c++) {
        const int r0 = b * Tt + c * CH;
        const size_t agbase = ((size_t)(b * NCH) + c) * (CH * CH);

        // ---- stage A, G, V slice, beta ----
        for (int e = tid; e < CH * CH; e += 256) {
            const int t = e >> 6, j = e & 63;
            As[t * 65 + j] = Ag[agbase + e];
            Gs[t * 65 + j] = Gg[agbase + e];
        }
        for (int e = tid; e < CH * DV; e += 256) {
            const int t = e >> 5, i = e & 31;
            Vb[t * 33 + i] = Vd[(size_t)(r0 + t) * Dd + i0 + i];
        }
        if (tid < 64) betas[tid] = Betad[r0 + tid];
        __syncthreads();

        // ---- Phase A: KS = K@S^T, QS = Q@S^T (64 x 32 each) ----
        const int t0 = lane * 2;
        const int ii = wid * 4;
        float aKS[2][4], aQS[2][4];
#pragma unroll
        for (int r = 0; r < 2; r++)
#pragma unroll
            for (int i = 0; i < 4; i++) { aKS[r][i] = 0.f; aQS[r][i] = 0.f; }

        for (int jt = 0; jt < 4; jt++) {
            __syncthreads();
#pragma unroll
            for (int n = 0; n < 8; n++) {
                const int f4 = tid + n * 256;
                const int row = f4 >> 5;
                const int col = (f4 & 31) * 4;
                float4 kv = *(const float4*)&Kd[(size_t)(r0 + row) * Dd + jt * 128 + col];
                float4 qv = *(const float4*)&Qd[(size_t)(r0 + row) * Dd + jt * 128 + col];
                const int so = row * 129 + col;
                Kt[so] = kv.x; Kt[so + 1] = kv.y; Kt[so + 2] = kv.z; Kt[so + 3] = kv.w;
                Qt[so] = qv.x; Qt[so + 1] = qv.y; Qt[so + 2] = qv.z; Qt[so + 3] = qv.w;
            }
            __syncthreads();
            const float* Sp  = S + ii * 512 + jt * 128;
            const float* kp0 = Kt + t0 * 129;
            const float* kp1 = Kt + (t0 + 1) * 129;
            const float* qp0 = Qt + t0 * 129;
            const float* qp1 = Qt + (t0 + 1) * 129;
#pragma unroll 4
            for (int dd = 0; dd < 128; dd++) {
                const float k0 = kp0[dd], k1 = kp1[dd];
                const float q0 = qp0[dd], q1 = qp1[dd];
#pragma unroll
                for (int i = 0; i < 4; i++) {
                    const float sv = Sp[i * 512 + dd];
                    aKS[0][i] += k0 * sv;
                    aKS[1][i] += k1 * sv;
                    aQS[0][i] += q0 * sv;
                    aQS[1][i] += q1 * sv;
                }
            }
        }
        __syncthreads();
        // rhs for U and QS into smem
#pragma unroll
        for (int r = 0; r < 2; r++) {
            const int t = t0 + r;
            const float bt = betas[t];
#pragma unroll
            for (int i = 0; i < 4; i++) {
                Um[t * 33 + ii + i] = bt * (Vb[t * 33 + ii + i] - aKS[r][i]);
                QSm[t * 33 + ii + i] = aQS[r][i];
            }
        }
        __syncthreads();

        // ---- Phase B: blocked forward substitution (block 16) ----
#pragma unroll
        for (int blk = 0; blk < 4; blk++) {
            const int bt0 = blk * 16;
            if (wid == 0) {
                for (int t = bt0; t < bt0 + 16; t++) {
                    float s = Um[t * 33 + lane];
                    for (int j = bt0; j < t; j++)
                        s -= As[t * 65 + j] * Um[j * 33 + lane];
                    Um[t * 33 + lane] = s;
                }
            }
            __syncthreads();
            if (blk < 3) {
                const int rem = 64 - (blk + 1) * 16;
                for (int e = tid; e < rem * 32; e += 256) {
                    const int t = (blk + 1) * 16 + (e >> 5);
                    const int i = e & 31;
                    float s = Um[t * 33 + i];
#pragma unroll
                    for (int j = 0; j < 16; j++)
                        s -= As[t * 65 + bt0 + j] * Um[(bt0 + j) * 33 + i];
                    Um[t * 33 + i] = s;
                }
                __syncthreads();
            }
        }

        // ---- Phase C: O = QS + tril(G) @ U ----
        for (int e = tid; e < CH * DV; e += 256) {
            const int t = e >> 5, i = e & 31;
            float s = QSm[t * 33 + i];
            for (int j = 0; j <= t; j++)
                s += Gs[t * 65 + j] * Um[j * 33 + i];
            Od[(size_t)(r0 + t) * Dd + i0 + i] = s;
        }

        // ---- Phase D: S += U^T @ K  (rank-64 update) ----
        for (int jt = 0; jt < 4; jt++) {
            __syncthreads();
#pragma unroll
            for (int n = 0; n < 8; n++) {
                const int f4 = tid + n * 256;
                const int row = f4 >> 5;
                const int col = (f4 & 31) * 4;
                float4 kv = *(const float4*)&Kd[(size_t)(r0 + row) * Dd + jt * 128 + col];
                const int so = row * 129 + col;
                Kt[so] = kv.x; Kt[so + 1] = kv.y; Kt[so + 2] = kv.z; Kt[so + 3] = kv.w;
            }
            __syncthreads();
            float sacc[4][4];
#pragma unroll
            for (int ig = 0; ig < 4; ig++)
#pragma unroll
                for (int g = 0; g < 4; g++)
                    sacc[ig][g] = S[(ii + ig) * 512 + jt * 128 + g * 32 + lane];
#pragma unroll 4
            for (int t = 0; t < 64; t++) {
                float uu[4], kk[4];
#pragma unroll
                for (int ig = 0; ig < 4; ig++) uu[ig] = Um[t * 33 + ii + ig];
#pragma unroll
                for (int g = 0; g < 4; g++) kk[g] = Kt[t * 129 + g * 32 + lane];
#pragma unroll
                for (int ig = 0; ig < 4; ig++)
#pragma unroll
                    for (int g = 0; g < 4; g++)
                        sacc[ig][g] += uu[ig] * kk[g];
            }
#pragma unroll
            for (int ig = 0; ig < 4; ig++)
#pragma unroll
                for (int g = 0; g < 4; g++)
                    S[(ii + ig) * 512 + jt * 128 + g * 32 + lane] = sacc[ig][g];
        }
        __syncthreads();
    }
}

// ---------------------------------------------------------------------------
extern "C" void kernel_launch(void* const* d_in, const int* in_sizes, int n_in,
                              void* d_out, int out_size)
{
    const float* x     = (const float*)d_in[0];
    const float* Wq    = (const float*)d_in[1];
    const float* bq    = (const float*)d_in[2];
    const float* Wk    = (const float*)d_in[3];
    const float* bk    = (const float*)d_in[4];
    const float* Wv    = (const float*)d_in[5];
    const float* bv    = (const float*)d_in[6];
    const float* Wbeta = (const float*)d_in[7];
    const float* bbeta = (const float*)d_in[8];
    const float* Wo    = (const float*)d_in[9];
    const float* bo    = (const float*)d_in[10];
    float* out = (float*)d_out;

    float *pQ, *pK, *pV, *pO, *pBeta, *pA, *pG;
    cudaGetSymbolAddress((void**)&pQ, g_Q);
    cudaGetSymbolAddress((void**)&pK, g_K);
    cudaGetSymbolAddress((void**)&pV, g_V);
    cudaGetSymbolAddress((void**)&pO, g_O);
    cudaGetSymbolAddress((void**)&pBeta, g_Beta);
    cudaGetSymbolAddress((void**)&pA, g_A);
    cudaGetSymbolAddress((void**)&pG, g_G);

    cudaFuncSetAttribute(scan_kernel,
                         cudaFuncAttributeMaxDynamicSharedMemorySize, SMEM_BYTES);

    dim3 ggrid(Dd / 128, BT / 128);   // (4, 128)
    gemm_bias_kernel<<<ggrid, 256>>>(x, Wq, bq, pQ, BT, Dd, Dd);
    gemm_bias_kernel<<<ggrid, 256>>>(x, Wk, bk, pK, BT, Dd, Dd);
    gemm_bias_kernel<<<ggrid, 256>>>(x, Wv, bv, pV, BT, Dd, Dd);

    norm_beta_kernel<<<BT, 128>>>(pK, Wbeta, bbeta, pBeta);

    chunk_ag_kernel<<<dim3(NCH, Bb), 256>>>(pQ, pK, pBeta, pA, pG);

    scan_kernel<<<dim3(NVT, Bb), 256, SMEM_BYTES>>>(pQ, pK, pV, pBeta, pA, pG, pO);

    gemm_bias_kernel<<<ggrid, 256>>>(pO, Wo, bo, out, BT, Dd, Dd);
}

// round 4
// speedup vs baseline: 1.6355x; 1.0272x over previous
#include <cuda_runtime.h>
#include <math.h>

namespace {
constexpr int Bb  = 8;
constexpr int Tt  = 2048;
constexpr int Dd  = 512;
constexpr int BT  = Bb * Tt;
constexpr int CH  = 64;
constexpr int NCH = Tt / CH;   // 32
constexpr int DV  = 32;
constexpr int NVT = Dd / DV;   // 16
// scan smem (float offsets, all even)
constexpr int SM_S    = 0;                    // [32][512]
constexpr int SM_KT   = SM_S  + 32 * 512;     // [64][130]
constexpr int SM_QT   = SM_KT + 64 * 130;     // [64][130]
constexpr int SM_A    = SM_QT + 64 * 130;     // [64][66]
constexpr int SM_G    = SM_A  + 64 * 66;      // [64][66]
constexpr int SM_U    = SM_G  + 64 * 66;      // [64][34]
constexpr int SM_QS   = SM_U  + 64 * 34;      // [64][34]
constexpr int SM_VB   = SM_QS + 64 * 34;      // [64][34]
constexpr int SM_BETA = SM_VB + 64 * 34;      // [64]
constexpr int SM_TOT  = SM_BETA + 64;
constexpr int SMEM_BYTES = SM_TOT * 4;        // 192256 B
}

using ull = unsigned long long;
__device__ __forceinline__ ull pk(float x, float y) {
    ull r; asm("mov.b64 %0,{%1,%2};" : "=l"(r) : "f"(x), "f"(y)); return r;
}
__device__ __forceinline__ float2 upk(ull v) {
    float2 r; asm("mov.b64 {%0,%1},%2;" : "=f"(r.x), "=f"(r.y) : "l"(v)); return r;
}
__device__ __forceinline__ void fma2(ull& d, ull a, ull b) {
    asm("fma.rn.f32x2 %0,%1,%2,%0;" : "+l"(d) : "l"(a), "l"(b));
}
__device__ __forceinline__ float hadd(ull v) { float2 f = upk(v); return f.x + f.y; }

__device__ float g_Q[BT * Dd];
__device__ float g_K[BT * Dd];
__device__ float g_V[BT * Dd];
__device__ float g_O[BT * Dd];
__device__ float g_Beta[BT];
__device__ float g_A[Bb * NCH * CH * CH];
__device__ float g_G[Bb * NCH * CH * CH];

// ---------------- NT GEMM with bias, f32x2 ----------------
__global__ __launch_bounds__(256) void gemm_bias_kernel(
    const float* __restrict__ A, const float* __restrict__ W,
    const float* __restrict__ bias, float* __restrict__ C,
    int M, int N, int K)
{
    constexpr int BK = 8;
    __shared__ float As[BK][128];
    __shared__ float Bs[BK][128];
    const int tid = threadIdx.x;
    const int bm = blockIdx.y * 128, bn = blockIdx.x * 128;
    const int tx = tid & 15, ty = tid >> 4;

    ull acc[8][4];
#pragma unroll
    for (int i = 0; i < 8; i++)
#pragma unroll
        for (int j = 0; j < 4; j++) acc[i][j] = 0ull;

    const int lrow = tid >> 1, lcol = (tid & 1) * 4;
    const float* Aptr = A + (size_t)(bm + lrow) * K + lcol;
    const float* Wptr = W + (size_t)(bn + lrow) * K + lcol;

    for (int k0 = 0; k0 < K; k0 += BK) {
        float4 av = *(const float4*)(Aptr + k0);
        float4 wv = *(const float4*)(Wptr + k0);
        __syncthreads();
        As[lcol + 0][lrow] = av.x; As[lcol + 1][lrow] = av.y;
        As[lcol + 2][lrow] = av.z; As[lcol + 3][lrow] = av.w;
        Bs[lcol + 0][lrow] = wv.x; Bs[lcol + 1][lrow] = wv.y;
        Bs[lcol + 2][lrow] = wv.z; Bs[lcol + 3][lrow] = wv.w;
        __syncthreads();
#pragma unroll
        for (int kk = 0; kk < BK; kk++) {
            float4 a0 = *(const float4*)&As[kk][ty * 8];
            float4 a1 = *(const float4*)&As[kk][ty * 8 + 4];
            const ull* bp = (const ull*)&Bs[kk][tx * 8];
            ull b0 = bp[0], b1 = bp[1], b2 = bp[2], b3 = bp[3];
            ull ap[8];
            ap[0] = pk(a0.x, a0.x); ap[1] = pk(a0.y, a0.y);
            ap[2] = pk(a0.z, a0.z); ap[3] = pk(a0.w, a0.w);
            ap[4] = pk(a1.x, a1.x); ap[5] = pk(a1.y, a1.y);
            ap[6] = pk(a1.z, a1.z); ap[7] = pk(a1.w, a1.w);
#pragma unroll
            for (int i = 0; i < 8; i++) {
                fma2(acc[i][0], ap[i], b0); fma2(acc[i][1], ap[i], b1);
                fma2(acc[i][2], ap[i], b2); fma2(acc[i][3], ap[i], b3);
            }
        }
    }
#pragma unroll
    for (int i = 0; i < 8; i++) {
        const int row = bm + ty * 8 + i, col = bn + tx * 8;
        float2 p0 = upk(acc[i][0]), p1 = upk(acc[i][1]);
        float2 p2 = upk(acc[i][2]), p3 = upk(acc[i][3]);
        float4 o0, o1;
        o0.x = p0.x + bias[col + 0]; o0.y = p0.y + bias[col + 1];
        o0.z = p1.x + bias[col + 2]; o0.w = p1.y + bias[col + 3];
        o1.x = p2.x + bias[col + 4]; o1.y = p2.y + bias[col + 5];
        o1.z = p3.x + bias[col + 6]; o1.w = p3.y + bias[col + 7];
        *(float4*)&C[(size_t)row * N + col] = o0;
        *(float4*)&C[(size_t)row * N + col + 4] = o1;
    }
}

// ---------------- l2norm + beta ----------------
__global__ __launch_bounds__(128) void norm_beta_kernel(
    float* __restrict__ Kd, const float* __restrict__ wb,
    const float* __restrict__ bb, float* __restrict__ Beta)
{
    const int row = blockIdx.x, tid = threadIdx.x;
    float4 v = ((const float4*)(Kd + (size_t)row * Dd))[tid];
    float ss = v.x * v.x + v.y * v.y + v.z * v.z + v.w * v.w;
#pragma unroll
    for (int o = 16; o; o >>= 1) ss += __shfl_xor_sync(0xffffffffu, ss, o);
    __shared__ float red1[4];
    if ((tid & 31) == 0) red1[tid >> 5] = ss;
    __syncthreads();
    const float inv = 1.0f / fmaxf(sqrtf(red1[0] + red1[1] + red1[2] + red1[3]), 1e-12f);
    float4 w = ((const float4*)wb)[tid];
    float bd = v.x * w.x + v.y * w.y + v.z * w.z + v.w * w.w;
#pragma unroll
    for (int o = 16; o; o >>= 1) bd += __shfl_xor_sync(0xffffffffu, bd, o);
    __shared__ float red2[4];
    if ((tid & 31) == 0) red2[tid >> 5] = bd;
    __syncthreads();
    v.x *= inv; v.y *= inv; v.z *= inv; v.w *= inv;
    ((float4*)(Kd + (size_t)row * Dd))[tid] = v;
    if (tid == 0) {
        const float z = (red2[0] + red2[1] + red2[2] + red2[3]) * inv + bb[0];
        Beta[row] = 1.0f / (1.0f + expf(-z));
    }
}

// ---------------- per-chunk A,G Gram matrices, f32x2 dot ----------------
__global__ __launch_bounds__(256) void chunk_ag_kernel(
    const float* __restrict__ Qd, const float* __restrict__ Kd,
    const float* __restrict__ Beta, float* __restrict__ Ag, float* __restrict__ Gg)
{
    const int c = blockIdx.x, b = blockIdx.y;
    const int r0 = b * Tt + c * CH;
    __shared__ float Ks[64 * 66];
    __shared__ float Qs[64 * 66];
    const int tid = threadIdx.x;
    const int t0 = (tid >> 4) * 4, j0 = (tid & 15) * 4;

    ull accA[4][4], accG[4][4];
#pragma unroll
    for (int i = 0; i < 4; i++)
#pragma unroll
        for (int j = 0; j < 4; j++) { accA[i][j] = 0ull; accG[i][j] = 0ull; }

    for (int dt = 0; dt < 8; dt++) {
        __syncthreads();
#pragma unroll
        for (int n = 0; n < 4; n++) {
            const int f4 = tid + n * 256;
            const int row = f4 >> 4, col = (f4 & 15) * 4;
            float4 kv = *(const float4*)&Kd[(size_t)(r0 + row) * Dd + dt * 64 + col];
            float4 qv = *(const float4*)&Qd[(size_t)(r0 + row) * Dd + dt * 64 + col];
            const int so = row * 66 + col;
            Ks[so] = kv.x; Ks[so + 1] = kv.y; Ks[so + 2] = kv.z; Ks[so + 3] = kv.w;
            Qs[so] = qv.x; Qs[so + 1] = qv.y; Qs[so + 2] = qv.z; Qs[so + 3] = qv.w;
        }
        __syncthreads();
#pragma unroll 2
        for (int dd = 0; dd < 64; dd += 2) {
            ull kt[4], kj[4], qt[4];
#pragma unroll
            for (int i = 0; i < 4; i++) {
                kt[i] = *(const ull*)&Ks[(t0 + i) * 66 + dd];
                qt[i] = *(const ull*)&Qs[(t0 + i) * 66 + dd];
                kj[i] = *(const ull*)&Ks[(j0 + i) * 66 + dd];
            }
#pragma unroll
            for (int i = 0; i < 4; i++)
#pragma unroll
                for (int j = 0; j < 4; j++) {
                    fma2(accA[i][j], kt[i], kj[j]);
                    fma2(accG[i][j], qt[i], kj[j]);
                }
        }
    }
    const size_t base = ((size_t)(b * NCH) + c) * (CH * CH);
#pragma unroll
    for (int i = 0; i < 4; i++) {
        const int t = t0 + i;
        const float bt = Beta[r0 + t];
#pragma unroll
        for (int j = 0; j < 4; j++) {
            const int jj = j0 + j;
            Ag[base + t * CH + jj] = (jj < t) ? bt * hadd(accA[i][j]) : 0.f;
            Gg[base + t * CH + jj] = (jj <= t) ? hadd(accG[i][j]) : 0.f;
        }
    }
}

// ---------------- chunked delta-rule scan, f32x2 ----------------
__global__ __launch_bounds__(256) void scan_kernel(
    const float* __restrict__ Qd, const float* __restrict__ Kd,
    const float* __restrict__ Vd, const float* __restrict__ Betad,
    const float* __restrict__ Ag, const float* __restrict__ Gg,
    float* __restrict__ Od)
{
    extern __shared__ float sm[];
    float* S     = sm + SM_S;
    float* Kt    = sm + SM_KT;
    float* Qt    = sm + SM_QT;
    float* As    = sm + SM_A;
    float* Gs    = sm + SM_G;
    float* Um    = sm + SM_U;
    float* QSm   = sm + SM_QS;
    float* Vb    = sm + SM_VB;
    float* betas = sm + SM_BETA;

    const int b = blockIdx.y;
    const int i0 = blockIdx.x * DV;
    const int tid = threadIdx.x;
    const int lane = tid & 31, wid = tid >> 5;

    for (int e = tid; e < 32 * 512; e += 256) S[e] = 0.f;
    __syncthreads();

    for (int c = 0; c < NCH; c++) {
        const int r0 = b * Tt + c * CH;
        const size_t agbase = ((size_t)(b * NCH) + c) * (CH * CH);

        for (int e = tid; e < CH * CH; e += 256) {
            const int t = e >> 6, j = e & 63;
            As[t * 66 + j] = Ag[agbase + e];
            Gs[t * 66 + j] = Gg[agbase + e];
        }
        for (int e = tid; e < CH * DV; e += 256) {
            const int t = e >> 5, i = e & 31;
            Vb[t * 34 + i] = Vd[(size_t)(r0 + t) * Dd + i0 + i];
        }
        if (tid < 64) betas[tid] = Betad[r0 + tid];
        __syncthreads();

        // Phase A: KS=K@S^T, QS=Q@S^T (64x32). dot-pairs along d.
        const int t0 = lane * 2;
        const int ii = wid * 4;
        ull aKS[2][4], aQS[2][4];
#pragma unroll
        for (int r = 0; r < 2; r++)
#pragma unroll
            for (int i = 0; i < 4; i++) { aKS[r][i] = 0ull; aQS[r][i] = 0ull; }

        for (int jt = 0; jt < 4; jt++) {
            __syncthreads();
#pragma unroll
            for (int n = 0; n < 8; n++) {
                const int f4 = tid + n * 256;
                const int row = f4 >> 5, col = (f4 & 31) * 4;
                float4 kv = *(const float4*)&Kd[(size_t)(r0 + row) * Dd + jt * 128 + col];
                float4 qv = *(const float4*)&Qd[(size_t)(r0 + row) * Dd + jt * 128 + col];
                const int so = row * 130 + col;
                Kt[so] = kv.x; Kt[so + 1] = kv.y; Kt[so + 2] = kv.z; Kt[so + 3] = kv.w;
                Qt[so] = qv.x; Qt[so + 1] = qv.y; Qt[so + 2] = qv.z; Qt[so + 3] = qv.w;
            }
            __syncthreads();
            const float* Sp = S + ii * 512 + jt * 128;
#pragma unroll 2
            for (int dd = 0; dd < 128; dd += 2) {
                ull k0 = *(const ull*)&Kt[t0 * 130 + dd];
                ull k1 = *(const ull*)&Kt[(t0 + 1) * 130 + dd];
                ull q0 = *(const ull*)&Qt[t0 * 130 + dd];
                ull q1 = *(const ull*)&Qt[(t0 + 1) * 130 + dd];
#pragma unroll
                for (int i = 0; i < 4; i++) {
                    ull sv = *(const ull*)&Sp[i * 512 + dd];
                    fma2(aKS[0][i], k0, sv); fma2(aKS[1][i], k1, sv);
                    fma2(aQS[0][i], q0, sv); fma2(aQS[1][i], q1, sv);
                }
            }
        }
        __syncthreads();
#pragma unroll
        for (int r = 0; r < 2; r++) {
            const int t = t0 + r;
            const float bt = betas[t];
#pragma unroll
            for (int i = 0; i < 4; i++) {
                Um[t * 34 + ii + i]  = bt * (Vb[t * 34 + ii + i] - hadd(aKS[r][i]));
                QSm[t * 34 + ii + i] = hadd(aQS[r][i]);
            }
        }
        __syncthreads();

        // Phase B: blocked forward substitution
#pragma unroll
        for (int blk = 0; blk < 4; blk++) {
            const int bt0 = blk * 16;
            if (wid == 0) {
                for (int t = bt0; t < bt0 + 16; t++) {
                    float s = Um[t * 34 + lane];
                    for (int j = bt0; j < t; j++)
                        s -= As[t * 66 + j] * Um[j * 34 + lane];
                    Um[t * 34 + lane] = s;
                }
            }
            __syncthreads();
            if (blk < 3) {
                const int rem = 64 - (blk + 1) * 16;
                for (int e = tid; e < rem * 32; e += 256) {
                    const int t = (blk + 1) * 16 + (e >> 5);
                    const int i = e & 31;
                    float s = Um[t * 34 + i];
#pragma unroll
                    for (int j = 0; j < 16; j++)
                        s -= As[t * 66 + bt0 + j] * Um[(bt0 + j) * 34 + i];
                    Um[t * 34 + i] = s;
                }
                __syncthreads();
            }
        }

        // Phase C: O = QS + tril(G)@U (pair along i)
        for (int e = tid; e < CH * 16; e += 256) {
            const int t = e >> 4, ip = (e & 15) * 2;
            ull s2 = *(const ull*)&QSm[t * 34 + ip];
            for (int j = 0; j <= t; j++) {
                ull g2 = pk(Gs[t * 66 + j], Gs[t * 66 + j]);
                fma2(s2, g2, *(const ull*)&Um[j * 34 + ip]);
            }
            *(float2*)&Od[(size_t)(r0 + t) * Dd + i0 + ip] = upk(s2);
        }

        // Phase D: S += U^T @ K  (d-pairs, packed accumulators)
        for (int jt = 0; jt < 4; jt++) {
            __syncthreads();
#pragma unroll
            for (int n = 0; n < 8; n++) {
                const int f4 = tid + n * 256;
                const int row = f4 >> 5, col = (f4 & 31) * 4;
                float4 kv = *(const float4*)&Kd[(size_t)(r0 + row) * Dd + jt * 128 + col];
                const int so = row * 130 + col;
                Kt[so] = kv.x; Kt[so + 1] = kv.y; Kt[so + 2] = kv.z; Kt[so + 3] = kv.w;
            }
            __syncthreads();
            const int d0 = lane * 2;
            ull sacc[4][2];
#pragma unroll
            for (int ig = 0; ig < 4; ig++)
#pragma unroll
                for (int g = 0; g < 2; g++)
                    sacc[ig][g] = *(const ull*)&S[(ii + ig) * 512 + jt * 128 + g * 64 + d0];
#pragma unroll 4
            for (int t = 0; t < 64; t++) {
                float2 ua = *(const float2*)&Um[t * 34 + ii];
                float2 ub = *(const float2*)&Um[t * 34 + ii + 2];
                ull ud[4] = { pk(ua.x, ua.x), pk(ua.y, ua.y), pk(ub.x, ub.x), pk(ub.y, ub.y) };
                ull kp0 = *(const ull*)&Kt[t * 130 + d0];
                ull kp1 = *(const ull*)&Kt[t * 130 + 64 + d0];
#pragma unroll
                for (int ig = 0; ig < 4; ig++) {
                    fma2(sacc[ig][0], ud[ig], kp0);
                    fma2(sacc[ig][1], ud[ig], kp1);
                }
            }
#pragma unroll
            for (int ig = 0; ig < 4; ig++)
#pragma unroll
                for (int g = 0; g < 2; g++)
                    *(ull*)&S[(ii + ig) * 512 + jt * 128 + g * 64 + d0] = sacc[ig][g];
        }
        __syncthreads();
    }
}

extern "C" void kernel_launch(void* const* d_in, const int* in_sizes, int n_in,
                              void* d_out, int out_size)
{
    const float* x     = (const float*)d_in[0];
    const float* Wq    = (const float*)d_in[1];
    const float* bq    = (const float*)d_in[2];
    const float* Wk    = (const float*)d_in[3];
    const float* bk    = (const float*)d_in[4];
    const float* Wv    = (const float*)d_in[5];
    const float* bv    = (const float*)d_in[6];
    const float* Wbeta = (const float*)d_in[7];
    const float* bbeta = (const float*)d_in[8];
    const float* Wo    = (const float*)d_in[9];
    const float* bo    = (const float*)d_in[10];
    float* out = (float*)d_out;

    float *pQ, *pK, *pV, *pO, *pBeta, *pA, *pG;
    cudaGetSymbolAddress((void**)&pQ, g_Q);
    cudaGetSymbolAddress((void**)&pK, g_K);
    cudaGetSymbolAddress((void**)&pV, g_V);
    cudaGetSymbolAddress((void**)&pO, g_O);
    cudaGetSymbolAddress((void**)&pBeta, g_Beta);
    cudaGetSymbolAddress((void**)&pA, g_A);
    cudaGetSymbolAddress((void**)&pG, g_G);

    cudaFuncSetAttribute(scan_kernel,
                         cudaFuncAttributeMaxDynamicSharedMemorySize, SMEM_BYTES);

    dim3 ggrid(Dd / 128, BT / 128);
    gemm_bias_kernel<<<ggrid, 256>>>(x, Wq, bq, pQ, BT, Dd, Dd);
    gemm_bias_kernel<<<ggrid, 256>>>(x, Wk, bk, pK, BT, Dd, Dd);
    gemm_bias_kernel<<<ggrid, 256>>>(x, Wv, bv, pV, BT, Dd, Dd);

    norm_beta_kernel<<<BT, 128>>>(pK, Wbeta, bbeta, pBeta);

    chunk_ag_kernel<<<dim3(NCH, Bb), 256>>>(pQ, pK, pBeta, pA, pG);

    scan_kernel<<<dim3(NVT, Bb), 256, SMEM_BYTES>>>(pQ, pK, pV, pBeta, pA, pG, pO);

    gemm_bias_kernel<<<ggrid, 256>>>(pO, Wo, bo, out, BT, Dd, Dd);
}

// round 6
// speedup vs baseline: 2.0675x; 1.2641x over previous
#include <cuda_runtime.h>
#include <cuda_bf16.h>
#include <math.h>
#include <stdint.h>

namespace {
constexpr int Bb  = 8;
constexpr int Tt  = 2048;
constexpr int Dd  = 512;
constexpr int BT  = Bb * Tt;
constexpr int CH  = 64;
constexpr int NCH = Tt / CH;   // 32
constexpr int DV  = 32;
constexpr int NVT = Dd / DV;   // 16
// scan smem (float offsets, all even)
constexpr int SM_S    = 0;                    // [32][512]
constexpr int SM_KT   = SM_S  + 32 * 512;     // [64][130]
constexpr int SM_QT   = SM_KT + 64 * 130;     // [64][130]
constexpr int SM_A    = SM_QT + 64 * 130;     // [64][66]
constexpr int SM_G    = SM_A  + 64 * 66;      // [64][66]
constexpr int SM_U    = SM_G  + 64 * 66;      // [64][34]
constexpr int SM_QS   = SM_U  + 64 * 34;      // [64][34]
constexpr int SM_VB   = SM_QS + 64 * 34;      // [64][34]
constexpr int SM_BETA = SM_VB + 64 * 34;      // [64]
constexpr int SM_TOT  = SM_BETA + 64;
constexpr int SMEM_BYTES = SM_TOT * 4;        // 192256 B
}

using ull = unsigned long long;
__device__ __forceinline__ ull pk(float x, float y) {
    ull r; asm("mov.b64 %0,{%1,%2};" : "=l"(r) : "f"(x), "f"(y)); return r;
}
__device__ __forceinline__ float2 upk(ull v) {
    float2 r; asm("mov.b64 {%0,%1},%2;" : "=f"(r.x), "=f"(r.y) : "l"(v)); return r;
}
__device__ __forceinline__ void fma2(ull& d, ull a, ull b) {
    asm("fma.rn.f32x2 %0,%1,%2,%0;" : "+l"(d) : "l"(a), "l"(b));
}
__device__ __forceinline__ float hadd(ull v) { float2 f = upk(v); return f.x + f.y; }

// ---------------- device scratch ----------------
__device__ float g_Q[BT * Dd];
__device__ float g_K[BT * Dd];
__device__ float g_V[BT * Dd];
__device__ float g_O[BT * Dd];
__device__ float g_Beta[BT];
__device__ float g_A[Bb * NCH * CH * CH];
__device__ float g_G[Bb * NCH * CH * CH];
__device__ __nv_bfloat16 g_xh[BT * Dd];
__device__ __nv_bfloat16 g_xl[BT * Dd];
__device__ __nv_bfloat16 g_oh[BT * Dd];
__device__ __nv_bfloat16 g_ol[BT * Dd];
__device__ __nv_bfloat16 g_wqh[Dd * Dd];
__device__ __nv_bfloat16 g_wql[Dd * Dd];
__device__ __nv_bfloat16 g_wkh[Dd * Dd];
__device__ __nv_bfloat16 g_wkl[Dd * Dd];
__device__ __nv_bfloat16 g_wvh[Dd * Dd];
__device__ __nv_bfloat16 g_wvl[Dd * Dd];
__device__ __nv_bfloat16 g_woh[Dd * Dd];
__device__ __nv_bfloat16 g_wol[Dd * Dd];

__device__ __forceinline__ uint32_t smem_u32(const void* p) {
    uint32_t a;
    asm("{ .reg .u64 t; cvta.to.shared.u64 t,%1; cvt.u32.u64 %0,t; }" : "=r"(a) : "l"(p));
    return a;
}
__device__ __forceinline__ void ldsm_x4(uint32_t* r, uint32_t addr) {
    asm volatile("ldmatrix.sync.aligned.m8n8.x4.shared.b16 {%0,%1,%2,%3}, [%4];"
                 : "=r"(r[0]), "=r"(r[1]), "=r"(r[2]), "=r"(r[3]) : "r"(addr));
}
__device__ __forceinline__ void mma_bf16(float* d, const uint32_t* a,
                                         uint32_t b0, uint32_t b1) {
    asm volatile(
        "mma.sync.aligned.m16n8k16.row.col.f32.bf16.bf16.f32 "
        "{%0,%1,%2,%3}, {%4,%5,%6,%7}, {%8,%9}, {%0,%1,%2,%3};"
        : "+f"(d[0]), "+f"(d[1]), "+f"(d[2]), "+f"(d[3])
        : "r"(a[0]), "r"(a[1]), "r"(a[2]), "r"(a[3]), "r"(b0), "r"(b1));
}

// ---------------- split fp32 -> bf16 hi/lo ----------------
__global__ __launch_bounds__(256) void split_kernel(
    const float* __restrict__ x, __nv_bfloat16* __restrict__ h,
    __nv_bfloat16* __restrict__ l, int n4)
{
    int i = blockIdx.x * 256 + threadIdx.x;
    if (i >= n4) return;
    float4 v = ((const float4*)x)[i];
    __nv_bfloat16 h0 = __float2bfloat16(v.x);
    __nv_bfloat16 h1 = __float2bfloat16(v.y);
    __nv_bfloat16 h2 = __float2bfloat16(v.z);
    __nv_bfloat16 h3 = __float2bfloat16(v.w);
    __nv_bfloat16 l0 = __float2bfloat16(v.x - __bfloat162float(h0));
    __nv_bfloat16 l1 = __float2bfloat16(v.y - __bfloat162float(h1));
    __nv_bfloat16 l2 = __float2bfloat16(v.z - __bfloat162float(h2));
    __nv_bfloat16 l3 = __float2bfloat16(v.w - __bfloat162float(h3));
    ((__nv_bfloat162*)h)[2 * i + 0] = __halves2bfloat162(h0, h1);
    ((__nv_bfloat162*)h)[2 * i + 1] = __halves2bfloat162(h2, h3);
    ((__nv_bfloat162*)l)[2 * i + 0] = __halves2bfloat162(l0, l1);
    ((__nv_bfloat162*)l)[2 * i + 1] = __halves2bfloat162(l2, l3);
}

// ---------------- HMMA split-bf16 GEMM: C = A@B^T + bias ----------------
// CTA 128x128, 8 warps (2m x 4n), warp tile 64x32, K staged 32 at a time.
// 3 accumulation passes: Ah*Bh, Ah*Bl, Al*Bh (all into fp32 regs).
__global__ __launch_bounds__(256) void tgemm_mma_kernel(
    const __nv_bfloat16* __restrict__ Ah, const __nv_bfloat16* __restrict__ Al,
    const __nv_bfloat16* __restrict__ Bh, const __nv_bfloat16* __restrict__ Bl,
    const float* __restrict__ bias, float* __restrict__ C)
{
    __shared__ __align__(16) __nv_bfloat16 sA[128 * 40];
    __shared__ __align__(16) __nv_bfloat16 sB[128 * 40];

    const int tid = threadIdx.x, lane = tid & 31, wid = tid >> 5;
    const int wm = wid & 1, wn = wid >> 1;     // warp grid 2(m) x 4(n)
    const int bm = blockIdx.y * 128, bn = blockIdx.x * 128;

    float d[4][4][4];
#pragma unroll
    for (int mt = 0; mt < 4; mt++)
#pragma unroll
        for (int nt = 0; nt < 4; nt++)
#pragma unroll
            for (int e = 0; e < 4; e++) d[mt][nt][e] = 0.f;

    // ldmatrix source addresses (row stride 40 halves = 80 B, conflict-free)
    const uint32_t aBase = smem_u32(sA), bBase = smem_u32(sB);
    uint32_t a_addr[4], b_addr[2];
    {
        const int ar = lane & 15, akoff = (lane >> 4) * 8;
#pragma unroll
        for (int mt = 0; mt < 4; mt++)
            a_addr[mt] = aBase + ((wm * 64 + mt * 16 + ar) * 40 + akoff) * 2;
        const int nrow = wn * 32 + ((lane >> 4) * 8) + (lane & 7);
        const int khalf = (lane >> 3) & 1;
#pragma unroll
        for (int np = 0; np < 2; np++)
            b_addr[np] = bBase + ((nrow + np * 16) * 40 + khalf * 8) * 2;
    }

#pragma unroll 1
    for (int p = 0; p < 3; p++) {
        const __nv_bfloat16* Ap = (p == 2) ? Al : Ah;
        const __nv_bfloat16* Bp = (p == 1) ? Bl : Bh;
#pragma unroll 1
        for (int kt = 0; kt < 16; kt++) {
            __syncthreads();
#pragma unroll
            for (int i = 0; i < 2; i++) {
                const int idx = tid + i * 256;       // 512 16B chunks each
                const int row = idx >> 2, c = idx & 3;
                uint4 va = *(const uint4*)(Ap + (size_t)(bm + row) * Dd + kt * 32 + c * 8);
                uint4 vb = *(const uint4*)(Bp + (size_t)(bn + row) * Dd + kt * 32 + c * 8);
                *(uint4*)((char*)sA + row * 80 + c * 16) = va;
                *(uint4*)((char*)sB + row * 80 + c * 16) = vb;
            }
            __syncthreads();
#pragma unroll
            for (int ks = 0; ks < 2; ks++) {
                uint32_t a[4][4], b[2][4];
#pragma unroll
                for (int mt = 0; mt < 4; mt++) ldsm_x4(a[mt], a_addr[mt] + ks * 32);
#pragma unroll
                for (int np = 0; np < 2; np++) ldsm_x4(b[np], b_addr[np] + ks * 32);
#pragma unroll
                for (int mt = 0; mt < 4; mt++)
#pragma unroll
                    for (int nt = 0; nt < 4; nt++)
                        mma_bf16(d[mt][nt], a[mt],
                                 b[nt >> 1][(nt & 1) * 2], b[nt >> 1][(nt & 1) * 2 + 1]);
            }
        }
    }

    // epilogue: frag c0,c1 -> (row, col..col+1); c2,c3 -> (row+8, ...)
#pragma unroll
    for (int mt = 0; mt < 4; mt++) {
        const int r0 = bm + wm * 64 + mt * 16 + (lane >> 2);
#pragma unroll
        for (int nt = 0; nt < 4; nt++) {
            const int c0 = bn + wn * 32 + nt * 8 + (lane & 3) * 2;
            const float b0 = bias[c0], b1 = bias[c0 + 1];
            float2 o0 = make_float2(d[mt][nt][0] + b0, d[mt][nt][1] + b1);
            float2 o1 = make_float2(d[mt][nt][2] + b0, d[mt][nt][3] + b1);
            *(float2*)&C[(size_t)r0 * Dd + c0] = o0;
            *(float2*)&C[(size_t)(r0 + 8) * Dd + c0] = o1;
        }
    }
}

// ---------------- l2norm + beta ----------------
__global__ __launch_bounds__(128) void norm_beta_kernel(
    float* __restrict__ Kd, const float* __restrict__ wb,
    const float* __restrict__ bb, float* __restrict__ Beta)
{
    const int row = blockIdx.x, tid = threadIdx.x;
    float4 v = ((const float4*)(Kd + (size_t)row * Dd))[tid];
    float ss = v.x * v.x + v.y * v.y + v.z * v.z + v.w * v.w;
#pragma unroll
    for (int o = 16; o; o >>= 1) ss += __shfl_xor_sync(0xffffffffu, ss, o);
    __shared__ float red1[4];
    if ((tid & 31) == 0) red1[tid >> 5] = ss;
    __syncthreads();
    const float inv = 1.0f / fmaxf(sqrtf(red1[0] + red1[1] + red1[2] + red1[3]), 1e-12f);
    float4 w = ((const float4*)wb)[tid];
    float bd = v.x * w.x + v.y * w.y + v.z * w.z + v.w * w.w;
#pragma unroll
    for (int o = 16; o; o >>= 1) bd += __shfl_xor_sync(0xffffffffu, bd, o);
    __shared__ float red2[4];
    if ((tid & 31) == 0) red2[tid >> 5] = bd;
    __syncthreads();
    v.x *= inv; v.y *= inv; v.z *= inv; v.w *= inv;
    ((float4*)(Kd + (size_t)row * Dd))[tid] = v;
    if (tid == 0) {
        const float z = (red2[0] + red2[1] + red2[2] + red2[3]) * inv + bb[0];
        Beta[row] = 1.0f / (1.0f + expf(-z));
    }
}

// ---------------- per-chunk A,G Gram matrices, f32x2 dot ----------------
__global__ __launch_bounds__(256) void chunk_ag_kernel(
    const float* __restrict__ Qd, const float* __restrict__ Kd,
    const float* __restrict__ Beta, float* __restrict__ Ag, float* __restrict__ Gg)
{
    const int c = blockIdx.x, b = blockIdx.y;
    const int r0 = b * Tt + c * CH;
    __shared__ float Ks[64 * 66];
    __shared__ float Qs[64 * 66];
    const int tid = threadIdx.x;
    const int t0 = (tid >> 4) * 4, j0 = (tid & 15) * 4;

    ull accA[4][4], accG[4][4];
#pragma unroll
    for (int i = 0; i < 4; i++)
#pragma unroll
        for (int j = 0; j < 4; j++) { accA[i][j] = 0ull; accG[i][j] = 0ull; }

    for (int dt = 0; dt < 8; dt++) {
        __syncthreads();
#pragma unroll
        for (int n = 0; n < 4; n++) {
            const int f4 = tid + n * 256;
            const int row = f4 >> 4, col = (f4 & 15) * 4;
            float4 kv = *(const float4*)&Kd[(size_t)(r0 + row) * Dd + dt * 64 + col];
            float4 qv = *(const float4*)&Qd[(size_t)(r0 + row) * Dd + dt * 64 + col];
            const int so = row * 66 + col;
            Ks[so] = kv.x; Ks[so + 1] = kv.y; Ks[so + 2] = kv.z; Ks[so + 3] = kv.w;
            Qs[so] = qv.x; Qs[so + 1] = qv.y; Qs[so + 2] = qv.z; Qs[so + 3] = qv.w;
        }
        __syncthreads();
#pragma unroll 2
        for (int dd = 0; dd < 64; dd += 2) {
            ull kt[4], kj[4], qt[4];
#pragma unroll
            for (int i = 0; i < 4; i++) {
                kt[i] = *(const ull*)&Ks[(t0 + i) * 66 + dd];
                qt[i] = *(const ull*)&Qs[(t0 + i) * 66 + dd];
                kj[i] = *(const ull*)&Ks[(j0 + i) * 66 + dd];
            }
#pragma unroll
            for (int i = 0; i < 4; i++)
#pragma unroll
                for (int j = 0; j < 4; j++) {
                    fma2(accA[i][j], kt[i], kj[j]);
                    fma2(accG[i][j], qt[i], kj[j]);
                }
        }
    }
    const size_t base = ((size_t)(b * NCH) + c) * (CH * CH);
#pragma unroll
    for (int i = 0; i < 4; i++) {
        const int t = t0 + i;
        const float bt = Beta[r0 + t];
#pragma unroll
        for (int j = 0; j < 4; j++) {
            const int jj = j0 + j;
            Ag[base + t * CH + jj] = (jj < t) ? bt * hadd(accA[i][j]) : 0.f;
            Gg[base + t * CH + jj] = (jj <= t) ? hadd(accG[i][j]) : 0.f;
        }
    }
}

// ---------------- chunked delta-rule scan, f32x2 ----------------
__global__ __launch_bounds__(256) void scan_kernel(
    const float* __restrict__ Qd, const float* __restrict__ Kd,
    const float* __restrict__ Vd, const float* __restrict__ Betad,
    const float* __restrict__ Ag, const float* __restrict__ Gg,
    float* __restrict__ Od)
{
    extern __shared__ float sm[];
    float* S     = sm + SM_S;
    float* Kt    = sm + SM_KT;
    float* Qt    = sm + SM_QT;
    float* As    = sm + SM_A;
    float* Gs    = sm + SM_G;
    float* Um    = sm + SM_U;
    float* QSm   = sm + SM_QS;
    float* Vb    = sm + SM_VB;
    float* betas = sm + SM_BETA;

    const int b = blockIdx.y;
    const int i0 = blockIdx.x * DV;
    const int tid = threadIdx.x;
    const int lane = tid & 31, wid = tid >> 5;

    for (int e = tid; e < 32 * 512; e += 256) S[e] = 0.f;
    __syncthreads();

    for (int c = 0; c < NCH; c++) {
        const int r0 = b * Tt + c * CH;
        const size_t agbase = ((size_t)(b * NCH) + c) * (CH * CH);

        for (int e = tid; e < CH * CH; e += 256) {
            const int t = e >> 6, j = e & 63;
            As[t * 66 + j] = Ag[agbase + e];
            Gs[t * 66 + j] = Gg[agbase + e];
        }
        for (int e = tid; e < CH * DV; e += 256) {
            const int t = e >> 5, i = e & 31;
            Vb[t * 34 + i] = Vd[(size_t)(r0 + t) * Dd + i0 + i];
        }
        if (tid < 64) betas[tid] = Betad[r0 + tid];
        __syncthreads();

        // Phase A: KS=K@S^T, QS=Q@S^T (64x32). dot-pairs along d.
        const int t0 = lane * 2;
        const int ii = wid * 4;
        ull aKS[2][4], aQS[2][4];
#pragma unroll
        for (int r = 0; r < 2; r++)
#pragma unroll
            for (int i = 0; i < 4; i++) { aKS[r][i] = 0ull; aQS[r][i] = 0ull; }

        for (int jt = 0; jt < 4; jt++) {
            __syncthreads();
#pragma unroll
            for (int n = 0; n < 8; n++) {
                const int f4 = tid + n * 256;
                const int row = f4 >> 5, col = (f4 & 31) * 4;
                float4 kv = *(const float4*)&Kd[(size_t)(r0 + row) * Dd + jt * 128 + col];
                float4 qv = *(const float4*)&Qd[(size_t)(r0 + row) * Dd + jt * 128 + col];
                const int so = row * 130 + col;
                Kt[so] = kv.x; Kt[so + 1] = kv.y; Kt[so + 2] = kv.z; Kt[so + 3] = kv.w;
                Qt[so] = qv.x; Qt[so + 1] = qv.y; Qt[so + 2] = qv.z; Qt[so + 3] = qv.w;
            }
            __syncthreads();
            const float* Sp = S + ii * 512 + jt * 128;
#pragma unroll 2
            for (int dd = 0; dd < 128; dd += 2) {
                ull k0 = *(const ull*)&Kt[t0 * 130 + dd];
                ull k1 = *(const ull*)&Kt[(t0 + 1) * 130 + dd];
                ull q0 = *(const ull*)&Qt[t0 * 130 + dd];
                ull q1 = *(const ull*)&Qt[(t0 + 1) * 130 + dd];
#pragma unroll
                for (int i = 0; i < 4; i++) {
                    ull sv = *(const ull*)&Sp[i * 512 + dd];
                    fma2(aKS[0][i], k0, sv); fma2(aKS[1][i], k1, sv);
                    fma2(aQS[0][i], q0, sv); fma2(aQS[1][i], q1, sv);
                }
            }
        }
        __syncthreads();
#pragma unroll
        for (int r = 0; r < 2; r++) {
            const int t = t0 + r;
            const float bt = betas[t];
#pragma unroll
            for (int i = 0; i < 4; i++) {
                Um[t * 34 + ii + i]  = bt * (Vb[t * 34 + ii + i] - hadd(aKS[r][i]));
                QSm[t * 34 + ii + i] = hadd(aQS[r][i]);
            }
        }
        __syncthreads();

        // Phase B: blocked forward substitution
#pragma unroll
        for (int blk = 0; blk < 4; blk++) {
            const int bt0 = blk * 16;
            if (wid == 0) {
                for (int t = bt0; t < bt0 + 16; t++) {
                    float s = Um[t * 34 + lane];
                    for (int j = bt0; j < t; j++)
                        s -= As[t * 66 + j] * Um[j * 34 + lane];
                    Um[t * 34 + lane] = s;
                }
            }
            __syncthreads();
            if (blk < 3) {
                const int rem = 64 - (blk + 1) * 16;
                for (int e = tid; e < rem * 32; e += 256) {
                    const int t = (blk + 1) * 16 + (e >> 5);
                    const int i = e & 31;
                    float s = Um[t * 34 + i];
#pragma unroll
                    for (int j = 0; j < 16; j++)
                        s -= As[t * 66 + bt0 + j] * Um[(bt0 + j) * 34 + i];
                    Um[t * 34 + i] = s;
                }
                __syncthreads();
            }
        }

        // Phase C: O = QS + tril(G)@U (pair along i)
        for (int e = tid; e < CH * 16; e += 256) {
            const int t = e >> 4, ip = (e & 15) * 2;
            ull s2 = *(const ull*)&QSm[t * 34 + ip];
            for (int j = 0; j <= t; j++) {
                ull g2 = pk(Gs[t * 66 + j], Gs[t * 66 + j]);
                fma2(s2, g2, *(const ull*)&Um[j * 34 + ip]);
            }
            *(float2*)&Od[(size_t)(r0 + t) * Dd + i0 + ip] = upk(s2);
        }

        // Phase D: S += U^T @ K  (d-pairs, packed accumulators)
        for (int jt = 0; jt < 4; jt++) {
            __syncthreads();
#pragma unroll
            for (int n = 0; n < 8; n++) {
                const int f4 = tid + n * 256;
                const int row = f4 >> 5, col = (f4 & 31) * 4;
                float4 kv = *(const float4*)&Kd[(size_t)(r0 + row) * Dd + jt * 128 + col];
                const int so = row * 130 + col;
                Kt[so] = kv.x; Kt[so + 1] = kv.y; Kt[so + 2] = kv.z; Kt[so + 3] = kv.w;
            }
            __syncthreads();
            const int d0 = lane * 2;
            ull sacc[4][2];
#pragma unroll
            for (int ig = 0; ig < 4; ig++)
#pragma unroll
                for (int g = 0; g < 2; g++)
                    sacc[ig][g] = *(const ull*)&S[(ii + ig) * 512 + jt * 128 + g * 64 + d0];
#pragma unroll 4
            for (int t = 0; t < 64; t++) {
                float2 ua = *(const float2*)&Um[t * 34 + ii];
                float2 ub = *(const float2*)&Um[t * 34 + ii + 2];
                ull ud[4] = { pk(ua.x, ua.x), pk(ua.y, ua.y), pk(ub.x, ub.x), pk(ub.y, ub.y) };
                ull kp0 = *(const ull*)&Kt[t * 130 + d0];
                ull kp1 = *(const ull*)&Kt[t * 130 + 64 + d0];
#pragma unroll
                for (int ig = 0; ig < 4; ig++) {
                    fma2(sacc[ig][0], ud[ig], kp0);
                    fma2(sacc[ig][1], ud[ig], kp1);
                }
            }
#pragma unroll
            for (int ig = 0; ig < 4; ig++)
#pragma unroll
                for (int g = 0; g < 2; g++)
                    *(ull*)&S[(ii + ig) * 512 + jt * 128 + g * 64 + d0] = sacc[ig][g];
        }
        __syncthreads();
    }
}

extern "C" void kernel_launch(void* const* d_in, const int* in_sizes, int n_in,
                              void* d_out, int out_size)
{
    const float* x     = (const float*)d_in[0];
    const float* Wq    = (const float*)d_in[1];
    const float* bq    = (const float*)d_in[2];
    const float* Wk    = (const float*)d_in[3];
    const float* bk    = (const float*)d_in[4];
    const float* Wv    = (const float*)d_in[5];
    const float* bv    = (const float*)d_in[6];
    const float* Wbeta = (const float*)d_in[7];
    const float* bbeta = (const float*)d_in[8];
    const float* Wo    = (const float*)d_in[9];
    const float* bo    = (const float*)d_in[10];
    float* out = (float*)d_out;

    float *pQ, *pK, *pV, *pO, *pBeta, *pA, *pG;
    cudaGetSymbolAddress((void**)&pQ, g_Q);
    cudaGetSymbolAddress((void**)&pK, g_K);
    cudaGetSymbolAddress((void**)&pV, g_V);
    cudaGetSymbolAddress((void**)&pO, g_O);
    cudaGetSymbolAddress((void**)&pBeta, g_Beta);
    cudaGetSymbolAddress((void**)&pA, g_A);
    cudaGetSymbolAddress((void**)&pG, g_G);

    __nv_bfloat16 *pxh, *pxl, *poh, *pol;
    __nv_bfloat16 *pwqh, *pwql, *pwkh, *pwkl, *pwvh, *pwvl, *pwoh, *pwol;
    cudaGetSymbolAddress((void**)&pxh, g_xh);
    cudaGetSymbolAddress((void**)&pxl, g_xl);
    cudaGetSymbolAddress((void**)&poh, g_oh);
    cudaGetSymbolAddress((void**)&pol, g_ol);
    cudaGetSymbolAddress((void**)&pwqh, g_wqh);
    cudaGetSymbolAddress((void**)&pwql, g_wql);
    cudaGetSymbolAddress((void**)&pwkh, g_wkh);
    cudaGetSymbolAddress((void**)&pwkl, g_wkl);
    cudaGetSymbolAddress((void**)&pwvh, g_wvh);
    cudaGetSymbolAddress((void**)&pwvl, g_wvl);
    cudaGetSymbolAddress((void**)&pwoh, g_woh);
    cudaGetSymbolAddress((void**)&pwol, g_wol);

    cudaFuncSetAttribute(scan_kernel,
                         cudaFuncAttributeMaxDynamicSharedMemorySize, SMEM_BYTES);

    const int nx4 = BT * Dd / 4;        // 2097152
    const int nw4 = Dd * Dd / 4;        // 65536
    split_kernel<<<(nx4 + 255) / 256, 256>>>(x, pxh, pxl, nx4);
    split_kernel<<<(nw4 + 255) / 256, 256>>>(Wq, pwqh, pwql, nw4);
    split_kernel<<<(nw4 + 255) / 256, 256>>>(Wk, pwkh, pwkl, nw4);
    split_kernel<<<(nw4 + 255) / 256, 256>>>(Wv, pwvh, pwvl, nw4);
    split_kernel<<<(nw4 + 255) / 256, 256>>>(Wo, pwoh, pwol, nw4);

    dim3 tgrid(Dd / 128, BT / 128);   // (4, 128)
    tgemm_mma_kernel<<<tgrid, 256>>>(pxh, pxl, pwqh, pwql, bq, pQ);
    tgemm_mma_kernel<<<tgrid, 256>>>(pxh, pxl, pwkh, pwkl, bk, pK);
    tgemm_mma_kernel<<<tgrid, 256>>>(pxh, pxl, pwvh, pwvl, bv, pV);

    norm_beta_kernel<<<BT, 128>>>(pK, Wbeta, bbeta, pBeta);

    chunk_ag_kernel<<<dim3(NCH, Bb), 256>>>(pQ, pK, pBeta, pA, pG);

    scan_kernel<<<dim3(NVT, Bb), 256, SMEM_BYTES>>>(pQ, pK, pV, pBeta, pA, pG, pO);

    split_kernel<<<(nx4 + 255) / 256, 256>>>(pO, poh, pol, nx4);
    tgemm_mma_kernel<<<tgrid, 256>>>(poh, pol, pwoh, pwol, bo, out);
}

// round 7
// speedup vs baseline: 2.1422x; 1.0361x over previous
#include <cuda_runtime.h>
#include <cuda_bf16.h>
#include <math.h>
#include <stdint.h>

namespace {
constexpr int Bb  = 8;
constexpr int Tt  = 2048;
constexpr int Dd  = 512;
constexpr int BT  = Bb * Tt;
constexpr int CH  = 64;
constexpr int NCH = Tt / CH;   // 32
constexpr int DV  = 32;
constexpr int NVT = Dd / DV;   // 16
// scan smem (float offsets, all even)
constexpr int SM_S    = 0;                    // [32][512]
constexpr int SM_KT   = SM_S  + 32 * 512;     // [64][130]
constexpr int SM_QT   = SM_KT + 64 * 130;     // [64][130]
constexpr int SM_A    = SM_QT + 64 * 130;     // [64][66]
constexpr int SM_G    = SM_A  + 64 * 66;      // [64][66]
constexpr int SM_U    = SM_G  + 64 * 66;      // [64][34]
constexpr int SM_QS   = SM_U  + 64 * 34;      // [64][34]
constexpr int SM_VB   = SM_QS + 64 * 34;      // [64][34]
constexpr int SM_BETA = SM_VB + 64 * 34;      // [64]
constexpr int SM_TOT  = SM_BETA + 64;
constexpr int SMEM_BYTES = SM_TOT * 4;        // 192256 B
}

using ull = unsigned long long;
__device__ __forceinline__ ull pk(float x, float y) {
    ull r; asm("mov.b64 %0,{%1,%2};" : "=l"(r) : "f"(x), "f"(y)); return r;
}
__device__ __forceinline__ float2 upk(ull v) {
    float2 r; asm("mov.b64 {%0,%1},%2;" : "=f"(r.x), "=f"(r.y) : "l"(v)); return r;
}
__device__ __forceinline__ void fma2(ull& d, ull a, ull b) {
    asm("fma.rn.f32x2 %0,%1,%2,%0;" : "+l"(d) : "l"(a), "l"(b));
}
__device__ __forceinline__ float hadd(ull v) { float2 f = upk(v); return f.x + f.y; }

// ---------------- device scratch ----------------
__device__ float g_Q[BT * Dd];
__device__ float g_K[BT * Dd];
__device__ float g_V[BT * Dd];
__device__ float g_O[BT * Dd];
__device__ float g_Beta[BT];
__device__ float g_A[Bb * NCH * CH * CH];
__device__ float g_G[Bb * NCH * CH * CH];
__device__ __nv_bfloat16 g_xh[BT * Dd];
__device__ __nv_bfloat16 g_xl[BT * Dd];
__device__ __nv_bfloat16 g_oh[BT * Dd];
__device__ __nv_bfloat16 g_ol[BT * Dd];
__device__ __nv_bfloat16 g_wqh[Dd * Dd];
__device__ __nv_bfloat16 g_wql[Dd * Dd];
__device__ __nv_bfloat16 g_wkh[Dd * Dd];
__device__ __nv_bfloat16 g_wkl[Dd * Dd];
__device__ __nv_bfloat16 g_wvh[Dd * Dd];
__device__ __nv_bfloat16 g_wvl[Dd * Dd];
__device__ __nv_bfloat16 g_woh[Dd * Dd];
__device__ __nv_bfloat16 g_wol[Dd * Dd];

__device__ __forceinline__ uint32_t smem_u32(const void* p) {
    uint32_t a;
    asm("{ .reg .u64 t; cvta.to.shared.u64 t,%1; cvt.u32.u64 %0,t; }" : "=r"(a) : "l"(p));
    return a;
}
__device__ __forceinline__ void ldsm_x4(uint32_t* r, uint32_t addr) {
    asm volatile("ldmatrix.sync.aligned.m8n8.x4.shared.b16 {%0,%1,%2,%3}, [%4];"
                 : "=r"(r[0]), "=r"(r[1]), "=r"(r[2]), "=r"(r[3]) : "r"(addr));
}
__device__ __forceinline__ void mma_bf16(float* d, const uint32_t* a,
                                         uint32_t b0, uint32_t b1) {
    asm volatile(
        "mma.sync.aligned.m16n8k16.row.col.f32.bf16.bf16.f32 "
        "{%0,%1,%2,%3}, {%4,%5,%6,%7}, {%8,%9}, {%0,%1,%2,%3};"
        : "+f"(d[0]), "+f"(d[1]), "+f"(d[2]), "+f"(d[3])
        : "r"(a[0]), "r"(a[1]), "r"(a[2]), "r"(a[3]), "r"(b0), "r"(b1));
}
__device__ __forceinline__ void cp16(uint32_t dst, const void* src) {
    asm volatile("cp.async.ca.shared.global [%0], [%1], 16;" :: "r"(dst), "l"(src));
}

// ---------------- split fp32 -> bf16 hi/lo ----------------
__global__ __launch_bounds__(256) void split_kernel(
    const float* __restrict__ x, __nv_bfloat16* __restrict__ h,
    __nv_bfloat16* __restrict__ l, int n4)
{
    int i = blockIdx.x * 256 + threadIdx.x;
    if (i >= n4) return;
    float4 v = ((const float4*)x)[i];
    __nv_bfloat16 h0 = __float2bfloat16(v.x);
    __nv_bfloat16 h1 = __float2bfloat16(v.y);
    __nv_bfloat16 h2 = __float2bfloat16(v.z);
    __nv_bfloat16 h3 = __float2bfloat16(v.w);
    __nv_bfloat16 l0 = __float2bfloat16(v.x - __bfloat162float(h0));
    __nv_bfloat16 l1 = __float2bfloat16(v.y - __bfloat162float(h1));
    __nv_bfloat16 l2 = __float2bfloat16(v.z - __bfloat162float(h2));
    __nv_bfloat16 l3 = __float2bfloat16(v.w - __bfloat162float(h3));
    ((__nv_bfloat162*)h)[2 * i + 0] = __halves2bfloat162(h0, h1);
    ((__nv_bfloat162*)h)[2 * i + 1] = __halves2bfloat162(h2, h3);
    ((__nv_bfloat162*)l)[2 * i + 0] = __halves2bfloat162(l0, l1);
    ((__nv_bfloat162*)l)[2 * i + 1] = __halves2bfloat162(l2, l3);
}

// ---------------- HMMA split-bf16 GEMM, cp.async double-buffered ----------------
// CTA 128x128, 8 warps (2m x 4n), warp tile 64x32, K staged 32 at a time.
// 48 stages = 3 passes (hh, hl, lh) x 16 K-tiles, 2-stage smem pipeline.
__global__ __launch_bounds__(256) void tgemm_mma_kernel(
    const __nv_bfloat16* __restrict__ Ah, const __nv_bfloat16* __restrict__ Al,
    const __nv_bfloat16* __restrict__ Bh, const __nv_bfloat16* __restrict__ Bl,
    const float* __restrict__ bias, float* __restrict__ C)
{
    __shared__ __align__(16) __nv_bfloat16 sA[2][128 * 40];
    __shared__ __align__(16) __nv_bfloat16 sB[2][128 * 40];
    constexpr uint32_t BUFB = 128 * 40 * 2;   // bytes per buffer

    const int tid = threadIdx.x, lane = tid & 31, wid = tid >> 5;
    const int wm = wid & 1, wn = wid >> 1;     // warp grid 2(m) x 4(n)
    const int bm = blockIdx.y * 128, bn = blockIdx.x * 128;

    float d[4][4][4];
#pragma unroll
    for (int mt = 0; mt < 4; mt++)
#pragma unroll
        for (int nt = 0; nt < 4; nt++)
#pragma unroll
            for (int e = 0; e < 4; e++) d[mt][nt][e] = 0.f;

    // ldmatrix addresses for buffer 0 (row stride 40 halves = 80 B)
    const uint32_t aBase = smem_u32(sA[0]), bBase = smem_u32(sB[0]);
    uint32_t a_addr[4], b_addr[2];
    {
        const int ar = lane & 15, akoff = (lane >> 4) * 8;
#pragma unroll
        for (int mt = 0; mt < 4; mt++)
            a_addr[mt] = aBase + ((wm * 64 + mt * 16 + ar) * 40 + akoff) * 2;
        const int nrow = wn * 32 + ((lane >> 4) * 8) + (lane & 7);
        const int khalf = (lane >> 3) & 1;
#pragma unroll
        for (int np = 0; np < 2; np++)
            b_addr[np] = bBase + ((nrow + np * 16) * 40 + khalf * 8) * 2;
    }

    // per-thread staging coords: 2 chunks of 16B for A and B each
    const int srow0 = tid >> 2,          sc0 = tid & 3;
    const int srow1 = (tid + 256) >> 2,  sc1 = (tid + 256) & 3;
    const uint32_t sa0 = smem_u32(sA[0]) + srow0 * 80 + sc0 * 16;
    const uint32_t sa1 = smem_u32(sA[0]) + srow1 * 80 + sc1 * 16;
    const uint32_t sb0 = smem_u32(sB[0]) + srow0 * 80 + sc0 * 16;
    const uint32_t sb1 = smem_u32(sB[0]) + srow1 * 80 + sc1 * 16;

    auto issue = [&](int s, int buf) {
        const int p = s >> 4, kt = s & 15;
        const __nv_bfloat16* Ap = (p == 2) ? Al : Ah;
        const __nv_bfloat16* Bp = (p == 1) ? Bl : Bh;
        const uint32_t bo = buf * BUFB;
        cp16(sa0 + bo, Ap + (size_t)(bm + srow0) * Dd + kt * 32 + sc0 * 8);
        cp16(sa1 + bo, Ap + (size_t)(bm + srow1) * Dd + kt * 32 + sc1 * 8);
        cp16(sb0 + bo, Bp + (size_t)(bn + srow0) * Dd + kt * 32 + sc0 * 8);
        cp16(sb1 + bo, Bp + (size_t)(bn + srow1) * Dd + kt * 32 + sc1 * 8);
        asm volatile("cp.async.commit_group;");
    };

    issue(0, 0);
#pragma unroll 1
    for (int s = 0; s < 48; s++) {
        const int buf = s & 1;
        if (s + 1 < 48) {
            issue(s + 1, buf ^ 1);
            asm volatile("cp.async.wait_group 1;");
        } else {
            asm volatile("cp.async.wait_group 0;");
        }
        __syncthreads();
        const uint32_t bo = buf * BUFB;
#pragma unroll
        for (int ks = 0; ks < 2; ks++) {
            uint32_t a[4][4], b[2][4];
#pragma unroll
            for (int mt = 0; mt < 4; mt++) ldsm_x4(a[mt], a_addr[mt] + bo + ks * 32);
#pragma unroll
            for (int np = 0; np < 2; np++) ldsm_x4(b[np], b_addr[np] + bo + ks * 32);
#pragma unroll
            for (int mt = 0; mt < 4; mt++)
#pragma unroll
                for (int nt = 0; nt < 4; nt++)
                    mma_bf16(d[mt][nt], a[mt],
                             b[nt >> 1][(nt & 1) * 2], b[nt >> 1][(nt & 1) * 2 + 1]);
        }
        __syncthreads();
    }

    // epilogue
#pragma unroll
    for (int mt = 0; mt < 4; mt++) {
        const int r0 = bm + wm * 64 + mt * 16 + (lane >> 2);
#pragma unroll
        for (int nt = 0; nt < 4; nt++) {
            const int c0 = bn + wn * 32 + nt * 8 + (lane & 3) * 2;
            const float b0 = bias[c0], b1 = bias[c0 + 1];
            float2 o0 = make_float2(d[mt][nt][0] + b0, d[mt][nt][1] + b1);
            float2 o1 = make_float2(d[mt][nt][2] + b0, d[mt][nt][3] + b1);
            *(float2*)&C[(size_t)r0 * Dd + c0] = o0;
            *(float2*)&C[(size_t)(r0 + 8) * Dd + c0] = o1;
        }
    }
}

// ---------------- l2norm + beta ----------------
__global__ __launch_bounds__(128) void norm_beta_kernel(
    float* __restrict__ Kd, const float* __restrict__ wb,
    const float* __restrict__ bb, float* __restrict__ Beta)
{
    const int row = blockIdx.x, tid = threadIdx.x;
    float4 v = ((const float4*)(Kd + (size_t)row * Dd))[tid];
    float ss = v.x * v.x + v.y * v.y + v.z * v.z + v.w * v.w;
#pragma unroll
    for (int o = 16; o; o >>= 1) ss += __shfl_xor_sync(0xffffffffu, ss, o);
    __shared__ float red1[4];
    if ((tid & 31) == 0) red1[tid >> 5] = ss;
    __syncthreads();
    const float inv = 1.0f / fmaxf(sqrtf(red1[0] + red1[1] + red1[2] + red1[3]), 1e-12f);
    float4 w = ((const float4*)wb)[tid];
    float bd = v.x * w.x + v.y * w.y + v.z * w.z + v.w * w.w;
#pragma unroll
    for (int o = 16; o; o >>= 1) bd += __shfl_xor_sync(0xffffffffu, bd, o);
    __shared__ float red2[4];
    if ((tid & 31) == 0) red2[tid >> 5] = bd;
    __syncthreads();
    v.x *= inv; v.y *= inv; v.z *= inv; v.w *= inv;
    ((float4*)(Kd + (size_t)row * Dd))[tid] = v;
    if (tid == 0) {
        const float z = (red2[0] + red2[1] + red2[2] + red2[3]) * inv + bb[0];
        Beta[row] = 1.0f / (1.0f + expf(-z));
    }
}

// ---------------- per-chunk A,G Gram matrices, f32x2 dot ----------------
__global__ __launch_bounds__(256) void chunk_ag_kernel(
    const float* __restrict__ Qd, const float* __restrict__ Kd,
    const float* __restrict__ Beta, float* __restrict__ Ag, float* __restrict__ Gg)
{
    const int c = blockIdx.x, b = blockIdx.y;
    const int r0 = b * Tt + c * CH;
    __shared__ float Ks[64 * 66];
    __shared__ float Qs[64 * 66];
    const int tid = threadIdx.x;
    const int t0 = (tid >> 4) * 4, j0 = (tid & 15) * 4;

    ull accA[4][4], accG[4][4];
#pragma unroll
    for (int i = 0; i < 4; i++)
#pragma unroll
        for (int j = 0; j < 4; j++) { accA[i][j] = 0ull; accG[i][j] = 0ull; }

    for (int dt = 0; dt < 8; dt++) {
        __syncthreads();
#pragma unroll
        for (int n = 0; n < 4; n++) {
            const int f4 = tid + n * 256;
            const int row = f4 >> 4, col = (f4 & 15) * 4;
            float4 kv = *(const float4*)&Kd[(size_t)(r0 + row) * Dd + dt * 64 + col];
            float4 qv = *(const float4*)&Qd[(size_t)(r0 + row) * Dd + dt * 64 + col];
            const int so = row * 66 + col;
            Ks[so] = kv.x; Ks[so + 1] = kv.y; Ks[so + 2] = kv.z; Ks[so + 3] = kv.w;
            Qs[so] = qv.x; Qs[so + 1] = qv.y; Qs[so + 2] = qv.z; Qs[so + 3] = qv.w;
        }
        __syncthreads();
#pragma unroll 2
        for (int dd = 0; dd < 64; dd += 2) {
            ull kt[4], kj[4], qt[4];
#pragma unroll
            for (int i = 0; i < 4; i++) {
                kt[i] = *(const ull*)&Ks[(t0 + i) * 66 + dd];
                qt[i] = *(const ull*)&Qs[(t0 + i) * 66 + dd];
                kj[i] = *(const ull*)&Ks[(j0 + i) * 66 + dd];
            }
#pragma unroll
            for (int i = 0; i < 4; i++)
#pragma unroll
                for (int j = 0; j < 4; j++) {
                    fma2(accA[i][j], kt[i], kj[j]);
                    fma2(accG[i][j], qt[i], kj[j]);
                }
        }
    }
    const size_t base = ((size_t)(b * NCH) + c) * (CH * CH);
#pragma unroll
    for (int i = 0; i < 4; i++) {
        const int t = t0 + i;
        const float bt = Beta[r0 + t];
#pragma unroll
        for (int j = 0; j < 4; j++) {
            const int jj = j0 + j;
            Ag[base + t * CH + jj] = (jj < t) ? bt * hadd(accA[i][j]) : 0.f;
            Gg[base + t * CH + jj] = (jj <= t) ? hadd(accG[i][j]) : 0.f;
        }
    }
}

// ---------------- chunked delta-rule scan, f32x2 ----------------
__global__ __launch_bounds__(256) void scan_kernel(
    const float* __restrict__ Qd, const float* __restrict__ Kd,
    const float* __restrict__ Vd, const float* __restrict__ Betad,
    const float* __restrict__ Ag, const float* __restrict__ Gg,
    float* __restrict__ Od)
{
    extern __shared__ float sm[];
    float* S     = sm + SM_S;
    float* Kt    = sm + SM_KT;
    float* Qt    = sm + SM_QT;
    float* As    = sm + SM_A;
    float* Gs    = sm + SM_G;
    float* Um    = sm + SM_U;
    float* QSm   = sm + SM_QS;
    float* Vb    = sm + SM_VB;
    float* betas = sm + SM_BETA;

    const int b = blockIdx.y;
    const int i0 = blockIdx.x * DV;
    const int tid = threadIdx.x;
    const int lane = tid & 31, wid = tid >> 5;

    for (int e = tid; e < 32 * 512; e += 256) S[e] = 0.f;
    __syncthreads();

    for (int c = 0; c < NCH; c++) {
        const int r0 = b * Tt + c * CH;
        const size_t agbase = ((size_t)(b * NCH) + c) * (CH * CH);

        for (int e = tid; e < CH * CH; e += 256) {
            const int t = e >> 6, j = e & 63;
            As[t * 66 + j] = Ag[agbase + e];
            Gs[t * 66 + j] = Gg[agbase + e];
        }
        for (int e = tid; e < CH * DV; e += 256) {
            const int t = e >> 5, i = e & 31;
            Vb[t * 34 + i] = Vd[(size_t)(r0 + t) * Dd + i0 + i];
        }
        if (tid < 64) betas[tid] = Betad[r0 + tid];
        __syncthreads();

        // Phase A: KS=K@S^T, QS=Q@S^T (64x32). dot-pairs along d.
        const int t0 = lane * 2;
        const int ii = wid * 4;
        ull aKS[2][4], aQS[2][4];
#pragma unroll
        for (int r = 0; r < 2; r++)
#pragma unroll
            for (int i = 0; i < 4; i++) { aKS[r][i] = 0ull; aQS[r][i] = 0ull; }

        for (int jt = 0; jt < 4; jt++) {
            __syncthreads();
#pragma unroll
            for (int n = 0; n < 8; n++) {
                const int f4 = tid + n * 256;
                const int row = f4 >> 5, col = (f4 & 31) * 4;
                float4 kv = *(const float4*)&Kd[(size_t)(r0 + row) * Dd + jt * 128 + col];
                float4 qv = *(const float4*)&Qd[(size_t)(r0 + row) * Dd + jt * 128 + col];
                const int so = row * 130 + col;
                Kt[so] = kv.x; Kt[so + 1] = kv.y; Kt[so + 2] = kv.z; Kt[so + 3] = kv.w;
                Qt[so] = qv.x; Qt[so + 1] = qv.y; Qt[so + 2] = qv.z; Qt[so + 3] = qv.w;
            }
            __syncthreads();
            const float* Sp = S + ii * 512 + jt * 128;
#pragma unroll 2
            for (int dd = 0; dd < 128; dd += 2) {
                ull k0 = *(const ull*)&Kt[t0 * 130 + dd];
                ull k1 = *(const ull*)&Kt[(t0 + 1) * 130 + dd];
                ull q0 = *(const ull*)&Qt[t0 * 130 + dd];
                ull q1 = *(const ull*)&Qt[(t0 + 1) * 130 + dd];
#pragma unroll
                for (int i = 0; i < 4; i++) {
                    ull sv = *(const ull*)&Sp[i * 512 + dd];
                    fma2(aKS[0][i], k0, sv); fma2(aKS[1][i], k1, sv);
                    fma2(aQS[0][i], q0, sv); fma2(aQS[1][i], q1, sv);
                }
            }
        }
        __syncthreads();
#pragma unroll
        for (int r = 0; r < 2; r++) {
            const int t = t0 + r;
            const float bt = betas[t];
#pragma unroll
            for (int i = 0; i < 4; i++) {
                Um[t * 34 + ii + i]  = bt * (Vb[t * 34 + ii + i] - hadd(aKS[r][i]));
                QSm[t * 34 + ii + i] = hadd(aQS[r][i]);
            }
        }
        __syncthreads();

        // Phase B: blocked forward substitution
#pragma unroll
        for (int blk = 0; blk < 4; blk++) {
            const int bt0 = blk * 16;
            if (wid == 0) {
                for (int t = bt0; t < bt0 + 16; t++) {
                    float s = Um[t * 34 + lane];
                    for (int j = bt0; j < t; j++)
                        s -= As[t * 66 + j] * Um[j * 34 + lane];
                    Um[t * 34 + lane] = s;
                }
            }
            __syncthreads();
            if (blk < 3) {
                const int rem = 64 - (blk + 1) * 16;
                for (int e = tid; e < rem * 32; e += 256) {
                    const int t = (blk + 1) * 16 + (e >> 5);
                    const int i = e & 31;
                    float s = Um[t * 34 + i];
#pragma unroll
                    for (int j = 0; j < 16; j++)
                        s -= As[t * 66 + bt0 + j] * Um[(bt0 + j) * 34 + i];
                    Um[t * 34 + i] = s;
                }
                __syncthreads();
            }
        }

        // Phase C: O = QS + tril(G)@U (pair along i)
        for (int e = tid; e < CH * 16; e += 256) {
            const int t = e >> 4, ip = (e & 15) * 2;
            ull s2 = *(const ull*)&QSm[t * 34 + ip];
            for (int j = 0; j <= t; j++) {
                ull g2 = pk(Gs[t * 66 + j], Gs[t * 66 + j]);
                fma2(s2, g2, *(const ull*)&Um[j * 34 + ip]);
            }
            *(float2*)&Od[(size_t)(r0 + t) * Dd + i0 + ip] = upk(s2);
        }

        // Phase D: S += U^T @ K  (d-pairs, packed accumulators)
        for (int jt = 0; jt < 4; jt++) {
            __syncthreads();
#pragma unroll
            for (int n = 0; n < 8; n++) {
                const int f4 = tid + n * 256;
                const int row = f4 >> 5, col = (f4 & 31) * 4;
                float4 kv = *(const float4*)&Kd[(size_t)(r0 + row) * Dd + jt * 128 + col];
                const int so = row * 130 + col;
                Kt[so] = kv.x; Kt[so + 1] = kv.y; Kt[so + 2] = kv.z; Kt[so + 3] = kv.w;
            }
            __syncthreads();
            const int d0 = lane * 2;
            ull sacc[4][2];
#pragma unroll
            for (int ig = 0; ig < 4; ig++)
#pragma unroll
                for (int g = 0; g < 2; g++)
                    sacc[ig][g] = *(const ull*)&S[(ii + ig) * 512 + jt * 128 + g * 64 + d0];
#pragma unroll 4
            for (int t = 0; t < 64; t++) {
                float2 ua = *(const float2*)&Um[t * 34 + ii];
                float2 ub = *(const float2*)&Um[t * 34 + ii + 2];
                ull ud[4] = { pk(ua.x, ua.x), pk(ua.y, ua.y), pk(ub.x, ub.x), pk(ub.y, ub.y) };
                ull kp0 = *(const ull*)&Kt[t * 130 + d0];
                ull kp1 = *(const ull*)&Kt[t * 130 + 64 + d0];
#pragma unroll
                for (int ig = 0; ig < 4; ig++) {
                    fma2(sacc[ig][0], ud[ig], kp0);
                    fma2(sacc[ig][1], ud[ig], kp1);
                }
            }
#pragma unroll
            for (int ig = 0; ig < 4; ig++)
#pragma unroll
                for (int g = 0; g < 2; g++)
                    *(ull*)&S[(ii + ig) * 512 + jt * 128 + g * 64 + d0] = sacc[ig][g];
        }
        __syncthreads();
    }
}

extern "C" void kernel_launch(void* const* d_in, const int* in_sizes, int n_in,
                              void* d_out, int out_size)
{
    const float* x     = (const float*)d_in[0];
    const float* Wq    = (const float*)d_in[1];
    const float* bq    = (const float*)d_in[2];
    const float* Wk    = (const float*)d_in[3];
    const float* bk    = (const float*)d_in[4];
    const float* Wv    = (const float*)d_in[5];
    const float* bv    = (const float*)d_in[6];
    const float* Wbeta = (const float*)d_in[7];
    const float* bbeta = (const float*)d_in[8];
    const float* Wo    = (const float*)d_in[9];
    const float* bo    = (const float*)d_in[10];
    float* out = (float*)d_out;

    float *pQ, *pK, *pV, *pO, *pBeta, *pA, *pG;
    cudaGetSymbolAddress((void**)&pQ, g_Q);
    cudaGetSymbolAddress((void**)&pK, g_K);
    cudaGetSymbolAddress((void**)&pV, g_V);
    cudaGetSymbolAddress((void**)&pO, g_O);
    cudaGetSymbolAddress((void**)&pBeta, g_Beta);
    cudaGetSymbolAddress((void**)&pA, g_A);
    cudaGetSymbolAddress((void**)&pG, g_G);

    __nv_bfloat16 *pxh, *pxl, *poh, *pol;
    __nv_bfloat16 *pwqh, *pwql, *pwkh, *pwkl, *pwvh, *pwvl, *pwoh, *pwol;
    cudaGetSymbolAddress((void**)&pxh, g_xh);
    cudaGetSymbolAddress((void**)&pxl, g_xl);
    cudaGetSymbolAddress((void**)&poh, g_oh);
    cudaGetSymbolAddress((void**)&pol, g_ol);
    cudaGetSymbolAddress((void**)&pwqh, g_wqh);
    cudaGetSymbolAddress((void**)&pwql, g_wql);
    cudaGetSymbolAddress((void**)&pwkh, g_wkh);
    cudaGetSymbolAddress((void**)&pwkl, g_wkl);
    cudaGetSymbolAddress((void**)&pwvh, g_wvh);
    cudaGetSymbolAddress((void**)&pwvl, g_wvl);
    cudaGetSymbolAddress((void**)&pwoh, g_woh);
    cudaGetSymbolAddress((void**)&pwol, g_wol);

    cudaFuncSetAttribute(scan_kernel,
                         cudaFuncAttributeMaxDynamicSharedMemorySize, SMEM_BYTES);

    const int nx4 = BT * Dd / 4;        // 2097152
    const int nw4 = Dd * Dd / 4;        // 65536
    split_kernel<<<(nx4 + 255) / 256, 256>>>(x, pxh, pxl, nx4);
    split_kernel<<<(nw4 + 255) / 256, 256>>>(Wq, pwqh, pwql, nw4);
    split_kernel<<<(nw4 + 255) / 256, 256>>>(Wk, pwkh, pwkl, nw4);
    split_kernel<<<(nw4 + 255) / 256, 256>>>(Wv, pwvh, pwvl, nw4);
    split_kernel<<<(nw4 + 255) / 256, 256>>>(Wo, pwoh, pwol, nw4);

    dim3 tgrid(Dd / 128, BT / 128);   // (4, 128)
    tgemm_mma_kernel<<<tgrid, 256>>>(pxh, pxl, pwqh, pwql, bq, pQ);
    tgemm_mma_kernel<<<tgrid, 256>>>(pxh, pxl, pwkh, pwkl, bk, pK);
    tgemm_mma_kernel<<<tgrid, 256>>>(pxh, pxl, pwvh, pwvl, bv, pV);

    norm_beta_kernel<<<BT, 128>>>(pK, Wbeta, bbeta, pBeta);

    chunk_ag_kernel<<<dim3(NCH, Bb), 256>>>(pQ, pK, pBeta, pA, pG);

    scan_kernel<<<dim3(NVT, Bb), 256, SMEM_BYTES>>>(pQ, pK, pV, pBeta, pA, pG, pO);

    split_kernel<<<(nx4 + 255) / 256, 256>>>(pO, poh, pol, nx4);
    tgemm_mma_kernel<<<tgrid, 256>>>(poh, pol, pwoh, pwol, bo, out);
}

// round 8
// speedup vs baseline: 2.6907x; 1.2560x over previous
#include <cuda_runtime.h>
#include <cuda_bf16.h>
#include <math.h>
#include <stdint.h>

namespace {
constexpr int Bb  = 8;
constexpr int Tt  = 2048;
constexpr int Dd  = 512;
constexpr int BT  = Bb * Tt;
constexpr int CH  = 64;
constexpr int NCH = Tt / CH;   // 32
constexpr int DV  = 32;
constexpr int NVT = Dd / DV;   // 16

// ---- scan smem layout (byte offsets) ----
constexpr int OFF_S    = 0;              // float [32][520]      66560
constexpr int OFF_AS   = 66560;          // float [64][66]       16896
constexpr int OFF_GS   = 83456;          // float [64][66]       16896
constexpr int OFF_UM   = 100352;         // float [64][34]        8704
constexpr int OFF_QS   = 109056;         // float [64][34]        8704
constexpr int OFF_VB   = 117760;         // float [64][34]        8704
constexpr int OFF_BETA = 126464;         // float [64]             256
constexpr int OFF_KH   = 126720;         // bf16 [64][136]       17408
constexpr int OFF_KL   = 144128;
constexpr int OFF_QH   = 161536;
constexpr int OFF_QL   = 178944;
constexpr int OFF_SH   = 196352;         // bf16 [32][136]        8704
constexpr int OFF_SL   = 205056;
constexpr int OFF_UH   = 213760;         // bf16 [32][72]         4608
constexpr int OFF_UL   = 218368;
constexpr int SCAN_SMEM = 222976;
}

using ull = unsigned long long;
__device__ __forceinline__ ull pk(float x, float y) {
    ull r; asm("mov.b64 %0,{%1,%2};" : "=l"(r) : "f"(x), "f"(y)); return r;
}
__device__ __forceinline__ float2 upk(ull v) {
    float2 r; asm("mov.b64 {%0,%1},%2;" : "=f"(r.x), "=f"(r.y) : "l"(v)); return r;
}
__device__ __forceinline__ void fma2(ull& d, ull a, ull b) {
    asm("fma.rn.f32x2 %0,%1,%2,%0;" : "+l"(d) : "l"(a), "l"(b));
}
__device__ __forceinline__ float hadd(ull v) { float2 f = upk(v); return f.x + f.y; }

// ---------------- device scratch ----------------
__device__ float g_Q[BT * Dd];
__device__ float g_K[BT * Dd];
__device__ float g_V[BT * Dd];
__device__ float g_O[BT * Dd];
__device__ float g_Beta[BT];
__device__ float g_A[Bb * NCH * CH * CH];
__device__ float g_G[Bb * NCH * CH * CH];
__device__ __nv_bfloat16 g_xh[BT * Dd];
__device__ __nv_bfloat16 g_xl[BT * Dd];
__device__ __nv_bfloat16 g_oh[BT * Dd];
__device__ __nv_bfloat16 g_ol[BT * Dd];
__device__ __nv_bfloat16 g_kh[BT * Dd];
__device__ __nv_bfloat16 g_kl[BT * Dd];
__device__ __nv_bfloat16 g_qh[BT * Dd];
__device__ __nv_bfloat16 g_ql[BT * Dd];
__device__ __nv_bfloat16 g_wqh[Dd * Dd];
__device__ __nv_bfloat16 g_wql[Dd * Dd];
__device__ __nv_bfloat16 g_wkh[Dd * Dd];
__device__ __nv_bfloat16 g_wkl[Dd * Dd];
__device__ __nv_bfloat16 g_wvh[Dd * Dd];
__device__ __nv_bfloat16 g_wvl[Dd * Dd];
__device__ __nv_bfloat16 g_woh[Dd * Dd];
__device__ __nv_bfloat16 g_wol[Dd * Dd];

__device__ __forceinline__ uint32_t smem_u32(const void* p) {
    uint32_t a;
    asm("{ .reg .u64 t; cvta.to.shared.u64 t,%1; cvt.u32.u64 %0,t; }" : "=r"(a) : "l"(p));
    return a;
}
__device__ __forceinline__ void ldsm_x4(uint32_t* r, uint32_t addr) {
    asm volatile("ldmatrix.sync.aligned.m8n8.x4.shared.b16 {%0,%1,%2,%3}, [%4];"
                 : "=r"(r[0]), "=r"(r[1]), "=r"(r[2]), "=r"(r[3]) : "r"(addr));
}
__device__ __forceinline__ void ldsm_x4t(uint32_t* r, uint32_t addr) {
    asm volatile("ldmatrix.sync.aligned.m8n8.x4.trans.shared.b16 {%0,%1,%2,%3}, [%4];"
                 : "=r"(r[0]), "=r"(r[1]), "=r"(r[2]), "=r"(r[3]) : "r"(addr));
}
__device__ __forceinline__ void mma_bf16(float* d, const uint32_t* a,
                                         uint32_t b0, uint32_t b1) {
    asm volatile(
        "mma.sync.aligned.m16n8k16.row.col.f32.bf16.bf16.f32 "
        "{%0,%1,%2,%3}, {%4,%5,%6,%7}, {%8,%9}, {%0,%1,%2,%3};"
        : "+f"(d[0]), "+f"(d[1]), "+f"(d[2]), "+f"(d[3])
        : "r"(a[0]), "r"(a[1]), "r"(a[2]), "r"(a[3]), "r"(b0), "r"(b1));
}
__device__ __forceinline__ void cp16(uint32_t dst, const void* src) {
    asm volatile("cp.async.ca.shared.global [%0], [%1], 16;" :: "r"(dst), "l"(src));
}
__device__ __forceinline__ void split2(float x, unsigned short& h, unsigned short& l) {
    __nv_bfloat16 hh = __float2bfloat16(x);
    __nv_bfloat16 ll = __float2bfloat16(x - __bfloat162float(hh));
    h = __bfloat16_as_ushort(hh); l = __bfloat16_as_ushort(ll);
}
__device__ __forceinline__ void split4(float4 v, ull& h, ull& l) {
    unsigned short h0, h1, h2, h3, l0, l1, l2, l3;
    split2(v.x, h0, l0); split2(v.y, h1, l1);
    split2(v.z, h2, l2); split2(v.w, h3, l3);
    h = (ull)h0 | ((ull)h1 << 16) | ((ull)h2 << 32) | ((ull)h3 << 48);
    l = (ull)l0 | ((ull)l1 << 16) | ((ull)l2 << 32) | ((ull)l3 << 48);
}

// ---------------- split fp32 -> bf16 hi/lo ----------------
__global__ __launch_bounds__(256) void split_kernel(
    const float* __restrict__ x, __nv_bfloat16* __restrict__ h,
    __nv_bfloat16* __restrict__ l, int n4)
{
    int i = blockIdx.x * 256 + threadIdx.x;
    if (i >= n4) return;
    float4 v = ((const float4*)x)[i];
    ull hw, lw; split4(v, hw, lw);
    ((ull*)h)[i] = hw;
    ((ull*)l)[i] = lw;
}

// ---------------- HMMA split-bf16 GEMM, cp.async double-buffered ----------------
__global__ __launch_bounds__(256) void tgemm_mma_kernel(
    const __nv_bfloat16* __restrict__ Ah, const __nv_bfloat16* __restrict__ Al,
    const __nv_bfloat16* __restrict__ Bh, const __nv_bfloat16* __restrict__ Bl,
    const float* __restrict__ bias, float* __restrict__ C)
{
    __shared__ __align__(16) __nv_bfloat16 sA[2][128 * 40];
    __shared__ __align__(16) __nv_bfloat16 sB[2][128 * 40];
    constexpr uint32_t BUFB = 128 * 40 * 2;

    const int tid = threadIdx.x, lane = tid & 31, wid = tid >> 5;
    const int wm = wid & 1, wn = wid >> 1;
    const int bm = blockIdx.y * 128, bn = blockIdx.x * 128;

    float d[4][4][4];
#pragma unroll
    for (int mt = 0; mt < 4; mt++)
#pragma unroll
        for (int nt = 0; nt < 4; nt++)
#pragma unroll
            for (int e = 0; e < 4; e++) d[mt][nt][e] = 0.f;

    const uint32_t aBase = smem_u32(sA[0]), bBase = smem_u32(sB[0]);
    uint32_t a_addr[4], b_addr[2];
    {
        const int ar = lane & 15, akoff = (lane >> 4) * 8;
#pragma unroll
        for (int mt = 0; mt < 4; mt++)
            a_addr[mt] = aBase + ((wm * 64 + mt * 16 + ar) * 40 + akoff) * 2;
        const int nrow = wn * 32 + ((lane >> 4) * 8) + (lane & 7);
        const int khalf = (lane >> 3) & 1;
#pragma unroll
        for (int np = 0; np < 2; np++)
            b_addr[np] = bBase + ((nrow + np * 16) * 40 + khalf * 8) * 2;
    }

    const int srow0 = tid >> 2,         sc0 = tid & 3;
    const int srow1 = (tid + 256) >> 2, sc1 = (tid + 256) & 3;
    const uint32_t sa0 = aBase + srow0 * 80 + sc0 * 16;
    const uint32_t sa1 = aBase + srow1 * 80 + sc1 * 16;
    const uint32_t sb0 = bBase + srow0 * 80 + sc0 * 16;
    const uint32_t sb1 = bBase + srow1 * 80 + sc1 * 16;

    auto issue = [&](int s, int buf) {
        const int p = s >> 4, kt = s & 15;
        const __nv_bfloat16* Ap = (p == 2) ? Al : Ah;
        const __nv_bfloat16* Bp = (p == 1) ? Bl : Bh;
        const uint32_t bo = buf * BUFB;
        cp16(sa0 + bo, Ap + (size_t)(bm + srow0) * Dd + kt * 32 + sc0 * 8);
        cp16(sa1 + bo, Ap + (size_t)(bm + srow1) * Dd + kt * 32 + sc1 * 8);
        cp16(sb0 + bo, Bp + (size_t)(bn + srow0) * Dd + kt * 32 + sc0 * 8);
        cp16(sb1 + bo, Bp + (size_t)(bn + srow1) * Dd + kt * 32 + sc1 * 8);
        asm volatile("cp.async.commit_group;");
    };

    issue(0, 0);
#pragma unroll 1
    for (int s = 0; s < 48; s++) {
        const int buf = s & 1;
        if (s + 1 < 48) {
            issue(s + 1, buf ^ 1);
            asm volatile("cp.async.wait_group 1;");
        } else {
            asm volatile("cp.async.wait_group 0;");
        }
        __syncthreads();
        const uint32_t bo = buf * BUFB;
#pragma unroll
        for (int ks = 0; ks < 2; ks++) {
            uint32_t a[4][4], b[2][4];
#pragma unroll
            for (int mt = 0; mt < 4; mt++) ldsm_x4(a[mt], a_addr[mt] + bo + ks * 32);
#pragma unroll
            for (int np = 0; np < 2; np++) ldsm_x4(b[np], b_addr[np] + bo + ks * 32);
#pragma unroll
            for (int mt = 0; mt < 4; mt++)
#pragma unroll
                for (int nt = 0; nt < 4; nt++)
                    mma_bf16(d[mt][nt], a[mt],
                             b[nt >> 1][(nt & 1) * 2], b[nt >> 1][(nt & 1) * 2 + 1]);
        }
        __syncthreads();
    }

#pragma unroll
    for (int mt = 0; mt < 4; mt++) {
        const int r0 = bm + wm * 64 + mt * 16 + (lane >> 2);
#pragma unroll
        for (int nt = 0; nt < 4; nt++) {
            const int c0 = bn + wn * 32 + nt * 8 + (lane & 3) * 2;
            const float b0 = bias[c0], b1 = bias[c0 + 1];
            float2 o0 = make_float2(d[mt][nt][0] + b0, d[mt][nt][1] + b1);
            float2 o1 = make_float2(d[mt][nt][2] + b0, d[mt][nt][3] + b1);
            *(float2*)&C[(size_t)r0 * Dd + c0] = o0;
            *(float2*)&C[(size_t)(r0 + 8) * Dd + c0] = o1;
        }
    }
}

// ---------------- l2norm + beta ----------------
__global__ __launch_bounds__(128) void norm_beta_kernel(
    float* __restrict__ Kd, const float* __restrict__ wb,
    const float* __restrict__ bb, float* __restrict__ Beta)
{
    const int row = blockIdx.x, tid = threadIdx.x;
    float4 v = ((const float4*)(Kd + (size_t)row * Dd))[tid];
    float ss = v.x * v.x + v.y * v.y + v.z * v.z + v.w * v.w;
#pragma unroll
    for (int o = 16; o; o >>= 1) ss += __shfl_xor_sync(0xffffffffu, ss, o);
    __shared__ float red1[4];
    if ((tid & 31) == 0) red1[tid >> 5] = ss;
    __syncthreads();
    const float inv = 1.0f / fmaxf(sqrtf(red1[0] + red1[1] + red1[2] + red1[3]), 1e-12f);
    float4 w = ((const float4*)wb)[tid];
    float bd = v.x * w.x + v.y * w.y + v.z * w.z + v.w * w.w;
#pragma unroll
    for (int o = 16; o; o >>= 1) bd += __shfl_xor_sync(0xffffffffu, bd, o);
    __shared__ float red2[4];
    if ((tid & 31) == 0) red2[tid >> 5] = bd;
    __syncthreads();
    v.x *= inv; v.y *= inv; v.z *= inv; v.w *= inv;
    ((float4*)(Kd + (size_t)row * Dd))[tid] = v;
    if (tid == 0) {
        const float z = (red2[0] + red2[1] + red2[2] + red2[3]) * inv + bb[0];
        Beta[row] = 1.0f / (1.0f + expf(-z));
    }
}

// ---------------- per-chunk A,G Gram matrices, f32x2 dot ----------------
__global__ __launch_bounds__(256) void chunk_ag_kernel(
    const float* __restrict__ Qd, const float* __restrict__ Kd,
    const float* __restrict__ Beta, float* __restrict__ Ag, float* __restrict__ Gg)
{
    const int c = blockIdx.x, b = blockIdx.y;
    const int r0 = b * Tt + c * CH;
    __shared__ float Ks[64 * 66];
    __shared__ float Qs[64 * 66];
    const int tid = threadIdx.x;
    const int t0 = (tid >> 4) * 4, j0 = (tid & 15) * 4;

    ull accA[4][4], accG[4][4];
#pragma unroll
    for (int i = 0; i < 4; i++)
#pragma unroll
        for (int j = 0; j < 4; j++) { accA[i][j] = 0ull; accG[i][j] = 0ull; }

    for (int dt = 0; dt < 8; dt++) {
        __syncthreads();
#pragma unroll
        for (int n = 0; n < 4; n++) {
            const int f4 = tid + n * 256;
            const int row = f4 >> 4, col = (f4 & 15) * 4;
            float4 kv = *(const float4*)&Kd[(size_t)(r0 + row) * Dd + dt * 64 + col];
            float4 qv = *(const float4*)&Qd[(size_t)(r0 + row) * Dd + dt * 64 + col];
            const int so = row * 66 + col;
            Ks[so] = kv.x; Ks[so + 1] = kv.y; Ks[so + 2] = kv.z; Ks[so + 3] = kv.w;
            Qs[so] = qv.x; Qs[so + 1] = qv.y; Qs[so + 2] = qv.z; Qs[so + 3] = qv.w;
        }
        __syncthreads();
#pragma unroll 2
        for (int dd = 0; dd < 64; dd += 2) {
            ull kt[4], kj[4], qt[4];
#pragma unroll
            for (int i = 0; i < 4; i++) {
                kt[i] = *(const ull*)&Ks[(t0 + i) * 66 + dd];
                qt[i] = *(const ull*)&Qs[(t0 + i) * 66 + dd];
                kj[i] = *(const ull*)&Ks[(j0 + i) * 66 + dd];
            }
#pragma unroll
            for (int i = 0; i < 4; i++)
#pragma unroll
                for (int j = 0; j < 4; j++) {
                    fma2(accA[i][j], kt[i], kj[j]);
                    fma2(accG[i][j], qt[i], kj[j]);
                }
        }
    }
    const size_t base = ((size_t)(b * NCH) + c) * (CH * CH);
#pragma unroll
    for (int i = 0; i < 4; i++) {
        const int t = t0 + i;
        const float bt = Beta[r0 + t];
#pragma unroll
        for (int j = 0; j < 4; j++) {
            const int jj = j0 + j;
            Ag[base + t * CH + jj] = (jj < t) ? bt * hadd(accA[i][j]) : 0.f;
            Gg[base + t * CH + jj] = (jj <= t) ? hadd(accG[i][j]) : 0.f;
        }
    }
}

// ---------------- chunked delta-rule scan: mma phases A & D ----------------
__global__ __launch_bounds__(256) void scan_kernel(
    const __nv_bfloat16* __restrict__ KhG, const __nv_bfloat16* __restrict__ KlG,
    const __nv_bfloat16* __restrict__ QhG, const __nv_bfloat16* __restrict__ QlG,
    const float* __restrict__ Vd, const float* __restrict__ Betad,
    const float* __restrict__ Ag, const float* __restrict__ Gg,
    float* __restrict__ Od)
{
    extern __shared__ char sraw[];
    float* S     = (float*)(sraw + OFF_S);     // [32][520]
    float* As    = (float*)(sraw + OFF_AS);    // [64][66]
    float* Gs    = (float*)(sraw + OFF_GS);    // [64][66]
    float* Um    = (float*)(sraw + OFF_UM);    // [64][34]
    float* QSm   = (float*)(sraw + OFF_QS);    // [64][34]
    float* Vb    = (float*)(sraw + OFF_VB);    // [64][34]
    float* betas = (float*)(sraw + OFF_BETA);  // [64]
    char* pKh = sraw + OFF_KH;  char* pKl = sraw + OFF_KL;
    char* pQh = sraw + OFF_QH;  char* pQl = sraw + OFF_QL;
    char* pSh = sraw + OFF_SH;  char* pSl = sraw + OFF_SL;
    char* pUh = sraw + OFF_UH;  char* pUl = sraw + OFF_UL;
    const uint32_t khB = smem_u32(pKh), klB = smem_u32(pKl);
    const uint32_t qhB = smem_u32(pQh), qlB = smem_u32(pQl);
    const uint32_t shB = smem_u32(pSh), slB = smem_u32(pSl);
    const uint32_t uhB = smem_u32(pUh), ulB = smem_u32(pUl);

    const int b = blockIdx.y;
    const int i0 = blockIdx.x * DV;
    const int tid = threadIdx.x;
    const int lane = tid & 31, wid = tid >> 5;
    const int fr = lane >> 2, fc = 2 * (lane & 3);

    for (int e = tid; e < 32 * 520; e += 256) S[e] = 0.f;
    __syncthreads();

    for (int c = 0; c < NCH; c++) {
        const int r0g = b * Tt + c * CH;
        const size_t agbase = ((size_t)(b * NCH) + c) * (CH * CH);

        // ---- stage A, G, V slice, beta ----
        for (int e = tid; e < CH * CH; e += 256) {
            const int t = e >> 6, j = e & 63;
            As[t * 66 + j] = Ag[agbase + e];
            Gs[t * 66 + j] = Gg[agbase + e];
        }
        for (int e = tid; e < CH * DV; e += 256) {
            const int t = e >> 5, i = e & 31;
            Vb[t * 34 + i] = Vd[(size_t)(r0g + t) * Dd + i0 + i];
        }
        if (tid < 64) betas[tid] = Betad[r0g + tid];
        __syncthreads();

        // ---- Phase A: KS = K@S^T, QS = Q@S^T via mma ----
        const int mat = wid >> 2;   // 0: K warps, 1: Q warps
        const int mb  = wid & 3;    // t-block (16 rows)
        float cacc[4][4];
#pragma unroll
        for (int nb = 0; nb < 4; nb++)
#pragma unroll
            for (int e = 0; e < 4; e++) cacc[nb][e] = 0.f;

#pragma unroll 1
        for (int jt = 0; jt < 4; jt++) {
            // stage K/Q hi/lo tiles [64][128] (swizzled, stride 136 halves)
#pragma unroll
            for (int n = 0; n < 8; n++) {
                const int e = tid + n * 256;
                const int t = e >> 5, d4 = (e & 31) * 4;
                const uint32_t off = (uint32_t)t * 272u
                    + ((uint32_t)((d4 >> 3) ^ ((t >> 3) & 1)) << 4) + (d4 & 7) * 2;
                const size_t g = (size_t)(r0g + t) * Dd + jt * 128 + d4;
                *(ull*)(pKh + off) = *(const ull*)&KhG[g];
                *(ull*)(pKl + off) = *(const ull*)&KlG[g];
                *(ull*)(pQh + off) = *(const ull*)&QhG[g];
                *(ull*)(pQl + off) = *(const ull*)&QlG[g];
            }
            // convert S tile [32][128] fp32 -> bf16 hi/lo
#pragma unroll
            for (int n = 0; n < 4; n++) {
                const int e = tid + n * 256;
                const int i = e >> 5, d4 = (e & 31) * 4;
                float4 v = *(const float4*)&S[i * 520 + jt * 128 + d4];
                ull hw, lw; split4(v, hw, lw);
                const uint32_t off = (uint32_t)i * 272u
                    + ((uint32_t)((d4 >> 3) ^ ((i >> 3) & 1)) << 4) + (d4 & 7) * 2;
                *(ull*)(pSh + off) = hw;
                *(ull*)(pSl + off) = lw;
            }
            __syncthreads();
#pragma unroll
            for (int p = 0; p < 3; p++) {
                const uint32_t aT = mat ? (p < 2 ? qhB : qlB) : (p < 2 ? khB : klB);
                const uint32_t bT = (p == 1) ? slB : shB;
#pragma unroll
                for (int k = 0; k < 8; k++) {
                    uint32_t a[4], b0[4], b1[4];
                    {
                        const int r = mb * 16 + (lane & 15);
                        const int cc = k * 2 + (lane >> 4);
                        ldsm_x4(a, aT + r * 272u + ((uint32_t)(cc ^ ((r >> 3) & 1)) << 4));
                    }
                    {
                        const int r = (lane & 7) + ((lane >> 4) << 3);
                        const int cc = k * 2 + ((lane >> 3) & 1);
                        ldsm_x4(b0, bT + r * 272u + ((uint32_t)(cc ^ ((r >> 3) & 1)) << 4));
                        const int r2 = r + 16;
                        ldsm_x4(b1, bT + r2 * 272u + ((uint32_t)(cc ^ ((r2 >> 3) & 1)) << 4));
                    }
                    mma_bf16(cacc[0], a, b0[0], b0[1]);
                    mma_bf16(cacc[1], a, b0[2], b0[3]);
                    mma_bf16(cacc[2], a, b1[0], b1[1]);
                    mma_bf16(cacc[3], a, b1[2], b1[3]);
                }
            }
            __syncthreads();
        }

        // write rhs: warps 0-3 -> Um = beta*(V - KS); warps 4-7 -> QSm
        {
            const int t0r = mb * 16 + fr, t1r = t0r + 8;
            if (mat == 0) {
                const float b0v = betas[t0r], b1v = betas[t1r];
#pragma unroll
                for (int nb = 0; nb < 4; nb++) {
                    const int i = nb * 8 + fc;
                    float2 v0 = *(float2*)&Vb[t0r * 34 + i];
                    float2 v1 = *(float2*)&Vb[t1r * 34 + i];
                    float2 u0 = make_float2(b0v * (v0.x - cacc[nb][0]),
                                            b0v * (v0.y - cacc[nb][1]));
                    float2 u1 = make_float2(b1v * (v1.x - cacc[nb][2]),
                                            b1v * (v1.y - cacc[nb][3]));
                    *(float2*)&Um[t0r * 34 + i] = u0;
                    *(float2*)&Um[t1r * 34 + i] = u1;
                }
            } else {
#pragma unroll
                for (int nb = 0; nb < 4; nb++) {
                    const int i = nb * 8 + fc;
                    *(float2*)&QSm[t0r * 34 + i] = make_float2(cacc[nb][0], cacc[nb][1]);
                    *(float2*)&QSm[t1r * 34 + i] = make_float2(cacc[nb][2], cacc[nb][3]);
                }
            }
        }
        __syncthreads();

        // ---- Phase B: blocked forward substitution (fp32) ----
#pragma unroll
        for (int blk = 0; blk < 4; blk++) {
            const int bt0 = blk * 16;
            if (wid == 0) {
                for (int t = bt0; t < bt0 + 16; t++) {
                    float s = Um[t * 34 + lane];
                    for (int j = bt0; j < t; j++)
                        s -= As[t * 66 + j] * Um[j * 34 + lane];
                    Um[t * 34 + lane] = s;
                }
            }
            __syncthreads();
            if (blk < 3) {
                const int rem = 64 - (blk + 1) * 16;
                for (int e = tid; e < rem * 32; e += 256) {
                    const int t = (blk + 1) * 16 + (e >> 5);
                    const int i = e & 31;
                    float s = Um[t * 34 + i];
#pragma unroll
                    for (int j = 0; j < 16; j++)
                        s -= As[t * 66 + bt0 + j] * Um[(bt0 + j) * 34 + i];
                    Um[t * 34 + i] = s;
                }
                __syncthreads();
            }
        }

        // ---- Phase C: O = QS + tril(G)@U (fp32, pair along i) ----
        for (int e = tid; e < CH * 16; e += 256) {
            const int t = e >> 4, ip = (e & 15) * 2;
            ull s2 = *(const ull*)&QSm[t * 34 + ip];
            for (int j = 0; j <= t; j++) {
                ull g2 = pk(Gs[t * 66 + j], Gs[t * 66 + j]);
                fma2(s2, g2, *(const ull*)&Um[j * 34 + ip]);
            }
            *(float2*)&Od[(size_t)(r0g + t) * Dd + i0 + ip] = upk(s2);
        }

        // ---- U -> bf16 hi/lo transposed [i][t] (stride 72, swizzled) ----
        for (int e = tid; e < 2048; e += 256) {
            const int t = e >> 5, i = e & 31;
            const float u = Um[t * 34 + i];
            unsigned short uh, ul; split2(u, uh, ul);
            const uint32_t off = (uint32_t)i * 144u
                + ((uint32_t)((t >> 3) ^ ((i >> 3) & 1)) << 4) + (t & 7) * 2;
            *(unsigned short*)(pUh + off) = uh;
            *(unsigned short*)(pUl + off) = ul;
        }
        __syncthreads();

        // ---- Phase D: S += U^T @ K via mma ----
#pragma unroll 1
        for (int jt = 0; jt < 4; jt++) {
            // stage K hi/lo tile [64][128]
#pragma unroll
            for (int n = 0; n < 8; n++) {
                const int e = tid + n * 256;
                const int t = e >> 5, d4 = (e & 31) * 4;
                const uint32_t off = (uint32_t)t * 272u
                    + ((uint32_t)((d4 >> 3) ^ ((t >> 3) & 1)) << 4) + (d4 & 7) * 2;
                const size_t g = (size_t)(r0g + t) * Dd + jt * 128 + d4;
                *(ull*)(pKh + off) = *(const ull*)&KhG[g];
                *(ull*)(pKl + off) = *(const ull*)&KlG[g];
            }
            __syncthreads();

            float cf[2][2][4];
            const int dbase = jt * 128 + wid * 16;
#pragma unroll
            for (int mi = 0; mi < 2; mi++)
#pragma unroll
                for (int n8 = 0; n8 < 2; n8++) {
                    const int i0r = mi * 16 + fr;
                    const int col = dbase + n8 * 8 + fc;
                    float2 x0 = *(float2*)&S[i0r * 520 + col];
                    float2 x1 = *(float2*)&S[(i0r + 8) * 520 + col];
                    cf[mi][n8][0] = x0.x; cf[mi][n8][1] = x0.y;
                    cf[mi][n8][2] = x1.x; cf[mi][n8][3] = x1.y;
                }
#pragma unroll
            for (int p = 0; p < 3; p++) {
                const uint32_t aT = (p < 2) ? uhB : ulB;
                const uint32_t bT = (p == 1) ? klB : khB;
#pragma unroll
                for (int k = 0; k < 4; k++) {
                    uint32_t a0[4], a1[4], bb[4];
                    {
                        const int r = lane & 15;
                        const int cc = k * 2 + (lane >> 4);
                        ldsm_x4(a0, aT + r * 144u + ((uint32_t)(cc ^ ((r >> 3) & 1)) << 4));
                        const int r2 = 16 + (lane & 15);
                        ldsm_x4(a1, aT + r2 * 144u + ((uint32_t)(cc ^ ((r2 >> 3) & 1)) << 4));
                    }
                    {
                        const int tr = k * 16 + (lane & 15);
                        const int cc = wid * 2 + (lane >> 4);
                        ldsm_x4t(bb, bT + tr * 272u + ((uint32_t)(cc ^ ((tr >> 3) & 1)) << 4));
                    }
                    mma_bf16(cf[0][0], a0, bb[0], bb[1]);
                    mma_bf16(cf[0][1], a0, bb[2], bb[3]);
                    mma_bf16(cf[1][0], a1, bb[0], bb[1]);
                    mma_bf16(cf[1][1], a1, bb[2], bb[3]);
                }
            }
#pragma unroll
            for (int mi = 0; mi < 2; mi++)
#pragma unroll
                for (int n8 = 0; n8 < 2; n8++) {
                    const int i0r = mi * 16 + fr;
                    const int col = dbase + n8 * 8 + fc;
                    *(float2*)&S[i0r * 520 + col] =
                        make_float2(cf[mi][n8][0], cf[mi][n8][1]);
                    *(float2*)&S[(i0r + 8) * 520 + col] =
                        make_float2(cf[mi][n8][2], cf[mi][n8][3]);
                }
            __syncthreads();
        }
    }
}

extern "C" void kernel_launch(void* const* d_in, const int* in_sizes, int n_in,
                              void* d_out, int out_size)
{
    const float* x     = (const float*)d_in[0];
    const float* Wq    = (const float*)d_in[1];
    const float* bq    = (const float*)d_in[2];
    const float* Wk    = (const float*)d_in[3];
    const float* bk    = (const float*)d_in[4];
    const float* Wv    = (const float*)d_in[5];
    const float* bv    = (const float*)d_in[6];
    const float* Wbeta = (const float*)d_in[7];
    const float* bbeta = (const float*)d_in[8];
    const float* Wo    = (const float*)d_in[9];
    const float* bo    = (const float*)d_in[10];
    float* out = (float*)d_out;

    float *pQ, *pK, *pV, *pO, *pBeta, *pA, *pG;
    cudaGetSymbolAddress((void**)&pQ, g_Q);
    cudaGetSymbolAddress((void**)&pK, g_K);
    cudaGetSymbolAddress((void**)&pV, g_V);
    cudaGetSymbolAddress((void**)&pO, g_O);
    cudaGetSymbolAddress((void**)&pBeta, g_Beta);
    cudaGetSymbolAddress((void**)&pA, g_A);
    cudaGetSymbolAddress((void**)&pG, g_G);

    __nv_bfloat16 *pxh, *pxl, *poh, *pol, *pkh, *pkl, *pqh, *pql;
    __nv_bfloat16 *pwqh, *pwql, *pwkh, *pwkl, *pwvh, *pwvl, *pwoh, *pwol;
    cudaGetSymbolAddress((void**)&pxh, g_xh);
    cudaGetSymbolAddress((void**)&pxl, g_xl);
    cudaGetSymbolAddress((void**)&poh, g_oh);
    cudaGetSymbolAddress((void**)&pol, g_ol);
    cudaGetSymbolAddress((void**)&pkh, g_kh);
    cudaGetSymbolAddress((void**)&pkl, g_kl);
    cudaGetSymbolAddress((void**)&pqh, g_qh);
    cudaGetSymbolAddress((void**)&pql, g_ql);
    cudaGetSymbolAddress((void**)&pwqh, g_wqh);
    cudaGetSymbolAddress((void**)&pwql, g_wql);
    cudaGetSymbolAddress((void**)&pwkh, g_wkh);
    cudaGetSymbolAddress((void**)&pwkl, g_wkl);
    cudaGetSymbolAddress((void**)&pwvh, g_wvh);
    cudaGetSymbolAddress((void**)&pwvl, g_wvl);
    cudaGetSymbolAddress((void**)&pwoh, g_woh);
    cudaGetSymbolAddress((void**)&pwol, g_wol);

    cudaFuncSetAttribute(scan_kernel,
                         cudaFuncAttributeMaxDynamicSharedMemorySize, SCAN_SMEM);

    const int nx4 = BT * Dd / 4;
    const int nw4 = Dd * Dd / 4;
    split_kernel<<<(nx4 + 255) / 256, 256>>>(x, pxh, pxl, nx4);
    split_kernel<<<(nw4 + 255) / 256, 256>>>(Wq, pwqh, pwql, nw4);
    split_kernel<<<(nw4 + 255) / 256, 256>>>(Wk, pwkh, pwkl, nw4);
    split_kernel<<<(nw4 + 255) / 256, 256>>>(Wv, pwvh, pwvl, nw4);
    split_kernel<<<(nw4 + 255) / 256, 256>>>(Wo, pwoh, pwol, nw4);

    dim3 tgrid(Dd / 128, BT / 128);
    tgemm_mma_kernel<<<tgrid, 256>>>(pxh, pxl, pwqh, pwql, bq, pQ);
    tgemm_mma_kernel<<<tgrid, 256>>>(pxh, pxl, pwkh, pwkl, bk, pK);
    tgemm_mma_kernel<<<tgrid, 256>>>(pxh, pxl, pwvh, pwvl, bv, pV);

    norm_beta_kernel<<<BT, 128>>>(pK, Wbeta, bbeta, pBeta);

    // split normalized K and Q to global bf16 hi/lo for the scan
    split_kernel<<<(nx4 + 255) / 256, 256>>>(pK, pkh, pkl, nx4);
    split_kernel<<<(nx4 + 255) / 256, 256>>>(pQ, pqh, pql, nx4);

    chunk_ag_kernel<<<dim3(NCH, Bb), 256>>>(pQ, pK, pBeta, pA, pG);

    scan_kernel<<<dim3(NVT, Bb), 256, SCAN_SMEM>>>(
        pkh, pkl, pqh, pql, pV, pBeta, pA, pG, pO);

    split_kernel<<<(nx4 + 255) / 256, 256>>>(pO, poh, pol, nx4);
    tgemm_mma_kernel<<<tgrid, 256>>>(poh, pol, pwoh, pwol, bo, out);
}

// round 9
// speedup vs baseline: 2.8147x; 1.0461x over previous
#include <cuda_runtime.h>
#include <cuda_bf16.h>
#include <math.h>
#include <stdint.h>

namespace {
constexpr int Bb  = 8;
constexpr int Tt  = 2048;
constexpr int Dd  = 512;
constexpr int BT  = Bb * Tt;
constexpr int CH  = 64;
constexpr int NCH = Tt / CH;   // 32
constexpr int DV  = 32;
constexpr int NVT = Dd / DV;   // 16

// ---- scan smem layout (byte offsets) ----
constexpr int OFF_S    = 0;              // float [32][520]
constexpr int OFF_AS   = 66560;          // float [64][66]
constexpr int OFF_GS   = 83456;          // float [64][66]
constexpr int OFF_UM   = 100352;         // float [64][34]
constexpr int OFF_QS   = 109056;         // float [64][34]
constexpr int OFF_VB   = 117760;         // float [64][34]
constexpr int OFF_BETA = 126464;         // float [64]
constexpr int OFF_KH   = 126720;         // bf16 [64][136]
constexpr int OFF_KL   = 144128;
constexpr int OFF_QH   = 161536;
constexpr int OFF_QL   = 178944;
constexpr int OFF_SH   = 196352;         // bf16 [32][136]
constexpr int OFF_SL   = 205056;
constexpr int OFF_UH   = 213760;         // bf16 [32][72]
constexpr int OFF_UL   = 218368;
constexpr int SCAN_SMEM = 222976;

// tgemm: 3 slots x (Ah|Al|Bh|Bl) each 128x40 halves = 10240 B
constexpr int TG_TILE  = 10240;
constexpr int TG_SLOT  = 4 * TG_TILE;          // 40960
constexpr int TG_SMEM  = 3 * TG_SLOT;          // 122880

// chunk_ag smem: Kh,Kl,Qh,Ql each [64][136] bf16 = 17408 B
constexpr int AG_TILE  = 17408;
constexpr int AG_SMEM  = 4 * AG_TILE;          // 69632
}

using ull = unsigned long long;
__device__ __forceinline__ ull pk(float x, float y) {
    ull r; asm("mov.b64 %0,{%1,%2};" : "=l"(r) : "f"(x), "f"(y)); return r;
}
__device__ __forceinline__ float2 upk(ull v) {
    float2 r; asm("mov.b64 {%0,%1},%2;" : "=f"(r.x), "=f"(r.y) : "l"(v)); return r;
}
__device__ __forceinline__ void fma2(ull& d, ull a, ull b) {
    asm("fma.rn.f32x2 %0,%1,%2,%0;" : "+l"(d) : "l"(a), "l"(b));
}

// ---------------- device scratch ----------------
__device__ float g_Q[BT * Dd];
__device__ float g_K[BT * Dd];
__device__ float g_V[BT * Dd];
__device__ float g_O[BT * Dd];
__device__ float g_Beta[BT];
__device__ float g_A[Bb * NCH * CH * CH];
__device__ float g_G[Bb * NCH * CH * CH];
__device__ __nv_bfloat16 g_xh[BT * Dd];
__device__ __nv_bfloat16 g_xl[BT * Dd];
__device__ __nv_bfloat16 g_oh[BT * Dd];
__device__ __nv_bfloat16 g_ol[BT * Dd];
__device__ __nv_bfloat16 g_kh[BT * Dd];
__device__ __nv_bfloat16 g_kl[BT * Dd];
__device__ __nv_bfloat16 g_qh[BT * Dd];
__device__ __nv_bfloat16 g_ql[BT * Dd];
__device__ __nv_bfloat16 g_wqh[Dd * Dd];
__device__ __nv_bfloat16 g_wql[Dd * Dd];
__device__ __nv_bfloat16 g_wkh[Dd * Dd];
__device__ __nv_bfloat16 g_wkl[Dd * Dd];
__device__ __nv_bfloat16 g_wvh[Dd * Dd];
__device__ __nv_bfloat16 g_wvl[Dd * Dd];
__device__ __nv_bfloat16 g_woh[Dd * Dd];
__device__ __nv_bfloat16 g_wol[Dd * Dd];

__device__ __forceinline__ uint32_t smem_u32(const void* p) {
    uint32_t a;
    asm("{ .reg .u64 t; cvta.to.shared.u64 t,%1; cvt.u32.u64 %0,t; }" : "=r"(a) : "l"(p));
    return a;
}
__device__ __forceinline__ void ldsm_x4(uint32_t* r, uint32_t addr) {
    asm volatile("ldmatrix.sync.aligned.m8n8.x4.shared.b16 {%0,%1,%2,%3}, [%4];"
                 : "=r"(r[0]), "=r"(r[1]), "=r"(r[2]), "=r"(r[3]) : "r"(addr));
}
__device__ __forceinline__ void ldsm_x4t(uint32_t* r, uint32_t addr) {
    asm volatile("ldmatrix.sync.aligned.m8n8.x4.trans.shared.b16 {%0,%1,%2,%3}, [%4];"
                 : "=r"(r[0]), "=r"(r[1]), "=r"(r[2]), "=r"(r[3]) : "r"(addr));
}
__device__ __forceinline__ void mma_bf16(float* d, const uint32_t* a,
                                         uint32_t b0, uint32_t b1) {
    asm volatile(
        "mma.sync.aligned.m16n8k16.row.col.f32.bf16.bf16.f32 "
        "{%0,%1,%2,%3}, {%4,%5,%6,%7}, {%8,%9}, {%0,%1,%2,%3};"
        : "+f"(d[0]), "+f"(d[1]), "+f"(d[2]), "+f"(d[3])
        : "r"(a[0]), "r"(a[1]), "r"(a[2]), "r"(a[3]), "r"(b0), "r"(b1));
}
__device__ __forceinline__ void cp16(uint32_t dst, const void* src) {
    asm volatile("cp.async.ca.shared.global [%0], [%1], 16;" :: "r"(dst), "l"(src));
}
__device__ __forceinline__ void split2(float x, unsigned short& h, unsigned short& l) {
    __nv_bfloat16 hh = __float2bfloat16(x);
    __nv_bfloat16 ll = __float2bfloat16(x - __bfloat162float(hh));
    h = __bfloat16_as_ushort(hh); l = __bfloat16_as_ushort(ll);
}
__device__ __forceinline__ void split4(float4 v, ull& h, ull& l) {
    unsigned short h0, h1, h2, h3, l0, l1, l2, l3;
    split2(v.x, h0, l0); split2(v.y, h1, l1);
    split2(v.z, h2, l2); split2(v.w, h3, l3);
    h = (ull)h0 | ((ull)h1 << 16) | ((ull)h2 << 32) | ((ull)h3 << 48);
    l = (ull)l0 | ((ull)l1 << 16) | ((ull)l2 << 32) | ((ull)l3 << 48);
}

// ---------------- split fp32 -> bf16 hi/lo ----------------
__global__ __launch_bounds__(256) void split_kernel(
    const float* __restrict__ x, __nv_bfloat16* __restrict__ h,
    __nv_bfloat16* __restrict__ l, int n4)
{
    int i = blockIdx.x * 256 + threadIdx.x;
    if (i >= n4) return;
    float4 v = ((const float4*)x)[i];
    ull hw, lw; split4(v, hw, lw);
    ((ull*)h)[i] = hw;
    ((ull*)l)[i] = lw;
}

// ---------------- HMMA split-bf16 GEMM, 3-slot cp.async pipeline ----------------
// Per K-tile stage: load Ah|Al|Bh|Bl once, run 3 passes (hh, hl, lh) resident.
__global__ __launch_bounds__(256) void tgemm_mma_kernel(
    const __nv_bfloat16* __restrict__ Ah, const __nv_bfloat16* __restrict__ Al,
    const __nv_bfloat16* __restrict__ Bh, const __nv_bfloat16* __restrict__ Bl,
    const float* __restrict__ bias, float* __restrict__ C)
{
    extern __shared__ char tgs[];
    const uint32_t sBase = smem_u32(tgs);

    const int tid = threadIdx.x, lane = tid & 31, wid = tid >> 5;
    const int wm = wid & 1, wn = wid >> 1;
    const int bm = blockIdx.y * 128, bn = blockIdx.x * 128;

    float d[4][4][4];
#pragma unroll
    for (int mt = 0; mt < 4; mt++)
#pragma unroll
        for (int nt = 0; nt < 4; nt++)
#pragma unroll
            for (int e = 0; e < 4; e++) d[mt][nt][e] = 0.f;

    // relative frag offsets (row stride 40 halves = 80 B)
    uint32_t a_rel[4], b_rel[2];
    {
        const int ar = lane & 15, akoff = (lane >> 4) * 8;
#pragma unroll
        for (int mt = 0; mt < 4; mt++)
            a_rel[mt] = ((wm * 64 + mt * 16 + ar) * 40 + akoff) * 2;
        const int nrow = wn * 32 + ((lane >> 4) << 3) + (lane & 7);
        const int khalf = (lane >> 3) & 1;
#pragma unroll
        for (int np = 0; np < 2; np++)
            b_rel[np] = ((nrow + np * 16) * 40 + khalf * 8) * 2;
    }

    // staging coords: 2 x 16B chunks per tensor per thread
    const int srow0 = tid >> 2,         sc0 = tid & 3;
    const int srow1 = (tid + 256) >> 2, sc1 = (tid + 256) & 3;
    const uint32_t st0 = srow0 * 80 + sc0 * 16;
    const uint32_t st1 = srow1 * 80 + sc1 * 16;

    auto issue = [&](int kt, int slot) {
        const uint32_t b0 = sBase + slot * TG_SLOT;
        const size_t ga0 = (size_t)(bm + srow0) * Dd + kt * 32 + sc0 * 8;
        const size_t ga1 = (size_t)(bm + srow1) * Dd + kt * 32 + sc1 * 8;
        const size_t gb0 = (size_t)(bn + srow0) * Dd + kt * 32 + sc0 * 8;
        const size_t gb1 = (size_t)(bn + srow1) * Dd + kt * 32 + sc1 * 8;
        cp16(b0 + st0,               Ah + ga0);
        cp16(b0 + st1,               Ah + ga1);
        cp16(b0 + TG_TILE + st0,     Al + ga0);
        cp16(b0 + TG_TILE + st1,     Al + ga1);
        cp16(b0 + 2 * TG_TILE + st0, Bh + gb0);
        cp16(b0 + 2 * TG_TILE + st1, Bh + gb1);
        cp16(b0 + 3 * TG_TILE + st0, Bl + gb0);
        cp16(b0 + 3 * TG_TILE + st1, Bl + gb1);
        asm volatile("cp.async.commit_group;");
    };

    issue(0, 0);
    issue(1, 1);
#pragma unroll 1
    for (int s = 0; s < 16; s++) {
        asm volatile("cp.async.wait_group 1;");
        __syncthreads();
        if (s + 2 < 16) issue(s + 2, (s + 2) % 3);
        const uint32_t slotB = sBase + (s % 3) * TG_SLOT;
#pragma unroll
        for (int p = 0; p < 3; p++) {
            const uint32_t aO = slotB + (p == 2 ? TG_TILE : 0);
            const uint32_t bO = slotB + 2 * TG_TILE + (p == 1 ? TG_TILE : 0);
#pragma unroll
            for (int ks = 0; ks < 2; ks++) {
                uint32_t a[4][4], b[2][4];
#pragma unroll
                for (int mt = 0; mt < 4; mt++) ldsm_x4(a[mt], aO + a_rel[mt] + ks * 32);
#pragma unroll
                for (int np = 0; np < 2; np++) ldsm_x4(b[np], bO + b_rel[np] + ks * 32);
#pragma unroll
                for (int mt = 0; mt < 4; mt++)
#pragma unroll
                    for (int nt = 0; nt < 4; nt++)
                        mma_bf16(d[mt][nt], a[mt],
                                 b[nt >> 1][(nt & 1) * 2], b[nt >> 1][(nt & 1) * 2 + 1]);
            }
        }
        __syncthreads();
    }

#pragma unroll
    for (int mt = 0; mt < 4; mt++) {
        const int r0 = bm + wm * 64 + mt * 16 + (lane >> 2);
#pragma unroll
        for (int nt = 0; nt < 4; nt++) {
            const int c0 = bn + wn * 32 + nt * 8 + (lane & 3) * 2;
            const float b0 = bias[c0], b1 = bias[c0 + 1];
            float2 o0 = make_float2(d[mt][nt][0] + b0, d[mt][nt][1] + b1);
            float2 o1 = make_float2(d[mt][nt][2] + b0, d[mt][nt][3] + b1);
            *(float2*)&C[(size_t)r0 * Dd + c0] = o0;
            *(float2*)&C[(size_t)(r0 + 8) * Dd + c0] = o1;
        }
    }
}

// ---------------- l2norm + beta ----------------
__global__ __launch_bounds__(128) void norm_beta_kernel(
    float* __restrict__ Kd, const float* __restrict__ wb,
    const float* __restrict__ bb, float* __restrict__ Beta)
{
    const int row = blockIdx.x, tid = threadIdx.x;
    float4 v = ((const float4*)(Kd + (size_t)row * Dd))[tid];
    float ss = v.x * v.x + v.y * v.y + v.z * v.z + v.w * v.w;
#pragma unroll
    for (int o = 16; o; o >>= 1) ss += __shfl_xor_sync(0xffffffffu, ss, o);
    __shared__ float red1[4];
    if ((tid & 31) == 0) red1[tid >> 5] = ss;
    __syncthreads();
    const float inv = 1.0f / fmaxf(sqrtf(red1[0] + red1[1] + red1[2] + red1[3]), 1e-12f);
    float4 w = ((const float4*)wb)[tid];
    float bd = v.x * w.x + v.y * w.y + v.z * w.z + v.w * w.w;
#pragma unroll
    for (int o = 16; o; o >>= 1) bd += __shfl_xor_sync(0xffffffffu, bd, o);
    __shared__ float red2[4];
    if ((tid & 31) == 0) red2[tid >> 5] = bd;
    __syncthreads();
    v.x *= inv; v.y *= inv; v.z *= inv; v.w *= inv;
    ((float4*)(Kd + (size_t)row * Dd))[tid] = v;
    if (tid == 0) {
        const float z = (red2[0] + red2[1] + red2[2] + red2[3]) * inv + bb[0];
        Beta[row] = 1.0f / (1.0f + expf(-z));
    }
}

// ---------------- per-chunk A,G via mma (split-bf16) ----------------
// A[t][j] = beta_t * K_t.K_j (j<t), G[t][j] = Q_t.K_j (j<=t).
// Warps 0-3: A rows; warps 4-7: G rows. 16 t-rows per warp, full 64 j-cols.
__global__ __launch_bounds__(256) void chunk_ag_mma_kernel(
    const __nv_bfloat16* __restrict__ KhG, const __nv_bfloat16* __restrict__ KlG,
    const __nv_bfloat16* __restrict__ QhG, const __nv_bfloat16* __restrict__ QlG,
    const float* __restrict__ Betad, float* __restrict__ Ag, float* __restrict__ Gg)
{
    extern __shared__ char ags[];
    char* pKh = ags;               char* pKl = ags + AG_TILE;
    char* pQh = ags + 2 * AG_TILE; char* pQl = ags + 3 * AG_TILE;
    const uint32_t khB = smem_u32(pKh), klB = smem_u32(pKl);
    const uint32_t qhB = smem_u32(pQh), qlB = smem_u32(pQl);

    const int c = blockIdx.x, b = blockIdx.y;
    const int r0g = b * Tt + c * CH;
    const int tid = threadIdx.x, lane = tid & 31, wid = tid >> 5;
    const int mat = wid >> 2, mb = wid & 3;
    const int fr = lane >> 2, fc = 2 * (lane & 3);

    float cacc[8][4];
#pragma unroll
    for (int nb = 0; nb < 8; nb++)
#pragma unroll
        for (int e = 0; e < 4; e++) cacc[nb][e] = 0.f;

#pragma unroll 1
    for (int jt = 0; jt < 4; jt++) {
        if (jt) __syncthreads();
#pragma unroll
        for (int n = 0; n < 8; n++) {
            const int e = tid + n * 256;
            const int t = e >> 5, d4 = (e & 31) * 4;
            const uint32_t off = (uint32_t)t * 272u
                + ((uint32_t)((d4 >> 3) ^ ((t >> 3) & 1)) << 4) + (d4 & 7) * 2;
            const size_t g = (size_t)(r0g + t) * Dd + jt * 128 + d4;
            *(ull*)(pKh + off) = *(const ull*)&KhG[g];
            *(ull*)(pKl + off) = *(const ull*)&KlG[g];
            *(ull*)(pQh + off) = *(const ull*)&QhG[g];
            *(ull*)(pQl + off) = *(const ull*)&QlG[g];
        }
        __syncthreads();
#pragma unroll
        for (int p = 0; p < 3; p++) {
            const uint32_t aT = mat ? (p < 2 ? qhB : qlB) : (p < 2 ? khB : klB);
            const uint32_t bT = (p == 1) ? klB : khB;
#pragma unroll
            for (int k = 0; k < 8; k++) {
                uint32_t a[4];
                {
                    const int r = mb * 16 + (lane & 15);
                    const int cc = k * 2 + (lane >> 4);
                    ldsm_x4(a, aT + r * 272u + ((uint32_t)(cc ^ ((r >> 3) & 1)) << 4));
                }
#pragma unroll
                for (int nb4 = 0; nb4 < 4; nb4++) {
                    uint32_t bb[4];
                    const int r = nb4 * 16 + (lane & 7) + ((lane >> 4) << 3);
                    const int cc = k * 2 + ((lane >> 3) & 1);
                    ldsm_x4(bb, bT + r * 272u + ((uint32_t)(cc ^ ((r >> 3) & 1)) << 4));
                    mma_bf16(cacc[nb4 * 2 + 0], a, bb[0], bb[1]);
                    mma_bf16(cacc[nb4 * 2 + 1], a, bb[2], bb[3]);
                }
            }
        }
    }

    const size_t base = ((size_t)(b * NCH) + c) * (CH * CH);
    const int t0r = mb * 16 + fr, t1r = t0r + 8;
    if (mat == 0) {
        const float bt0 = Betad[r0g + t0r], bt1 = Betad[r0g + t1r];
#pragma unroll
        for (int nb = 0; nb < 8; nb++) {
            const int j = nb * 8 + fc;
            float2 o0, o1;
            o0.x = (j     < t0r) ? bt0 * cacc[nb][0] : 0.f;
            o0.y = (j + 1 < t0r) ? bt0 * cacc[nb][1] : 0.f;
            o1.x = (j     < t1r) ? bt1 * cacc[nb][2] : 0.f;
            o1.y = (j + 1 < t1r) ? bt1 * cacc[nb][3] : 0.f;
            *(float2*)&Ag[base + t0r * CH + j] = o0;
            *(float2*)&Ag[base + t1r * CH + j] = o1;
        }
    } else {
#pragma unroll
        for (int nb = 0; nb < 8; nb++) {
            const int j = nb * 8 + fc;
            float2 o0, o1;
            o0.x = (j     <= t0r) ? cacc[nb][0] : 0.f;
            o0.y = (j + 1 <= t0r) ? cacc[nb][1] : 0.f;
            o1.x = (j     <= t1r) ? cacc[nb][2] : 0.f;
            o1.y = (j + 1 <= t1r) ? cacc[nb][3] : 0.f;
            *(float2*)&Gg[base + t0r * CH + j] = o0;
            *(float2*)&Gg[base + t1r * CH + j] = o1;
        }
    }
}

// ---------------- chunked delta-rule scan: mma phases A & D ----------------
__global__ __launch_bounds__(256) void scan_kernel(
    const __nv_bfloat16* __restrict__ KhG, const __nv_bfloat16* __restrict__ KlG,
    const __nv_bfloat16* __restrict__ QhG, const __nv_bfloat16* __restrict__ QlG,
    const float* __restrict__ Vd, const float* __restrict__ Betad,
    const float* __restrict__ Ag, const float* __restrict__ Gg,
    float* __restrict__ Od)
{
    extern __shared__ char sraw[];
    float* S     = (float*)(sraw + OFF_S);     // [32][520]
    float* As    = (float*)(sraw + OFF_AS);    // [64][66]
    float* Gs    = (float*)(sraw + OFF_GS);    // [64][66]
    float* Um    = (float*)(sraw + OFF_UM);    // [64][34]
    float* QSm   = (float*)(sraw + OFF_QS);    // [64][34]
    float* Vb    = (float*)(sraw + OFF_VB);    // [64][34]
    float* betas = (float*)(sraw + OFF_BETA);  // [64]
    char* pKh = sraw + OFF_KH;  char* pKl = sraw + OFF_KL;
    char* pQh = sraw + OFF_QH;  char* pQl = sraw + OFF_QL;
    char* pSh = sraw + OFF_SH;  char* pSl = sraw + OFF_SL;
    char* pUh = sraw + OFF_UH;  char* pUl = sraw + OFF_UL;
    const uint32_t khB = smem_u32(pKh), klB = smem_u32(pKl);
    const uint32_t qhB = smem_u32(pQh), qlB = smem_u32(pQl);
    const uint32_t shB = smem_u32(pSh), slB = smem_u32(pSl);
    const uint32_t uhB = smem_u32(pUh), ulB = smem_u32(pUl);

    const int b = blockIdx.y;
    const int i0 = blockIdx.x * DV;
    const int tid = threadIdx.x;
    const int lane = tid & 31, wid = tid >> 5;
    const int fr = lane >> 2, fc = 2 * (lane & 3);

    for (int e = tid; e < 32 * 520; e += 256) S[e] = 0.f;
    __syncthreads();

    for (int c = 0; c < NCH; c++) {
        const int r0g = b * Tt + c * CH;
        const size_t agbase = ((size_t)(b * NCH) + c) * (CH * CH);

        for (int e = tid; e < CH * CH; e += 256) {
            const int t = e >> 6, j = e & 63;
            As[t * 66 + j] = Ag[agbase + e];
            Gs[t * 66 + j] = Gg[agbase + e];
        }
        for (int e = tid; e < CH * DV; e += 256) {
            const int t = e >> 5, i = e & 31;
            Vb[t * 34 + i] = Vd[(size_t)(r0g + t) * Dd + i0 + i];
        }
        if (tid < 64) betas[tid] = Betad[r0g + tid];
        __syncthreads();

        // ---- Phase A ----
        const int mat = wid >> 2;
        const int mb  = wid & 3;
        float cacc[4][4];
#pragma unroll
        for (int nb = 0; nb < 4; nb++)
#pragma unroll
            for (int e = 0; e < 4; e++) cacc[nb][e] = 0.f;

#pragma unroll 1
        for (int jt = 0; jt < 4; jt++) {
#pragma unroll
            for (int n = 0; n < 8; n++) {
                const int e = tid + n * 256;
                const int t = e >> 5, d4 = (e & 31) * 4;
                const uint32_t off = (uint32_t)t * 272u
                    + ((uint32_t)((d4 >> 3) ^ ((t >> 3) & 1)) << 4) + (d4 & 7) * 2;
                const size_t g = (size_t)(r0g + t) * Dd + jt * 128 + d4;
                *(ull*)(pKh + off) = *(const ull*)&KhG[g];
                *(ull*)(pKl + off) = *(const ull*)&KlG[g];
                *(ull*)(pQh + off) = *(const ull*)&QhG[g];
                *(ull*)(pQl + off) = *(const ull*)&QlG[g];
            }
#pragma unroll
            for (int n = 0; n < 4; n++) {
                const int e = tid + n * 256;
                const int i = e >> 5, d4 = (e & 31) * 4;
                float4 v = *(const float4*)&S[i * 520 + jt * 128 + d4];
                ull hw, lw; split4(v, hw, lw);
                const uint32_t off = (uint32_t)i * 272u
                    + ((uint32_t)((d4 >> 3) ^ ((i >> 3) & 1)) << 4) + (d4 & 7) * 2;
                *(ull*)(pSh + off) = hw;
                *(ull*)(pSl + off) = lw;
            }
            __syncthreads();
#pragma unroll
            for (int p = 0; p < 3; p++) {
                const uint32_t aT = mat ? (p < 2 ? qhB : qlB) : (p < 2 ? khB : klB);
                const uint32_t bT = (p == 1) ? slB : shB;
#pragma unroll
                for (int k = 0; k < 8; k++) {
                    uint32_t a[4], b0[4], b1[4];
                    {
                        const int r = mb * 16 + (lane & 15);
                        const int cc = k * 2 + (lane >> 4);
                        ldsm_x4(a, aT + r * 272u + ((uint32_t)(cc ^ ((r >> 3) & 1)) << 4));
                    }
                    {
                        const int r = (lane & 7) + ((lane >> 4) << 3);
                        const int cc = k * 2 + ((lane >> 3) & 1);
                        ldsm_x4(b0, bT + r * 272u + ((uint32_t)(cc ^ ((r >> 3) & 1)) << 4));
                        const int r2 = r + 16;
                        ldsm_x4(b1, bT + r2 * 272u + ((uint32_t)(cc ^ ((r2 >> 3) & 1)) << 4));
                    }
                    mma_bf16(cacc[0], a, b0[0], b0[1]);
                    mma_bf16(cacc[1], a, b0[2], b0[3]);
                    mma_bf16(cacc[2], a, b1[0], b1[1]);
                    mma_bf16(cacc[3], a, b1[2], b1[3]);
                }
            }
            __syncthreads();
        }

        {
            const int t0r = mb * 16 + fr, t1r = t0r + 8;
            if (mat == 0) {
                const float b0v = betas[t0r], b1v = betas[t1r];
#pragma unroll
                for (int nb = 0; nb < 4; nb++) {
                    const int i = nb * 8 + fc;
                    float2 v0 = *(float2*)&Vb[t0r * 34 + i];
                    float2 v1 = *(float2*)&Vb[t1r * 34 + i];
                    *(float2*)&Um[t0r * 34 + i] =
                        make_float2(b0v * (v0.x - cacc[nb][0]), b0v * (v0.y - cacc[nb][1]));
                    *(float2*)&Um[t1r * 34 + i] =
                        make_float2(b1v * (v1.x - cacc[nb][2]), b1v * (v1.y - cacc[nb][3]));
                }
            } else {
#pragma unroll
                for (int nb = 0; nb < 4; nb++) {
                    const int i = nb * 8 + fc;
                    *(float2*)&QSm[t0r * 34 + i] = make_float2(cacc[nb][0], cacc[nb][1]);
                    *(float2*)&QSm[t1r * 34 + i] = make_float2(cacc[nb][2], cacc[nb][3]);
                }
            }
        }
        __syncthreads();

        // ---- Phase B ----
#pragma unroll
        for (int blk = 0; blk < 4; blk++) {
            const int bt0 = blk * 16;
            if (wid == 0) {
                for (int t = bt0; t < bt0 + 16; t++) {
                    float s = Um[t * 34 + lane];
                    for (int j = bt0; j < t; j++)
                        s -= As[t * 66 + j] * Um[j * 34 + lane];
                    Um[t * 34 + lane] = s;
                }
            }
            __syncthreads();
            if (blk < 3) {
                const int rem = 64 - (blk + 1) * 16;
                for (int e = tid; e < rem * 32; e += 256) {
                    const int t = (blk + 1) * 16 + (e >> 5);
                    const int i = e & 31;
                    float s = Um[t * 34 + i];
#pragma unroll
                    for (int j = 0; j < 16; j++)
                        s -= As[t * 66 + bt0 + j] * Um[(bt0 + j) * 34 + i];
                    Um[t * 34 + i] = s;
                }
                __syncthreads();
            }
        }

        // ---- Phase C ----
        for (int e = tid; e < CH * 16; e += 256) {
            const int t = e >> 4, ip = (e & 15) * 2;
            ull s2 = *(const ull*)&QSm[t * 34 + ip];
            for (int j = 0; j <= t; j++) {
                ull g2 = pk(Gs[t * 66 + j], Gs[t * 66 + j]);
                fma2(s2, g2, *(const ull*)&Um[j * 34 + ip]);
            }
            *(float2*)&Od[(size_t)(r0g + t) * Dd + i0 + ip] = upk(s2);
        }

        // ---- U -> bf16 hi/lo transposed ----
        for (int e = tid; e < 2048; e += 256) {
            const int t = e >> 5, i = e & 31;
            const float u = Um[t * 34 + i];
            unsigned short uh, ul; split2(u, uh, ul);
            const uint32_t off = (uint32_t)i * 144u
                + ((uint32_t)((t >> 3) ^ ((i >> 3) & 1)) << 4) + (t & 7) * 2;
            *(unsigned short*)(pUh + off) = uh;
            *(unsigned short*)(pUl + off) = ul;
        }
        __syncthreads();

        // ---- Phase D ----
#pragma unroll 1
        for (int jt = 0; jt < 4; jt++) {
#pragma unroll
            for (int n = 0; n < 8; n++) {
                const int e = tid + n * 256;
                const int t = e >> 5, d4 = (e & 31) * 4;
                const uint32_t off = (uint32_t)t * 272u
                    + ((uint32_t)((d4 >> 3) ^ ((t >> 3) & 1)) << 4) + (d4 & 7) * 2;
                const size_t g = (size_t)(r0g + t) * Dd + jt * 128 + d4;
                *(ull*)(pKh + off) = *(const ull*)&KhG[g];
                *(ull*)(pKl + off) = *(const ull*)&KlG[g];
            }
            __syncthreads();

            float cf[2][2][4];
            const int dbase = jt * 128 + wid * 16;
#pragma unroll
            for (int mi = 0; mi < 2; mi++)
#pragma unroll
                for (int n8 = 0; n8 < 2; n8++) {
                    const int i0r = mi * 16 + fr;
                    const int col = dbase + n8 * 8 + fc;
                    float2 x0 = *(float2*)&S[i0r * 520 + col];
                    float2 x1 = *(float2*)&S[(i0r + 8) * 520 + col];
                    cf[mi][n8][0] = x0.x; cf[mi][n8][1] = x0.y;
                    cf[mi][n8][2] = x1.x; cf[mi][n8][3] = x1.y;
                }
#pragma unroll
            for (int p = 0; p < 3; p++) {
                const uint32_t aT = (p < 2) ? uhB : ulB;
                const uint32_t bT = (p == 1) ? klB : khB;
#pragma unroll
                for (int k = 0; k < 4; k++) {
                    uint32_t a0[4], a1[4], bb[4];
                    {
                        const int r = lane & 15;
                        const int cc = k * 2 + (lane >> 4);
                        ldsm_x4(a0, aT + r * 144u + ((uint32_t)(cc ^ ((r >> 3) & 1)) << 4));
                        const int r2 = 16 + (lane & 15);
                        ldsm_x4(a1, aT + r2 * 144u + ((uint32_t)(cc ^ ((r2 >> 3) & 1)) << 4));
                    }
                    {
                        const int tr = k * 16 + (lane & 15);
                        const int cc = wid * 2 + (lane >> 4);
                        ldsm_x4t(bb, bT + tr * 272u + ((uint32_t)(cc ^ ((tr >> 3) & 1)) << 4));
                    }
                    mma_bf16(cf[0][0], a0, bb[0], bb[1]);
                    mma_bf16(cf[0][1], a0, bb[2], bb[3]);
                    mma_bf16(cf[1][0], a1, bb[0], bb[1]);
                    mma_bf16(cf[1][1], a1, bb[2], bb[3]);
                }
            }
#pragma unroll
            for (int mi = 0; mi < 2; mi++)
#pragma unroll
                for (int n8 = 0; n8 < 2; n8++) {
                    const int i0r = mi * 16 + fr;
                    const int col = dbase + n8 * 8 + fc;
                    *(float2*)&S[i0r * 520 + col] =
                        make_float2(cf[mi][n8][0], cf[mi][n8][1]);
                    *(float2*)&S[(i0r + 8) * 520 + col] =
                        make_float2(cf[mi][n8][2], cf[mi][n8][3]);
                }
            __syncthreads();
        }
    }
}

extern "C" void kernel_launch(void* const* d_in, const int* in_sizes, int n_in,
                              void* d_out, int out_size)
{
    const float* x     = (const float*)d_in[0];
    const float* Wq    = (const float*)d_in[1];
    const float* bq    = (const float*)d_in[2];
    const float* Wk    = (const float*)d_in[3];
    const float* bk    = (const float*)d_in[4];
    const float* Wv    = (const float*)d_in[5];
    const float* bv    = (const float*)d_in[6];
    const float* Wbeta = (const float*)d_in[7];
    const float* bbeta = (const float*)d_in[8];
    const float* Wo    = (const float*)d_in[9];
    const float* bo    = (const float*)d_in[10];
    float* out = (float*)d_out;

    float *pQ, *pK, *pV, *pO, *pBeta, *pA, *pG;
    cudaGetSymbolAddress((void**)&pQ, g_Q);
    cudaGetSymbolAddress((void**)&pK, g_K);
    cudaGetSymbolAddress((void**)&pV, g_V);
    cudaGetSymbolAddress((void**)&pO, g_O);
    cudaGetSymbolAddress((void**)&pBeta, g_Beta);
    cudaGetSymbolAddress((void**)&pA, g_A);
    cudaGetSymbolAddress((void**)&pG, g_G);

    __nv_bfloat16 *pxh, *pxl, *poh, *pol, *pkh, *pkl, *pqh, *pql;
    __nv_bfloat16 *pwqh, *pwql, *pwkh, *pwkl, *pwvh, *pwvl, *pwoh, *pwol;
    cudaGetSymbolAddress((void**)&pxh, g_xh);
    cudaGetSymbolAddress((void**)&pxl, g_xl);
    cudaGetSymbolAddress((void**)&poh, g_oh);
    cudaGetSymbolAddress((void**)&pol, g_ol);
    cudaGetSymbolAddress((void**)&pkh, g_kh);
    cudaGetSymbolAddress((void**)&pkl, g_kl);
    cudaGetSymbolAddress((void**)&pqh, g_qh);
    cudaGetSymbolAddress((void**)&pql, g_ql);
    cudaGetSymbolAddress((void**)&pwqh, g_wqh);
    cudaGetSymbolAddress((void**)&pwql, g_wql);
    cudaGetSymbolAddress((void**)&pwkh, g_wkh);
    cudaGetSymbolAddress((void**)&pwkl, g_wkl);
    cudaGetSymbolAddress((void**)&pwvh, g_wvh);
    cudaGetSymbolAddress((void**)&pwvl, g_wvl);
    cudaGetSymbolAddress((void**)&pwoh, g_woh);
    cudaGetSymbolAddress((void**)&pwol, g_wol);

    cudaFuncSetAttribute(scan_kernel,
                         cudaFuncAttributeMaxDynamicSharedMemorySize, SCAN_SMEM);
    cudaFuncSetAttribute(tgemm_mma_kernel,
                         cudaFuncAttributeMaxDynamicSharedMemorySize, TG_SMEM);
    cudaFuncSetAttribute(chunk_ag_mma_kernel,
                         cudaFuncAttributeMaxDynamicSharedMemorySize, AG_SMEM);

    const int nx4 = BT * Dd / 4;
    const int nw4 = Dd * Dd / 4;
    split_kernel<<<(nx4 + 255) / 256, 256>>>(x, pxh, pxl, nx4);
    split_kernel<<<(nw4 + 255) / 256, 256>>>(Wq, pwqh, pwql, nw4);
    split_kernel<<<(nw4 + 255) / 256, 256>>>(Wk, pwkh, pwkl, nw4);
    split_kernel<<<(nw4 + 255) / 256, 256>>>(Wv, pwvh, pwvl, nw4);
    split_kernel<<<(nw4 + 255) / 256, 256>>>(Wo, pwoh, pwol, nw4);

    dim3 tgrid(Dd / 128, BT / 128);
    tgemm_mma_kernel<<<tgrid, 256, TG_SMEM>>>(pxh, pxl, pwqh, pwql, bq, pQ);
    tgemm_mma_kernel<<<tgrid, 256, TG_SMEM>>>(pxh, pxl, pwkh, pwkl, bk, pK);
    tgemm_mma_kernel<<<tgrid, 256, TG_SMEM>>>(pxh, pxl, pwvh, pwvl, bv, pV);

    norm_beta_kernel<<<BT, 128>>>(pK, Wbeta, bbeta, pBeta);

    split_kernel<<<(nx4 + 255) / 256, 256>>>(pK, pkh, pkl, nx4);
    split_kernel<<<(nx4 + 255) / 256, 256>>>(pQ, pqh, pql, nx4);

    chunk_ag_mma_kernel<<<dim3(NCH, Bb), 256, AG_SMEM>>>(
        pkh, pkl, pqh, pql, pBeta, pA, pG);

    scan_kernel<<<dim3(NVT, Bb), 256, SCAN_SMEM>>>(
        pkh, pkl, pqh, pql, pV, pBeta, pA, pG, pO);

    split_kernel<<<(nx4 + 255) / 256, 256>>>(pO, poh, pol, nx4);
    tgemm_mma_kernel<<<tgrid, 256, TG_SMEM>>>(poh, pol, pwoh, pwol, bo, out);
}

// round 10
// speedup vs baseline: 3.8811x; 1.3789x over previous
#include <cuda_runtime.h>
#include <cuda_bf16.h>
#include <math.h>
#include <stdint.h>

namespace {
constexpr int Bb  = 8;
constexpr int Tt  = 2048;
constexpr int Dd  = 512;
constexpr int BT  = Bb * Tt;
constexpr int CH  = 64;
constexpr int NCH = Tt / CH;   // 32
constexpr int DV  = 32;
constexpr int NVT = Dd / DV;   // 16

// ---- scan smem layout (byte offsets) ----
constexpr int OFF_S    = 0;              // float [32][520]
constexpr int OFF_UM   = 66560;          // float [64][34]
constexpr int OFF_QS   = 75264;          // float [64][34]
constexpr int OFF_VB   = 83968;          // float [64][34]
constexpr int OFF_BETA = 92672;          // float [64]
constexpr int OFF_KH   = 92928;          // bf16 [64][136]
constexpr int OFF_KL   = 110336;
constexpr int OFF_QH   = 127744;
constexpr int OFF_QL   = 145152;
constexpr int OFF_SH   = 162560;         // bf16 [32][136]
constexpr int OFF_SL   = 171264;
constexpr int OFF_UH   = 179968;         // bf16 [32][72]
constexpr int OFF_UL   = 184576;
constexpr int OFF_TH   = 189184;         // bf16 [64][72]
constexpr int OFF_TL   = 198400;
constexpr int OFF_GH   = 207616;         // bf16 [64][72]
constexpr int OFF_GL   = 216832;
constexpr int SCAN_SMEM = 226048;

// tgemm: 3 slots x (Ah|Al|Bh|Bl) each 128x40 halves = 10240 B
constexpr int TG_TILE  = 10240;
constexpr int TG_SLOT  = 4 * TG_TILE;
constexpr int TG_SMEM  = 3 * TG_SLOT;          // 122880

// chunk_ag smem: 4 staging tiles + As fp32 + Tm fp32 + Ws
constexpr int AG_TILE  = 17408;
constexpr int AG_AS    = 4 * AG_TILE;          // 69632
constexpr int AG_TM    = AG_AS + 64 * 66 * 4;  // 86528
constexpr int AG_WS    = AG_TM + 64 * 66 * 4;  // 103424
constexpr int AG_SMEM  = AG_WS + 16 * 17 * 4;  // 104512
}

using ull = unsigned long long;
__device__ __forceinline__ ull pk(float x, float y) {
    ull r; asm("mov.b64 %0,{%1,%2};" : "=l"(r) : "f"(x), "f"(y)); return r;
}
__device__ __forceinline__ float2 upk(ull v) {
    float2 r; asm("mov.b64 {%0,%1},%2;" : "=f"(r.x), "=f"(r.y) : "l"(v)); return r;
}

// ---------------- device scratch ----------------
__device__ float g_Q[BT * Dd];
__device__ float g_K[BT * Dd];
__device__ float g_V[BT * Dd];
__device__ float g_O[BT * Dd];
__device__ float g_Beta[BT];
__device__ __nv_bfloat16 g_xh[BT * Dd];
__device__ __nv_bfloat16 g_xl[BT * Dd];
__device__ __nv_bfloat16 g_oh[BT * Dd];
__device__ __nv_bfloat16 g_ol[BT * Dd];
__device__ __nv_bfloat16 g_kh[BT * Dd];
__device__ __nv_bfloat16 g_kl[BT * Dd];
__device__ __nv_bfloat16 g_qh[BT * Dd];
__device__ __nv_bfloat16 g_ql[BT * Dd];
__device__ __nv_bfloat16 g_Th[Bb * NCH * CH * CH];
__device__ __nv_bfloat16 g_Tl[Bb * NCH * CH * CH];
__device__ __nv_bfloat16 g_Gh[Bb * NCH * CH * CH];
__device__ __nv_bfloat16 g_Gl[Bb * NCH * CH * CH];
__device__ __nv_bfloat16 g_wqh[Dd * Dd];
__device__ __nv_bfloat16 g_wql[Dd * Dd];
__device__ __nv_bfloat16 g_wkh[Dd * Dd];
__device__ __nv_bfloat16 g_wkl[Dd * Dd];
__device__ __nv_bfloat16 g_wvh[Dd * Dd];
__device__ __nv_bfloat16 g_wvl[Dd * Dd];
__device__ __nv_bfloat16 g_woh[Dd * Dd];
__device__ __nv_bfloat16 g_wol[Dd * Dd];

__device__ __forceinline__ uint32_t smem_u32(const void* p) {
    uint32_t a;
    asm("{ .reg .u64 t; cvta.to.shared.u64 t,%1; cvt.u32.u64 %0,t; }" : "=r"(a) : "l"(p));
    return a;
}
__device__ __forceinline__ void ldsm_x4(uint32_t* r, uint32_t addr) {
    asm volatile("ldmatrix.sync.aligned.m8n8.x4.shared.b16 {%0,%1,%2,%3}, [%4];"
                 : "=r"(r[0]), "=r"(r[1]), "=r"(r[2]), "=r"(r[3]) : "r"(addr));
}
__device__ __forceinline__ void ldsm_x4t(uint32_t* r, uint32_t addr) {
    asm volatile("ldmatrix.sync.aligned.m8n8.x4.trans.shared.b16 {%0,%1,%2,%3}, [%4];"
                 : "=r"(r[0]), "=r"(r[1]), "=r"(r[2]), "=r"(r[3]) : "r"(addr));
}
__device__ __forceinline__ void mma_bf16(float* d, const uint32_t* a,
                                         uint32_t b0, uint32_t b1) {
    asm volatile(
        "mma.sync.aligned.m16n8k16.row.col.f32.bf16.bf16.f32 "
        "{%0,%1,%2,%3}, {%4,%5,%6,%7}, {%8,%9}, {%0,%1,%2,%3};"
        : "+f"(d[0]), "+f"(d[1]), "+f"(d[2]), "+f"(d[3])
        : "r"(a[0]), "r"(a[1]), "r"(a[2]), "r"(a[3]), "r"(b0), "r"(b1));
}
__device__ __forceinline__ void cp16(uint32_t dst, const void* src) {
    asm volatile("cp.async.ca.shared.global [%0], [%1], 16;" :: "r"(dst), "l"(src));
}
__device__ __forceinline__ void split2(float x, unsigned short& h, unsigned short& l) {
    __nv_bfloat16 hh = __float2bfloat16(x);
    __nv_bfloat16 ll = __float2bfloat16(x - __bfloat162float(hh));
    h = __bfloat16_as_ushort(hh); l = __bfloat16_as_ushort(ll);
}
__device__ __forceinline__ void split4(float4 v, ull& h, ull& l) {
    unsigned short h0, h1, h2, h3, l0, l1, l2, l3;
    split2(v.x, h0, l0); split2(v.y, h1, l1);
    split2(v.z, h2, l2); split2(v.w, h3, l3);
    h = (ull)h0 | ((ull)h1 << 16) | ((ull)h2 << 32) | ((ull)h3 << 48);
    l = (ull)l0 | ((ull)l1 << 16) | ((ull)l2 << 32) | ((ull)l3 << 48);
}

// ---------------- split fp32 -> bf16 hi/lo ----------------
__global__ __launch_bounds__(256) void split_kernel(
    const float* __restrict__ x, __nv_bfloat16* __restrict__ h,
    __nv_bfloat16* __restrict__ l, int n4)
{
    int i = blockIdx.x * 256 + threadIdx.x;
    if (i >= n4) return;
    float4 v = ((const float4*)x)[i];
    ull hw, lw; split4(v, hw, lw);
    ((ull*)h)[i] = hw;
    ((ull*)l)[i] = lw;
}

// ---------------- HMMA split-bf16 GEMM body (3-slot cp.async) ----------------
__device__ __forceinline__ void tgemm_body(
    const __nv_bfloat16* __restrict__ Ah, const __nv_bfloat16* __restrict__ Al,
    const __nv_bfloat16* __restrict__ Bh, const __nv_bfloat16* __restrict__ Bl,
    const float* __restrict__ bias, float* __restrict__ C,
    int bm, int bn, char* tgs)
{
    const uint32_t sBase = smem_u32(tgs);
    const int tid = threadIdx.x, lane = tid & 31, wid = tid >> 5;
    const int wm = wid & 1, wn = wid >> 1;

    float d[4][4][4];
#pragma unroll
    for (int mt = 0; mt < 4; mt++)
#pragma unroll
        for (int nt = 0; nt < 4; nt++)
#pragma unroll
            for (int e = 0; e < 4; e++) d[mt][nt][e] = 0.f;

    uint32_t a_rel[4], b_rel[2];
    {
        const int ar = lane & 15, akoff = (lane >> 4) * 8;
#pragma unroll
        for (int mt = 0; mt < 4; mt++)
            a_rel[mt] = ((wm * 64 + mt * 16 + ar) * 40 + akoff) * 2;
        const int nrow = wn * 32 + ((lane >> 4) << 3) + (lane & 7);
        const int khalf = (lane >> 3) & 1;
#pragma unroll
        for (int np = 0; np < 2; np++)
            b_rel[np] = ((nrow + np * 16) * 40 + khalf * 8) * 2;
    }

    const int srow0 = tid >> 2,         sc0 = tid & 3;
    const int srow1 = (tid + 256) >> 2, sc1 = (tid + 256) & 3;
    const uint32_t st0 = srow0 * 80 + sc0 * 16;
    const uint32_t st1 = srow1 * 80 + sc1 * 16;

    auto issue = [&](int kt, int slot) {
        const uint32_t b0 = sBase + slot * TG_SLOT;
        const size_t ga0 = (size_t)(bm + srow0) * Dd + kt * 32 + sc0 * 8;
        const size_t ga1 = (size_t)(bm + srow1) * Dd + kt * 32 + sc1 * 8;
        const size_t gb0 = (size_t)(bn + srow0) * Dd + kt * 32 + sc0 * 8;
        const size_t gb1 = (size_t)(bn + srow1) * Dd + kt * 32 + sc1 * 8;
        cp16(b0 + st0,               Ah + ga0);
        cp16(b0 + st1,               Ah + ga1);
        cp16(b0 + TG_TILE + st0,     Al + ga0);
        cp16(b0 + TG_TILE + st1,     Al + ga1);
        cp16(b0 + 2 * TG_TILE + st0, Bh + gb0);
        cp16(b0 + 2 * TG_TILE + st1, Bh + gb1);
        cp16(b0 + 3 * TG_TILE + st0, Bl + gb0);
        cp16(b0 + 3 * TG_TILE + st1, Bl + gb1);
        asm volatile("cp.async.commit_group;");
    };

    issue(0, 0);
    issue(1, 1);
#pragma unroll 1
    for (int s = 0; s < 16; s++) {
        if (s == 15) asm volatile("cp.async.wait_group 0;");
        else         asm volatile("cp.async.wait_group 1;");
        __syncthreads();
        if (s + 2 < 16) issue(s + 2, (s + 2) % 3);
        const uint32_t slotB = sBase + (s % 3) * TG_SLOT;
#pragma unroll
        for (int p = 0; p < 3; p++) {
            const uint32_t aO = slotB + (p == 2 ? TG_TILE : 0);
            const uint32_t bO = slotB + 2 * TG_TILE + (p == 1 ? TG_TILE : 0);
#pragma unroll
            for (int ks = 0; ks < 2; ks++) {
                uint32_t a[4][4], b[2][4];
#pragma unroll
                for (int mt = 0; mt < 4; mt++) ldsm_x4(a[mt], aO + a_rel[mt] + ks * 32);
#pragma unroll
                for (int np = 0; np < 2; np++) ldsm_x4(b[np], bO + b_rel[np] + ks * 32);
#pragma unroll
                for (int mt = 0; mt < 4; mt++)
#pragma unroll
                    for (int nt = 0; nt < 4; nt++)
                        mma_bf16(d[mt][nt], a[mt],
                                 b[nt >> 1][(nt & 1) * 2], b[nt >> 1][(nt & 1) * 2 + 1]);
            }
        }
    }

#pragma unroll
    for (int mt = 0; mt < 4; mt++) {
        const int r0 = bm + wm * 64 + mt * 16 + (lane >> 2);
#pragma unroll
        for (int nt = 0; nt < 4; nt++) {
            const int c0 = bn + wn * 32 + nt * 8 + (lane & 3) * 2;
            const float b0 = bias[c0], b1 = bias[c0 + 1];
            float2 o0 = make_float2(d[mt][nt][0] + b0, d[mt][nt][1] + b1);
            float2 o1 = make_float2(d[mt][nt][2] + b0, d[mt][nt][3] + b1);
            *(float2*)&C[(size_t)r0 * Dd + c0] = o0;
            *(float2*)&C[(size_t)(r0 + 8) * Dd + c0] = o1;
        }
    }
}

__global__ __launch_bounds__(256) void tgemm_mma_kernel(
    const __nv_bfloat16* __restrict__ Ah, const __nv_bfloat16* __restrict__ Al,
    const __nv_bfloat16* __restrict__ Bh, const __nv_bfloat16* __restrict__ Bl,
    const float* __restrict__ bias, float* __restrict__ C)
{
    extern __shared__ char tgs[];
    tgemm_body(Ah, Al, Bh, Bl, bias, C, blockIdx.y * 128, blockIdx.x * 128, tgs);
}

__global__ __launch_bounds__(256) void tgemm_qkv_kernel(
    const __nv_bfloat16* __restrict__ Ah, const __nv_bfloat16* __restrict__ Al,
    const __nv_bfloat16* __restrict__ Bqh, const __nv_bfloat16* __restrict__ Bql,
    const __nv_bfloat16* __restrict__ Bkh, const __nv_bfloat16* __restrict__ Bkl,
    const __nv_bfloat16* __restrict__ Bvh, const __nv_bfloat16* __restrict__ Bvl,
    const float* __restrict__ bq, const float* __restrict__ bk,
    const float* __restrict__ bv,
    float* __restrict__ Cq, float* __restrict__ Ck, float* __restrict__ Cv)
{
    extern __shared__ char tgs[];
    const int gsel = blockIdx.x >> 2;
    const int bn = (blockIdx.x & 3) * 128;
    const __nv_bfloat16* Bh = (gsel == 0) ? Bqh : (gsel == 1) ? Bkh : Bvh;
    const __nv_bfloat16* Bl = (gsel == 0) ? Bql : (gsel == 1) ? Bkl : Bvl;
    const float* bias = (gsel == 0) ? bq : (gsel == 1) ? bk : bv;
    float* C = (gsel == 0) ? Cq : (gsel == 1) ? Ck : Cv;
    tgemm_body(Ah, Al, Bh, Bl, bias, C, blockIdx.y * 128, bn, tgs);
}

// ---------------- l2norm + beta ----------------
__global__ __launch_bounds__(128) void norm_beta_kernel(
    float* __restrict__ Kd, const float* __restrict__ wb,
    const float* __restrict__ bb, float* __restrict__ Beta)
{
    const int row = blockIdx.x, tid = threadIdx.x;
    float4 v = ((const float4*)(Kd + (size_t)row * Dd))[tid];
    float ss = v.x * v.x + v.y * v.y + v.z * v.z + v.w * v.w;
#pragma unroll
    for (int o = 16; o; o >>= 1) ss += __shfl_xor_sync(0xffffffffu, ss, o);
    __shared__ float red1[4];
    if ((tid & 31) == 0) red1[tid >> 5] = ss;
    __syncthreads();
    const float inv = 1.0f / fmaxf(sqrtf(red1[0] + red1[1] + red1[2] + red1[3]), 1e-12f);
    float4 w = ((const float4*)wb)[tid];
    float bd = v.x * w.x + v.y * w.y + v.z * w.z + v.w * w.w;
#pragma unroll
    for (int o = 16; o; o >>= 1) bd += __shfl_xor_sync(0xffffffffu, bd, o);
    __shared__ float red2[4];
    if ((tid & 31) == 0) red2[tid >> 5] = bd;
    __syncthreads();
    v.x *= inv; v.y *= inv; v.z *= inv; v.w *= inv;
    ((float4*)(Kd + (size_t)row * Dd))[tid] = v;
    if (tid == 0) {
        const float z = (red2[0] + red2[1] + red2[2] + red2[3]) * inv + bb[0];
        Beta[row] = 1.0f / (1.0f + expf(-z));
    }
}

// ---------------- chunk_ag: A,G via mma + T = (I+A)^-1, all bf16-split out ----
__global__ __launch_bounds__(256) void chunk_ag_mma_kernel(
    const __nv_bfloat16* __restrict__ KhG, const __nv_bfloat16* __restrict__ KlG,
    const __nv_bfloat16* __restrict__ QhG, const __nv_bfloat16* __restrict__ QlG,
    const float* __restrict__ Betad,
    __nv_bfloat16* __restrict__ ThG, __nv_bfloat16* __restrict__ TlG,
    __nv_bfloat16* __restrict__ GhG, __nv_bfloat16* __restrict__ GlG)
{
    extern __shared__ char ags[];
    char* pKh = ags;               char* pKl = ags + AG_TILE;
    char* pQh = ags + 2 * AG_TILE; char* pQl = ags + 3 * AG_TILE;
    float* As = (float*)(ags + AG_AS);   // [64][66]
    float* Tm = (float*)(ags + AG_TM);   // [64][66]
    float* Ws = (float*)(ags + AG_WS);   // [16][17]
    const uint32_t khB = smem_u32(pKh), klB = smem_u32(pKl);
    const uint32_t qhB = smem_u32(pQh), qlB = smem_u32(pQl);

    const int c = blockIdx.x, b = blockIdx.y;
    const int r0g = b * Tt + c * CH;
    const int tid = threadIdx.x, lane = tid & 31, wid = tid >> 5;
    const int mat = wid >> 2, mb = wid & 3;
    const int fr = lane >> 2, fc = 2 * (lane & 3);

    float cacc[8][4];
#pragma unroll
    for (int nb = 0; nb < 8; nb++)
#pragma unroll
        for (int e = 0; e < 4; e++) cacc[nb][e] = 0.f;

#pragma unroll 1
    for (int jt = 0; jt < 4; jt++) {
        if (jt) __syncthreads();
#pragma unroll
        for (int n = 0; n < 8; n++) {
            const int e = tid + n * 256;
            const int t = e >> 5, d4 = (e & 31) * 4;
            const uint32_t off = (uint32_t)t * 272u
                + ((uint32_t)((d4 >> 3) ^ ((t >> 3) & 1)) << 4) + (d4 & 7) * 2;
            const size_t g = (size_t)(r0g + t) * Dd + jt * 128 + d4;
            *(ull*)(pKh + off) = *(const ull*)&KhG[g];
            *(ull*)(pKl + off) = *(const ull*)&KlG[g];
            *(ull*)(pQh + off) = *(const ull*)&QhG[g];
            *(ull*)(pQl + off) = *(const ull*)&QlG[g];
        }
        __syncthreads();
#pragma unroll
        for (int p = 0; p < 3; p++) {
            const uint32_t aT = mat ? (p < 2 ? qhB : qlB) : (p < 2 ? khB : klB);
            const uint32_t bT = (p == 1) ? klB : khB;
#pragma unroll
            for (int k = 0; k < 8; k++) {
                uint32_t a[4];
                {
                    const int r = mb * 16 + (lane & 15);
                    const int cc = k * 2 + (lane >> 4);
                    ldsm_x4(a, aT + r * 272u + ((uint32_t)(cc ^ ((r >> 3) & 1)) << 4));
                }
#pragma unroll
                for (int nb4 = 0; nb4 < 4; nb4++) {
                    uint32_t bb[4];
                    const int r = nb4 * 16 + (lane & 7) + ((lane >> 4) << 3);
                    const int cc = k * 2 + ((lane >> 3) & 1);
                    ldsm_x4(bb, bT + r * 272u + ((uint32_t)(cc ^ ((r >> 3) & 1)) << 4));
                    mma_bf16(cacc[nb4 * 2 + 0], a, bb[0], bb[1]);
                    mma_bf16(cacc[nb4 * 2 + 1], a, bb[2], bb[3]);
                }
            }
        }
    }
    __syncthreads();

    const size_t gbase = ((size_t)(b * NCH) + c) * (CH * CH);
    const int t0r = mb * 16 + fr, t1r = t0r + 8;
    if (mat == 0) {
        // A (masked, beta-scaled) -> smem As
        const float bt0 = Betad[r0g + t0r], bt1 = Betad[r0g + t1r];
#pragma unroll
        for (int nb = 0; nb < 8; nb++) {
            const int j = nb * 8 + fc;
            float2 o0, o1;
            o0.x = (j     < t0r) ? bt0 * cacc[nb][0] : 0.f;
            o0.y = (j + 1 < t0r) ? bt0 * cacc[nb][1] : 0.f;
            o1.x = (j     < t1r) ? bt1 * cacc[nb][2] : 0.f;
            o1.y = (j + 1 < t1r) ? bt1 * cacc[nb][3] : 0.f;
            *(float2*)&As[t0r * 66 + j] = o0;
            *(float2*)&As[t1r * 66 + j] = o1;
        }
    } else {
        // G (masked incl diag) -> split bf16 hi/lo direct to global
        unsigned short* Gh = (unsigned short*)GhG;
        unsigned short* Gl = (unsigned short*)GlG;
#pragma unroll
        for (int nb = 0; nb < 8; nb++) {
            const int j = nb * 8 + fc;
            float v00 = (j     <= t0r) ? cacc[nb][0] : 0.f;
            float v01 = (j + 1 <= t0r) ? cacc[nb][1] : 0.f;
            float v10 = (j     <= t1r) ? cacc[nb][2] : 0.f;
            float v11 = (j + 1 <= t1r) ? cacc[nb][3] : 0.f;
            unsigned short h, l;
            split2(v00, h, l); Gh[gbase + t0r * 64 + j] = h;     Gl[gbase + t0r * 64 + j] = l;
            split2(v01, h, l); Gh[gbase + t0r * 64 + j + 1] = h; Gl[gbase + t0r * 64 + j + 1] = l;
            split2(v10, h, l); Gh[gbase + t1r * 64 + j] = h;     Gl[gbase + t1r * 64 + j] = l;
            split2(v11, h, l); Gh[gbase + t1r * 64 + j + 1] = h; Gl[gbase + t1r * 64 + j + 1] = l;
        }
    }
    // zero Tm
    for (int e = tid; e < 64 * 66; e += 256) Tm[e] = 0.f;
    __syncthreads();

    // ---- diagonal 16x16 inversions: warp w inverts (I + A_ww) ----
    if (wid < 4) {
        const int r = lane & 15;
        float Lr[16], val[16];
#pragma unroll
        for (int j = 0; j < 16; j++) Lr[j] = As[(wid * 16 + r) * 66 + wid * 16 + j];
#pragma unroll
        for (int cc = 0; cc < 16; cc++) val[cc] = (r == cc) ? 1.f : 0.f;
#pragma unroll
        for (int j = 0; j < 15; j++) {
#pragma unroll
            for (int cc = 0; cc < 16; cc++) {
                if (cc <= j) {
                    float tjc = __shfl_sync(0xffffffffu, val[cc], j);
                    if (r > j) val[cc] -= Lr[j] * tjc;
                }
            }
        }
        if (lane < 16) {
#pragma unroll
            for (int cc = 0; cc < 16; cc++)
                Tm[(wid * 16 + r) * 66 + wid * 16 + cc] = val[cc];
        }
    }
    __syncthreads();

    // ---- off-diagonal blocks: T_ij = -T_ii @ (sum_k A_ik T_kj) ----
    {
        const int oi[6] = {1, 2, 3, 2, 3, 3};
        const int oj[6] = {0, 0, 0, 1, 1, 2};
        const int r = tid >> 4, cc = tid & 15;
#pragma unroll 1
        for (int s6 = 0; s6 < 6; s6++) {
            const int bi = oi[s6], bj = oj[s6];
            float w = 0.f;
            for (int k = bj; k < bi; k++)
#pragma unroll
                for (int m = 0; m < 16; m++)
                    w += As[(bi * 16 + r) * 66 + k * 16 + m] *
                         Tm[(k * 16 + m) * 66 + bj * 16 + cc];
            Ws[r * 17 + cc] = w;
            __syncthreads();
            float t2 = 0.f;
#pragma unroll
            for (int m = 0; m < 16; m++)
                t2 += Tm[(bi * 16 + r) * 66 + bi * 16 + m] * Ws[m * 17 + cc];
            Tm[(bi * 16 + r) * 66 + bj * 16 + cc] = -t2;
            __syncthreads();
        }
    }

    // ---- split Tm -> global bf16 hi/lo ----
    {
        unsigned short* Th = (unsigned short*)ThG;
        unsigned short* Tl = (unsigned short*)TlG;
        for (int e = tid; e < 4096; e += 256) {
            const int t = e >> 6, j = e & 63;
            unsigned short h, l;
            split2(Tm[t * 66 + j], h, l);
            Th[gbase + e] = h; Tl[gbase + e] = l;
        }
    }
}

// ---------------- chunked delta-rule scan: all-mma phases ----------------
__global__ __launch_bounds__(256) void scan_kernel(
    const __nv_bfloat16* __restrict__ KhG, const __nv_bfloat16* __restrict__ KlG,
    const __nv_bfloat16* __restrict__ QhG, const __nv_bfloat16* __restrict__ QlG,
    const __nv_bfloat16* __restrict__ ThG, const __nv_bfloat16* __restrict__ TlG,
    const __nv_bfloat16* __restrict__ GhG, const __nv_bfloat16* __restrict__ GlG,
    const float* __restrict__ Vd, const float* __restrict__ Betad,
    float* __restrict__ Od)
{
    extern __shared__ char sraw[];
    float* S     = (float*)(sraw + OFF_S);     // [32][520]
    float* Um    = (float*)(sraw + OFF_UM);    // [64][34]
    float* QSm   = (float*)(sraw + OFF_QS);    // [64][34]
    float* Vb    = (float*)(sraw + OFF_VB);    // [64][34]
    float* betas = (float*)(sraw + OFF_BETA);  // [64]
    char* pKh = sraw + OFF_KH;  char* pKl = sraw + OFF_KL;
    char* pQh = sraw + OFF_QH;  char* pQl = sraw + OFF_QL;
    char* pSh = sraw + OFF_SH;  char* pSl = sraw + OFF_SL;
    char* pUh = sraw + OFF_UH;  char* pUl = sraw + OFF_UL;
    char* pTh = sraw + OFF_TH;  char* pTl = sraw + OFF_TL;
    char* pGh = sraw + OFF_GH;  char* pGl = sraw + OFF_GL;
    const uint32_t khB = smem_u32(pKh), klB = smem_u32(pKl);
    const uint32_t qhB = smem_u32(pQh), qlB = smem_u32(pQl);
    const uint32_t shB = smem_u32(pSh), slB = smem_u32(pSl);
    const uint32_t uhB = smem_u32(pUh), ulB = smem_u32(pUl);
    const uint32_t thB = smem_u32(pTh), tlB = smem_u32(pTl);
    const uint32_t ghB = smem_u32(pGh), glB = smem_u32(pGl);

    const int b = blockIdx.y;
    const int i0 = blockIdx.x * DV;
    const int tid = threadIdx.x;
    const int lane = tid & 31, wid = tid >> 5;
    const int fr = lane >> 2, fc = 2 * (lane & 3);

    for (int e = tid; e < 32 * 520; e += 256) S[e] = 0.f;
    __syncthreads();

    for (int c = 0; c < NCH; c++) {
        const int r0g = b * Tt + c * CH;
        const size_t gbase = ((size_t)(b * NCH) + c) * (CH * CH);

        // ---- stage T/G bf16 tiles, V slice, beta ----
#pragma unroll
        for (int n = 0; n < 4; n++) {
            const int e = tid + n * 256;          // 1024 ull per array
            const int r = e >> 4, j4 = (e & 15) * 4;
            const uint32_t off = (uint32_t)r * 144u
                + ((uint32_t)((j4 >> 3) ^ ((r >> 3) & 1)) << 4) + (j4 & 7) * 2;
            const size_t g = gbase + r * 64 + j4;
            *(ull*)(pTh + off) = *(const ull*)&ThG[g];
            *(ull*)(pTl + off) = *(const ull*)&TlG[g];
            *(ull*)(pGh + off) = *(const ull*)&GhG[g];
            *(ull*)(pGl + off) = *(const ull*)&GlG[g];
        }
        for (int e = tid; e < CH * DV; e += 256) {
            const int t = e >> 5, i = e & 31;
            Vb[t * 34 + i] = Vd[(size_t)(r0g + t) * Dd + i0 + i];
        }
        if (tid < 64) betas[tid] = Betad[r0g + tid];
        __syncthreads();

        // ---- Phase A: KS / QS via mma ----
        const int mat = wid >> 2;
        const int mb  = wid & 3;
        float cacc[4][4];
#pragma unroll
        for (int nb = 0; nb < 4; nb++)
#pragma unroll
            for (int e = 0; e < 4; e++) cacc[nb][e] = 0.f;

#pragma unroll 1
        for (int jt = 0; jt < 4; jt++) {
#pragma unroll
            for (int n = 0; n < 8; n++) {
                const int e = tid + n * 256;
                const int t = e >> 5, d4 = (e & 31) * 4;
                const uint32_t off = (uint32_t)t * 272u
                    + ((uint32_t)((d4 >> 3) ^ ((t >> 3) & 1)) << 4) + (d4 & 7) * 2;
                const size_t g = (size_t)(r0g + t) * Dd + jt * 128 + d4;
                *(ull*)(pKh + off) = *(const ull*)&KhG[g];
                *(ull*)(pKl + off) = *(const ull*)&KlG[g];
                *(ull*)(pQh + off) = *(const ull*)&QhG[g];
                *(ull*)(pQl + off) = *(const ull*)&QlG[g];
            }
#pragma unroll
            for (int n = 0; n < 4; n++) {
                const int e = tid + n * 256;
                const int i = e >> 5, d4 = (e & 31) * 4;
                float4 v = *(const float4*)&S[i * 520 + jt * 128 + d4];
                ull hw, lw; split4(v, hw, lw);
                const uint32_t off = (uint32_t)i * 272u
                    + ((uint32_t)((d4 >> 3) ^ ((i >> 3) & 1)) << 4) + (d4 & 7) * 2;
                *(ull*)(pSh + off) = hw;
                *(ull*)(pSl + off) = lw;
            }
            __syncthreads();
#pragma unroll
            for (int p = 0; p < 3; p++) {
                const uint32_t aT = mat ? (p < 2 ? qhB : qlB) : (p < 2 ? khB : klB);
                const uint32_t bT = (p == 1) ? slB : shB;
#pragma unroll
                for (int k = 0; k < 8; k++) {
                    uint32_t a[4], b0[4], b1[4];
                    {
                        const int r = mb * 16 + (lane & 15);
                        const int cc = k * 2 + (lane >> 4);
                        ldsm_x4(a, aT + r * 272u + ((uint32_t)(cc ^ ((r >> 3) & 1)) << 4));
                    }
                    {
                        const int r = (lane & 7) + ((lane >> 4) << 3);
                        const int cc = k * 2 + ((lane >> 3) & 1);
                        ldsm_x4(b0, bT + r * 272u + ((uint32_t)(cc ^ ((r >> 3) & 1)) << 4));
                        const int r2 = r + 16;
                        ldsm_x4(b1, bT + r2 * 272u + ((uint32_t)(cc ^ ((r2 >> 3) & 1)) << 4));
                    }
                    mma_bf16(cacc[0], a, b0[0], b0[1]);
                    mma_bf16(cacc[1], a, b0[2], b0[3]);
                    mma_bf16(cacc[2], a, b1[0], b1[1]);
                    mma_bf16(cacc[3], a, b1[2], b1[3]);
                }
            }
            __syncthreads();
        }

        // epilogue: Um = rhs = beta*(V - KS); QSm = QS
        {
            const int t0r = mb * 16 + fr, t1r = t0r + 8;
            if (mat == 0) {
                const float b0v = betas[t0r], b1v = betas[t1r];
#pragma unroll
                for (int nb = 0; nb < 4; nb++) {
                    const int i = nb * 8 + fc;
                    float2 v0 = *(float2*)&Vb[t0r * 34 + i];
                    float2 v1 = *(float2*)&Vb[t1r * 34 + i];
                    *(float2*)&Um[t0r * 34 + i] =
                        make_float2(b0v * (v0.x - cacc[nb][0]), b0v * (v0.y - cacc[nb][1]));
                    *(float2*)&Um[t1r * 34 + i] =
                        make_float2(b1v * (v1.x - cacc[nb][2]), b1v * (v1.y - cacc[nb][3]));
                }
            } else {
#pragma unroll
                for (int nb = 0; nb < 4; nb++) {
                    const int i = nb * 8 + fc;
                    *(float2*)&QSm[t0r * 34 + i] = make_float2(cacc[nb][0], cacc[nb][1]);
                    *(float2*)&QSm[t1r * 34 + i] = make_float2(cacc[nb][2], cacc[nb][3]);
                }
            }
        }
        __syncthreads();

        // ---- split rhs -> UH/UL transposed [i][t] ----
        for (int e = tid; e < 2048; e += 256) {
            const int t = e >> 5, i = e & 31;
            unsigned short uh, ul; split2(Um[t * 34 + i], uh, ul);
            const uint32_t off = (uint32_t)i * 144u
                + ((uint32_t)((t >> 3) ^ ((i >> 3) & 1)) << 4) + (t & 7) * 2;
            *(unsigned short*)(pUh + off) = uh;
            *(unsigned short*)(pUl + off) = ul;
        }
        __syncthreads();

        // ---- Phase B': U = T @ rhs via mma ----
        {
            const int mb2 = wid >> 1, nh = wid & 1;
            float du[2][4];
#pragma unroll
            for (int n8 = 0; n8 < 2; n8++)
#pragma unroll
                for (int e = 0; e < 4; e++) du[n8][e] = 0.f;
#pragma unroll
            for (int p = 0; p < 3; p++) {
                const uint32_t aT = (p < 2) ? thB : tlB;
                const uint32_t bT = (p == 1) ? ulB : uhB;
#pragma unroll
                for (int k = 0; k < 4; k++) {
                    uint32_t a[4], bb[4];
                    {
                        const int r = mb2 * 16 + (lane & 15);
                        const int cc = k * 2 + (lane >> 4);
                        ldsm_x4(a, aT + r * 144u + ((uint32_t)(cc ^ ((r >> 3) & 1)) << 4));
                    }
                    {
                        const int rr = nh * 16 + (lane & 7) + ((lane >> 4) << 3);
                        const int cc = k * 2 + ((lane >> 3) & 1);
                        ldsm_x4(bb, bT + rr * 144u + ((uint32_t)(cc ^ ((rr >> 3) & 1)) << 4));
                    }
                    mma_bf16(du[0], a, bb[0], bb[1]);
                    mma_bf16(du[1], a, bb[2], bb[3]);
                }
            }
            __syncthreads();
            const int t0r = mb2 * 16 + fr, t1r = t0r + 8;
#pragma unroll
            for (int n8 = 0; n8 < 2; n8++) {
                const int i = nh * 16 + n8 * 8 + fc;
                *(float2*)&Um[t0r * 34 + i] = make_float2(du[n8][0], du[n8][1]);
                *(float2*)&Um[t1r * 34 + i] = make_float2(du[n8][2], du[n8][3]);
            }
        }
        __syncthreads();

        // ---- split U -> UH/UL transposed ----
        for (int e = tid; e < 2048; e += 256) {
            const int t = e >> 5, i = e & 31;
            unsigned short uh, ul; split2(Um[t * 34 + i], uh, ul);
            const uint32_t off = (uint32_t)i * 144u
                + ((uint32_t)((t >> 3) ^ ((i >> 3) & 1)) << 4) + (t & 7) * 2;
            *(unsigned short*)(pUh + off) = uh;
            *(unsigned short*)(pUl + off) = ul;
        }
        __syncthreads();

        // ---- Phase C': O = QS + G @ U via mma ----
        {
            const int mb2 = wid >> 1, nh = wid & 1;
            const int t0r = mb2 * 16 + fr, t1r = t0r + 8;
            float du[2][4];
#pragma unroll
            for (int n8 = 0; n8 < 2; n8++) {
                const int i = nh * 16 + n8 * 8 + fc;
                float2 q0 = *(float2*)&QSm[t0r * 34 + i];
                float2 q1 = *(float2*)&QSm[t1r * 34 + i];
                du[n8][0] = q0.x; du[n8][1] = q0.y;
                du[n8][2] = q1.x; du[n8][3] = q1.y;
            }
#pragma unroll
            for (int p = 0; p < 3; p++) {
                const uint32_t aT = (p < 2) ? ghB : glB;
                const uint32_t bT = (p == 1) ? ulB : uhB;
#pragma unroll
                for (int k = 0; k < 4; k++) {
                    uint32_t a[4], bb[4];
                    {
                        const int r = mb2 * 16 + (lane & 15);
                        const int cc = k * 2 + (lane >> 4);
                        ldsm_x4(a, aT + r * 144u + ((uint32_t)(cc ^ ((r >> 3) & 1)) << 4));
                    }
                    {
                        const int rr = nh * 16 + (lane & 7) + ((lane >> 4) << 3);
                        const int cc = k * 2 + ((lane >> 3) & 1);
                        ldsm_x4(bb, bT + rr * 144u + ((uint32_t)(cc ^ ((rr >> 3) & 1)) << 4));
                    }
                    mma_bf16(du[0], a, bb[0], bb[1]);
                    mma_bf16(du[1], a, bb[2], bb[3]);
                }
            }
#pragma unroll
            for (int n8 = 0; n8 < 2; n8++) {
                const int i = nh * 16 + n8 * 8 + fc;
                *(float2*)&Od[(size_t)(r0g + t0r) * Dd + i0 + i] =
                    make_float2(du[n8][0], du[n8][1]);
                *(float2*)&Od[(size_t)(r0g + t1r) * Dd + i0 + i] =
                    make_float2(du[n8][2], du[n8][3]);
            }
        }

        // ---- Phase D: S += U^T @ K via mma ----
#pragma unroll 1
        for (int jt = 0; jt < 4; jt++) {
            __syncthreads();
#pragma unroll
            for (int n = 0; n < 8; n++) {
                const int e = tid + n * 256;
                const int t = e >> 5, d4 = (e & 31) * 4;
                const uint32_t off = (uint32_t)t * 272u
                    + ((uint32_t)((d4 >> 3) ^ ((t >> 3) & 1)) << 4) + (d4 & 7) * 2;
                const size_t g = (size_t)(r0g + t) * Dd + jt * 128 + d4;
                *(ull*)(pKh + off) = *(const ull*)&KhG[g];
                *(ull*)(pKl + off) = *(const ull*)&KlG[g];
            }
            __syncthreads();

            float cf[2][2][4];
            const int dbase = jt * 128 + wid * 16;
#pragma unroll
            for (int mi = 0; mi < 2; mi++)
#pragma unroll
                for (int n8 = 0; n8 < 2; n8++) {
                    const int i0r = mi * 16 + fr;
                    const int col = dbase + n8 * 8 + fc;
                    float2 x0 = *(float2*)&S[i0r * 520 + col];
                    float2 x1 = *(float2*)&S[(i0r + 8) * 520 + col];
                    cf[mi][n8][0] = x0.x; cf[mi][n8][1] = x0.y;
                    cf[mi][n8][2] = x1.x; cf[mi][n8][3] = x1.y;
                }
#pragma unroll
            for (int p = 0; p < 3; p++) {
                const uint32_t aT = (p < 2) ? uhB : ulB;
                const uint32_t bT = (p == 1) ? klB : khB;
#pragma unroll
                for (int k = 0; k < 4; k++) {
                    uint32_t a0[4], a1[4], bb[4];
                    {
                        const int r = lane & 15;
                        const int cc = k * 2 + (lane >> 4);
                        ldsm_x4(a0, aT + r * 144u + ((uint32_t)(cc ^ ((r >> 3) & 1)) << 4));
                        const int r2 = 16 + (lane & 15);
                        ldsm_x4(a1, aT + r2 * 144u + ((uint32_t)(cc ^ ((r2 >> 3) & 1)) << 4));
                    }
                    {
                        const int tr = k * 16 + (lane & 15);
                        const int cc = wid * 2 + (lane >> 4);
                        ldsm_x4t(bb, bT + tr * 272u + ((uint32_t)(cc ^ ((tr >> 3) & 1)) << 4));
                    }
                    mma_bf16(cf[0][0], a0, bb[0], bb[1]);
                    mma_bf16(cf[0][1], a0, bb[2], bb[3]);
                    mma_bf16(cf[1][0], a1, bb[0], bb[1]);
                    mma_bf16(cf[1][1], a1, bb[2], bb[3]);
                }
            }
#pragma unroll
            for (int mi = 0; mi < 2; mi++)
#pragma unroll
                for (int n8 = 0; n8 < 2; n8++) {
                    const int i0r = mi * 16 + fr;
                    const int col = dbase + n8 * 8 + fc;
                    *(float2*)&S[i0r * 520 + col] =
                        make_float2(cf[mi][n8][0], cf[mi][n8][1]);
                    *(float2*)&S[(i0r + 8) * 520 + col] =
                        make_float2(cf[mi][n8][2], cf[mi][n8][3]);
                }
        }
        __syncthreads();
    }
}

extern "C" void kernel_launch(void* const* d_in, const int* in_sizes, int n_in,
                              void* d_out, int out_size)
{
    const float* x     = (const float*)d_in[0];
    const float* Wq    = (const float*)d_in[1];
    const float* bq    = (const float*)d_in[2];
    const float* Wk    = (const float*)d_in[3];
    const float* bk    = (const float*)d_in[4];
    const float* Wv    = (const float*)d_in[5];
    const float* bv    = (const float*)d_in[6];
    const float* Wbeta = (const float*)d_in[7];
    const float* bbeta = (const float*)d_in[8];
    const float* Wo    = (const float*)d_in[9];
    const float* bo    = (const float*)d_in[10];
    float* out = (float*)d_out;

    float *pQ, *pK, *pV, *pO, *pBeta;
    cudaGetSymbolAddress((void**)&pQ, g_Q);
    cudaGetSymbolAddress((void**)&pK, g_K);
    cudaGetSymbolAddress((void**)&pV, g_V);
    cudaGetSymbolAddress((void**)&pO, g_O);
    cudaGetSymbolAddress((void**)&pBeta, g_Beta);

    __nv_bfloat16 *pxh, *pxl, *poh, *pol, *pkh, *pkl, *pqh, *pql;
    __nv_bfloat16 *pTh, *pTl, *pGh, *pGl;
    __nv_bfloat16 *pwqh, *pwql, *pwkh, *pwkl, *pwvh, *pwvl, *pwoh, *pwol;
    cudaGetSymbolAddress((void**)&pxh, g_xh);
    cudaGetSymbolAddress((void**)&pxl, g_xl);
    cudaGetSymbolAddress((void**)&poh, g_oh);
    cudaGetSymbolAddress((void**)&pol, g_ol);
    cudaGetSymbolAddress((void**)&pkh, g_kh);
    cudaGetSymbolAddress((void**)&pkl, g_kl);
    cudaGetSymbolAddress((void**)&pqh, g_qh);
    cudaGetSymbolAddress((void**)&pql, g_ql);
    cudaGetSymbolAddress((void**)&pTh, g_Th);
    cudaGetSymbolAddress((void**)&pTl, g_Tl);
    cudaGetSymbolAddress((void**)&pGh, g_Gh);
    cudaGetSymbolAddress((void**)&pGl, g_Gl);
    cudaGetSymbolAddress((void**)&pwqh, g_wqh);
    cudaGetSymbolAddress((void**)&pwql, g_wql);
    cudaGetSymbolAddress((void**)&pwkh, g_wkh);
    cudaGetSymbolAddress((void**)&pwkl, g_wkl);
    cudaGetSymbolAddress((void**)&pwvh, g_wvh);
    cudaGetSymbolAddress((void**)&pwvl, g_wvl);
    cudaGetSymbolAddress((void**)&pwoh, g_woh);
    cudaGetSymbolAddress((void**)&pwol, g_wol);

    cudaFuncSetAttribute(scan_kernel,
                         cudaFuncAttributeMaxDynamicSharedMemorySize, SCAN_SMEM);
    cudaFuncSetAttribute(tgemm_mma_kernel,
                         cudaFuncAttributeMaxDynamicSharedMemorySize, TG_SMEM);
    cudaFuncSetAttribute(tgemm_qkv_kernel,
                         cudaFuncAttributeMaxDynamicSharedMemorySize, TG_SMEM);
    cudaFuncSetAttribute(chunk_ag_mma_kernel,
                         cudaFuncAttributeMaxDynamicSharedMemorySize, AG_SMEM);

    const int nx4 = BT * Dd / 4;
    const int nw4 = Dd * Dd / 4;
    split_kernel<<<(nx4 + 255) / 256, 256>>>(x, pxh, pxl, nx4);
    split_kernel<<<(nw4 + 255) / 256, 256>>>(Wq, pwqh, pwql, nw4);
    split_kernel<<<(nw4 + 255) / 256, 256>>>(Wk, pwkh, pwkl, nw4);
    split_kernel<<<(nw4 + 255) / 256, 256>>>(Wv, pwvh, pwvl, nw4);
    split_kernel<<<(nw4 + 255) / 256, 256>>>(Wo, pwoh, pwol, nw4);

    tgemm_qkv_kernel<<<dim3(12, BT / 128), 256, TG_SMEM>>>(
        pxh, pxl, pwqh, pwql, pwkh, pwkl, pwvh, pwvl, bq, bk, bv, pQ, pK, pV);

    norm_beta_kernel<<<BT, 128>>>(pK, Wbeta, bbeta, pBeta);

    split_kernel<<<(nx4 + 255) / 256, 256>>>(pK, pkh, pkl, nx4);
    split_kernel<<<(nx4 + 255) / 256, 256>>>(pQ, pqh, pql, nx4);

    chunk_ag_mma_kernel<<<dim3(NCH, Bb), 256, AG_SMEM>>>(
        pkh, pkl, pqh, pql, pBeta, pTh, pTl, pGh, pGl);

    scan_kernel<<<dim3(NVT, Bb), 256, SCAN_SMEM>>>(
        pkh, pkl, pqh, pql, pTh, pTl, pGh, pGl, pV, pBeta, pO);

    split_kernel<<<(nx4 + 255) / 256, 256>>>(pO, poh, pol, nx4);
    tgemm_mma_kernel<<<dim3(4, BT / 128), 256, TG_SMEM>>>(
        poh, pol, pwoh, pwol, bo, out);
}

// round 12
// speedup vs baseline: 4.2401x; 1.0925x over previous
#include <cuda_runtime.h>
#include <cuda_bf16.h>
#include <math.h>
#include <stdint.h>

namespace {
constexpr int Bb  = 8;
constexpr int Tt  = 2048;
constexpr int Dd  = 512;
constexpr int BT  = Bb * Tt;
constexpr int CH  = 64;
constexpr int NCH = Tt / CH;   // 32
constexpr int DV  = 32;
constexpr int NVT = Dd / DV;   // 16

// ---- scan smem layout (byte offsets) ----
constexpr int OFF_S    = 0;              // float [32][520]
constexpr int OFF_UM   = 66560;          // float [64][34]
constexpr int OFF_QS   = 75264;          // float [64][34]
constexpr int OFF_VB   = 83968;          // float [64][34]
constexpr int OFF_BETA = 92672;          // float [64]
constexpr int OFF_KH   = 92928;          // bf16 [64][136]
constexpr int OFF_KL   = 110336;
constexpr int OFF_QH   = 127744;
constexpr int OFF_QL   = 145152;
constexpr int OFF_SH   = 162560;         // bf16 [32][136]
constexpr int OFF_SL   = 171264;
constexpr int OFF_UH   = 179968;         // bf16 [32][72]
constexpr int OFF_UL   = 184576;
constexpr int OFF_TH   = 189184;         // bf16 [64][72]
constexpr int OFF_TL   = 198400;
constexpr int OFF_GH   = 207616;         // bf16 [64][72]
constexpr int OFF_GL   = 216832;
constexpr int SCAN_SMEM = 226048;

// tgemm: 2 slots x (Ah|Al|Bh|Bl) each 128x40 halves = 10240 B
constexpr int TG_TILE  = 10240;
constexpr int TG_SLOT  = 4 * TG_TILE;          // 40960
constexpr int TG_SMEM  = 2 * TG_SLOT;          // 81920 -> 2 CTAs/SM

// chunk_ag smem
constexpr int AG_TILE  = 17408;
constexpr int AG_AS    = 4 * AG_TILE;          // 69632
constexpr int AG_TM    = AG_AS + 64 * 66 * 4;  // 86528
constexpr int AG_WS    = AG_TM + 64 * 66 * 4;  // 103424
constexpr int AG_SMEM  = AG_WS + 16 * 17 * 4;  // 104512
}

using ull = unsigned long long;

// ---------------- device scratch ----------------
__device__ float g_K[BT * Dd];
__device__ float g_V[BT * Dd];
__device__ float g_Beta[BT];
__device__ __nv_bfloat16 g_xh[BT * Dd];
__device__ __nv_bfloat16 g_xl[BT * Dd];
__device__ __nv_bfloat16 g_oh[BT * Dd];
__device__ __nv_bfloat16 g_ol[BT * Dd];
__device__ __nv_bfloat16 g_kh[BT * Dd];
__device__ __nv_bfloat16 g_kl[BT * Dd];
__device__ __nv_bfloat16 g_qh[BT * Dd];
__device__ __nv_bfloat16 g_ql[BT * Dd];
__device__ __nv_bfloat16 g_Th[Bb * NCH * CH * CH];
__device__ __nv_bfloat16 g_Tl[Bb * NCH * CH * CH];
__device__ __nv_bfloat16 g_Gh[Bb * NCH * CH * CH];
__device__ __nv_bfloat16 g_Gl[Bb * NCH * CH * CH];
__device__ __nv_bfloat16 g_wqh[Dd * Dd];
__device__ __nv_bfloat16 g_wql[Dd * Dd];
__device__ __nv_bfloat16 g_wkh[Dd * Dd];
__device__ __nv_bfloat16 g_wkl[Dd * Dd];
__device__ __nv_bfloat16 g_wvh[Dd * Dd];
__device__ __nv_bfloat16 g_wvl[Dd * Dd];
__device__ __nv_bfloat16 g_woh[Dd * Dd];
__device__ __nv_bfloat16 g_wol[Dd * Dd];

__device__ __forceinline__ uint32_t smem_u32(const void* p) {
    uint32_t a;
    asm("{ .reg .u64 t; cvta.to.shared.u64 t,%1; cvt.u32.u64 %0,t; }" : "=r"(a) : "l"(p));
    return a;
}
__device__ __forceinline__ void ldsm_x4(uint32_t* r, uint32_t addr) {
    asm volatile("ldmatrix.sync.aligned.m8n8.x4.shared.b16 {%0,%1,%2,%3}, [%4];"
                 : "=r"(r[0]), "=r"(r[1]), "=r"(r[2]), "=r"(r[3]) : "r"(addr));
}
__device__ __forceinline__ void ldsm_x4t(uint32_t* r, uint32_t addr) {
    asm volatile("ldmatrix.sync.aligned.m8n8.x4.trans.shared.b16 {%0,%1,%2,%3}, [%4];"
                 : "=r"(r[0]), "=r"(r[1]), "=r"(r[2]), "=r"(r[3]) : "r"(addr));
}
__device__ __forceinline__ void mma_bf16(float* d, const uint32_t* a,
                                         uint32_t b0, uint32_t b1) {
    asm volatile(
        "mma.sync.aligned.m16n8k16.row.col.f32.bf16.bf16.f32 "
        "{%0,%1,%2,%3}, {%4,%5,%6,%7}, {%8,%9}, {%0,%1,%2,%3};"
        : "+f"(d[0]), "+f"(d[1]), "+f"(d[2]), "+f"(d[3])
        : "r"(a[0]), "r"(a[1]), "r"(a[2]), "r"(a[3]), "r"(b0), "r"(b1));
}
__device__ __forceinline__ void cp16(uint32_t dst, const void* src) {
    asm volatile("cp.async.ca.shared.global [%0], [%1], 16;" :: "r"(dst), "l"(src));
}
__device__ __forceinline__ void split2(float x, unsigned short& h, unsigned short& l) {
    __nv_bfloat16 hh = __float2bfloat16(x);
    __nv_bfloat16 ll = __float2bfloat16(x - __bfloat162float(hh));
    h = __bfloat16_as_ushort(hh); l = __bfloat16_as_ushort(ll);
}
__device__ __forceinline__ void split4(float4 v, ull& h, ull& l) {
    unsigned short h0, h1, h2, h3, l0, l1, l2, l3;
    split2(v.x, h0, l0); split2(v.y, h1, l1);
    split2(v.z, h2, l2); split2(v.w, h3, l3);
    h = (ull)h0 | ((ull)h1 << 16) | ((ull)h2 << 32) | ((ull)h3 << 48);
    l = (ull)l0 | ((ull)l1 << 16) | ((ull)l2 << 32) | ((ull)l3 << 48);
}
__device__ __forceinline__ uint32_t pack2(float a, float b, bool hi) {
    unsigned short ha, la, hb, lb;
    split2(a, ha, la); split2(b, hb, lb);
    return hi ? ((uint32_t)ha | ((uint32_t)hb << 16))
              : ((uint32_t)la | ((uint32_t)lb << 16));
}

// ---------------- split fp32 -> bf16 hi/lo ----------------
__global__ __launch_bounds__(256) void split_kernel(
    const float* __restrict__ x, __nv_bfloat16* __restrict__ h,
    __nv_bfloat16* __restrict__ l, int n4)
{
    int i = blockIdx.x * 256 + threadIdx.x;
    if (i >= n4) return;
    float4 v = ((const float4*)x)[i];
    ull hw, lw; split4(v, hw, lw);
    ((ull*)h)[i] = hw;
    ((ull*)l)[i] = lw;
}

// ---------------- HMMA split-bf16 GEMM body (2-slot cp.async) ----------------
__device__ __forceinline__ void tgemm_body(
    const __nv_bfloat16* __restrict__ Ah, const __nv_bfloat16* __restrict__ Al,
    const __nv_bfloat16* __restrict__ Bh, const __nv_bfloat16* __restrict__ Bl,
    const float* __restrict__ bias, float* __restrict__ C,
    __nv_bfloat16* __restrict__ Ch, __nv_bfloat16* __restrict__ Cl,
    int bm, int bn, char* tgs)
{
    const uint32_t sBase = smem_u32(tgs);
    const int tid = threadIdx.x, lane = tid & 31, wid = tid >> 5;
    const int wm = wid & 1, wn = wid >> 1;

    float d[4][4][4];
#pragma unroll
    for (int mt = 0; mt < 4; mt++)
#pragma unroll
        for (int nt = 0; nt < 4; nt++)
#pragma unroll
            for (int e = 0; e < 4; e++) d[mt][nt][e] = 0.f;

    uint32_t a_rel[4], b_rel[2];
    {
        const int ar = lane & 15, akoff = (lane >> 4) * 8;
#pragma unroll
        for (int mt = 0; mt < 4; mt++)
            a_rel[mt] = ((wm * 64 + mt * 16 + ar) * 40 + akoff) * 2;
        const int nrow = wn * 32 + ((lane >> 4) << 3) + (lane & 7);
        const int khalf = (lane >> 3) & 1;
#pragma unroll
        for (int np = 0; np < 2; np++)
            b_rel[np] = ((nrow + np * 16) * 40 + khalf * 8) * 2;
    }

    const int srow0 = tid >> 2,         sc0 = tid & 3;
    const int srow1 = (tid + 256) >> 2, sc1 = (tid + 256) & 3;
    const uint32_t st0 = srow0 * 80 + sc0 * 16;
    const uint32_t st1 = srow1 * 80 + sc1 * 16;

    auto issue = [&](int kt, int slot) {
        const uint32_t b0 = sBase + slot * TG_SLOT;
        const size_t ga0 = (size_t)(bm + srow0) * Dd + kt * 32 + sc0 * 8;
        const size_t ga1 = (size_t)(bm + srow1) * Dd + kt * 32 + sc1 * 8;
        const size_t gb0 = (size_t)(bn + srow0) * Dd + kt * 32 + sc0 * 8;
        const size_t gb1 = (size_t)(bn + srow1) * Dd + kt * 32 + sc1 * 8;
        cp16(b0 + st0,               Ah + ga0);
        cp16(b0 + st1,               Ah + ga1);
        cp16(b0 + TG_TILE + st0,     Al + ga0);
        cp16(b0 + TG_TILE + st1,     Al + ga1);
        cp16(b0 + 2 * TG_TILE + st0, Bh + gb0);
        cp16(b0 + 2 * TG_TILE + st1, Bh + gb1);
        cp16(b0 + 3 * TG_TILE + st0, Bl + gb0);
        cp16(b0 + 3 * TG_TILE + st1, Bl + gb1);
        asm volatile("cp.async.commit_group;");
    };

    issue(0, 0);
#pragma unroll 1
    for (int s = 0; s < 16; s++) {
        if (s + 1 < 16) {
            issue(s + 1, (s + 1) & 1);
            asm volatile("cp.async.wait_group 1;");
        } else {
            asm volatile("cp.async.wait_group 0;");
        }
        __syncthreads();
        const uint32_t slotB = sBase + (s & 1) * TG_SLOT;
#pragma unroll
        for (int p = 0; p < 3; p++) {
            const uint32_t aO = slotB + (p == 2 ? TG_TILE : 0);
            const uint32_t bO = slotB + 2 * TG_TILE + (p == 1 ? TG_TILE : 0);
#pragma unroll
            for (int ks = 0; ks < 2; ks++) {
                uint32_t a[4][4], b[2][4];
#pragma unroll
                for (int mt = 0; mt < 4; mt++) ldsm_x4(a[mt], aO + a_rel[mt] + ks * 32);
#pragma unroll
                for (int np = 0; np < 2; np++) ldsm_x4(b[np], bO + b_rel[np] + ks * 32);
#pragma unroll
                for (int mt = 0; mt < 4; mt++)
#pragma unroll
                    for (int nt = 0; nt < 4; nt++)
                        mma_bf16(d[mt][nt], a[mt],
                                 b[nt >> 1][(nt & 1) * 2], b[nt >> 1][(nt & 1) * 2 + 1]);
            }
        }
        __syncthreads();
    }

#pragma unroll
    for (int mt = 0; mt < 4; mt++) {
        const int r0 = bm + wm * 64 + mt * 16 + (lane >> 2);
#pragma unroll
        for (int nt = 0; nt < 4; nt++) {
            const int c0 = bn + wn * 32 + nt * 8 + (lane & 3) * 2;
            const float b0 = bias[c0], b1 = bias[c0 + 1];
            const float o00 = d[mt][nt][0] + b0, o01 = d[mt][nt][1] + b1;
            const float o10 = d[mt][nt][2] + b0, o11 = d[mt][nt][3] + b1;
            if (C) {
                *(float2*)&C[(size_t)r0 * Dd + c0] = make_float2(o00, o01);
                *(float2*)&C[(size_t)(r0 + 8) * Dd + c0] = make_float2(o10, o11);
            } else {
                unsigned short* ch = (unsigned short*)Ch;
                unsigned short* cl = (unsigned short*)Cl;
                *(uint32_t*)&ch[(size_t)r0 * Dd + c0] = pack2(o00, o01, true);
                *(uint32_t*)&cl[(size_t)r0 * Dd + c0] = pack2(o00, o01, false);
                *(uint32_t*)&ch[(size_t)(r0 + 8) * Dd + c0] = pack2(o10, o11, true);
                *(uint32_t*)&cl[(size_t)(r0 + 8) * Dd + c0] = pack2(o10, o11, false);
            }
        }
    }
}

__global__ __launch_bounds__(256, 2) void tgemm_mma_kernel(
    const __nv_bfloat16* __restrict__ Ah, const __nv_bfloat16* __restrict__ Al,
    const __nv_bfloat16* __restrict__ Bh, const __nv_bfloat16* __restrict__ Bl,
    const float* __restrict__ bias, float* __restrict__ C)
{
    extern __shared__ char tgs[];
    tgemm_body(Ah, Al, Bh, Bl, bias, C, nullptr, nullptr,
               blockIdx.y * 128, blockIdx.x * 128, tgs);
}

__global__ __launch_bounds__(256, 2) void tgemm_qkv_kernel(
    const __nv_bfloat16* __restrict__ Ah, const __nv_bfloat16* __restrict__ Al,
    const __nv_bfloat16* __restrict__ Bqh, const __nv_bfloat16* __restrict__ Bql,
    const __nv_bfloat16* __restrict__ Bkh, const __nv_bfloat16* __restrict__ Bkl,
    const __nv_bfloat16* __restrict__ Bvh, const __nv_bfloat16* __restrict__ Bvl,
    const float* __restrict__ bq, const float* __restrict__ bk,
    const float* __restrict__ bv,
    __nv_bfloat16* __restrict__ Qh, __nv_bfloat16* __restrict__ Ql,
    float* __restrict__ Ck, float* __restrict__ Cv)
{
    extern __shared__ char tgs[];
    const int gsel = blockIdx.x >> 2;
    const int bn = (blockIdx.x & 3) * 128;
    const __nv_bfloat16* Bh = (gsel == 0) ? Bqh : (gsel == 1) ? Bkh : Bvh;
    const __nv_bfloat16* Bl = (gsel == 0) ? Bql : (gsel == 1) ? Bkl : Bvl;
    const float* bias = (gsel == 0) ? bq : (gsel == 1) ? bk : bv;
    float* C = (gsel == 0) ? nullptr : (gsel == 1) ? Ck : Cv;
    tgemm_body(Ah, Al, Bh, Bl, bias, C,
               (gsel == 0) ? Qh : nullptr, (gsel == 0) ? Ql : nullptr,
               blockIdx.y * 128, bn, tgs);
}

// ---------------- l2norm + beta -> split K directly ----------------
__global__ __launch_bounds__(128) void norm_beta_kernel(
    const float* __restrict__ Kd, const float* __restrict__ wb,
    const float* __restrict__ bb, float* __restrict__ Beta,
    __nv_bfloat16* __restrict__ Kh, __nv_bfloat16* __restrict__ Kl)
{
    const int row = blockIdx.x, tid = threadIdx.x;
    float4 v = ((const float4*)(Kd + (size_t)row * Dd))[tid];
    float ss = v.x * v.x + v.y * v.y + v.z * v.z + v.w * v.w;
#pragma unroll
    for (int o = 16; o; o >>= 1) ss += __shfl_xor_sync(0xffffffffu, ss, o);
    __shared__ float red1[4];
    if ((tid & 31) == 0) red1[tid >> 5] = ss;
    __syncthreads();
    const float inv = 1.0f / fmaxf(sqrtf(red1[0] + red1[1] + red1[2] + red1[3]), 1e-12f);
    float4 w = ((const float4*)wb)[tid];
    float bd = v.x * w.x + v.y * w.y + v.z * w.z + v.w * w.w;
#pragma unroll
    for (int o = 16; o; o >>= 1) bd += __shfl_xor_sync(0xffffffffu, bd, o);
    __shared__ float red2[4];
    if ((tid & 31) == 0) red2[tid >> 5] = bd;
    __syncthreads();
    v.x *= inv; v.y *= inv; v.z *= inv; v.w *= inv;
    ull hw, lw; split4(v, hw, lw);
    ((ull*)(Kh + (size_t)row * Dd))[tid] = hw;
    ((ull*)(Kl + (size_t)row * Dd))[tid] = lw;
    if (tid == 0) {
        const float z = (red2[0] + red2[1] + red2[2] + red2[3]) * inv + bb[0];
        Beta[row] = 1.0f / (1.0f + expf(-z));
    }
}

// ---------------- chunk_ag: A,G via mma + T = (I+A)^-1 ----------------
__global__ __launch_bounds__(256) void chunk_ag_mma_kernel(
    const __nv_bfloat16* __restrict__ KhG, const __nv_bfloat16* __restrict__ KlG,
    const __nv_bfloat16* __restrict__ QhG, const __nv_bfloat16* __restrict__ QlG,
    const float* __restrict__ Betad,
    __nv_bfloat16* __restrict__ ThG, __nv_bfloat16* __restrict__ TlG,
    __nv_bfloat16* __restrict__ GhG, __nv_bfloat16* __restrict__ GlG)
{
    extern __shared__ char ags[];
    char* pKh = ags;               char* pKl = ags + AG_TILE;
    char* pQh = ags + 2 * AG_TILE; char* pQl = ags + 3 * AG_TILE;
    float* As = (float*)(ags + AG_AS);
    float* Tm = (float*)(ags + AG_TM);
    float* Ws = (float*)(ags + AG_WS);
    const uint32_t khB = smem_u32(pKh), klB = smem_u32(pKl);
    const uint32_t qhB = smem_u32(pQh), qlB = smem_u32(pQl);

    const int c = blockIdx.x, b = blockIdx.y;
    const int r0g = b * Tt + c * CH;
    const int tid = threadIdx.x, lane = tid & 31, wid = tid >> 5;
    const int mat = wid >> 2, mb = wid & 3;
    const int fr = lane >> 2, fc = 2 * (lane & 3);

    float cacc[8][4];
#pragma unroll
    for (int nb = 0; nb < 8; nb++)
#pragma unroll
        for (int e = 0; e < 4; e++) cacc[nb][e] = 0.f;

#pragma unroll 1
    for (int jt = 0; jt < 4; jt++) {
        if (jt) __syncthreads();
#pragma unroll
        for (int n = 0; n < 4; n++) {
            const int e = tid + n * 256;
            const int t = e >> 4, cc = e & 15;
            const uint32_t off = (uint32_t)t * 272u
                + ((uint32_t)(cc ^ ((t >> 3) & 1)) << 4);
            const size_t g = (size_t)(r0g + t) * Dd + jt * 128 + cc * 8;
            cp16(khB + off, KhG + g);
            cp16(klB + off, KlG + g);
            cp16(qhB + off, QhG + g);
            cp16(qlB + off, QlG + g);
        }
        asm volatile("cp.async.commit_group;");
        asm volatile("cp.async.wait_group 0;");
        __syncthreads();
#pragma unroll
        for (int p = 0; p < 3; p++) {
            const uint32_t aT = mat ? (p < 2 ? qhB : qlB) : (p < 2 ? khB : klB);
            const uint32_t bT = (p == 1) ? klB : khB;
#pragma unroll
            for (int k = 0; k < 8; k++) {
                uint32_t a[4];
                {
                    const int r = mb * 16 + (lane & 15);
                    const int cc = k * 2 + (lane >> 4);
                    ldsm_x4(a, aT + r * 272u + ((uint32_t)(cc ^ ((r >> 3) & 1)) << 4));
                }
#pragma unroll
                for (int nb4 = 0; nb4 < 4; nb4++) {
                    uint32_t bb[4];
                    const int r = nb4 * 16 + (lane & 7) + ((lane >> 4) << 3);
                    const int cc = k * 2 + ((lane >> 3) & 1);
                    ldsm_x4(bb, bT + r * 272u + ((uint32_t)(cc ^ ((r >> 3) & 1)) << 4));
                    mma_bf16(cacc[nb4 * 2 + 0], a, bb[0], bb[1]);
                    mma_bf16(cacc[nb4 * 2 + 1], a, bb[2], bb[3]);
                }
            }
        }
    }
    __syncthreads();

    const size_t gbase = ((size_t)(b * NCH) + c) * (CH * CH);
    const int t0r = mb * 16 + fr, t1r = t0r + 8;
    if (mat == 0) {
        const float bt0 = Betad[r0g + t0r], bt1 = Betad[r0g + t1r];
#pragma unroll
        for (int nb = 0; nb < 8; nb++) {
            const int j = nb * 8 + fc;
            float2 o0, o1;
            o0.x = (j     < t0r) ? bt0 * cacc[nb][0] : 0.f;
            o0.y = (j + 1 < t0r) ? bt0 * cacc[nb][1] : 0.f;
            o1.x = (j     < t1r) ? bt1 * cacc[nb][2] : 0.f;
            o1.y = (j + 1 < t1r) ? bt1 * cacc[nb][3] : 0.f;
            *(float2*)&As[t0r * 66 + j] = o0;
            *(float2*)&As[t1r * 66 + j] = o1;
        }
    } else {
        unsigned short* Gh = (unsigned short*)GhG;
        unsigned short* Gl = (unsigned short*)GlG;
#pragma unroll
        for (int nb = 0; nb < 8; nb++) {
            const int j = nb * 8 + fc;
            float v00 = (j     <= t0r) ? cacc[nb][0] : 0.f;
            float v01 = (j + 1 <= t0r) ? cacc[nb][1] : 0.f;
            float v10 = (j     <= t1r) ? cacc[nb][2] : 0.f;
            float v11 = (j + 1 <= t1r) ? cacc[nb][3] : 0.f;
            *(uint32_t*)&Gh[gbase + t0r * 64 + j] = pack2(v00, v01, true);
            *(uint32_t*)&Gl[gbase + t0r * 64 + j] = pack2(v00, v01, false);
            *(uint32_t*)&Gh[gbase + t1r * 64 + j] = pack2(v10, v11, true);
            *(uint32_t*)&Gl[gbase + t1r * 64 + j] = pack2(v10, v11, false);
        }
    }
    for (int e = tid; e < 64 * 66; e += 256) Tm[e] = 0.f;
    __syncthreads();

    // diagonal 16x16 inversions
    if (wid < 4) {
        const int r = lane & 15;
        float Lr[16], val[16];
#pragma unroll
        for (int j = 0; j < 16; j++) Lr[j] = As[(wid * 16 + r) * 66 + wid * 16 + j];
#pragma unroll
        for (int cc = 0; cc < 16; cc++) val[cc] = (r == cc) ? 1.f : 0.f;
#pragma unroll
        for (int j = 0; j < 15; j++) {
#pragma unroll
            for (int cc = 0; cc < 16; cc++) {
                if (cc <= j) {
                    float tjc = __shfl_sync(0xffffffffu, val[cc], j);
                    if (r > j) val[cc] -= Lr[j] * tjc;
                }
            }
        }
        if (lane < 16) {
#pragma unroll
            for (int cc = 0; cc < 16; cc++)
                Tm[(wid * 16 + r) * 66 + wid * 16 + cc] = val[cc];
        }
    }
    __syncthreads();

    // off-diagonal blocks
    {
        const int oi[6] = {1, 2, 3, 2, 3, 3};
        const int oj[6] = {0, 0, 0, 1, 1, 2};
        const int r = tid >> 4, cc = tid & 15;
#pragma unroll 1
        for (int s6 = 0; s6 < 6; s6++) {
            const int bi = oi[s6], bj = oj[s6];
            float w = 0.f;
            for (int k = bj; k < bi; k++)
#pragma unroll
                for (int m = 0; m < 16; m++)
                    w += As[(bi * 16 + r) * 66 + k * 16 + m] *
                         Tm[(k * 16 + m) * 66 + bj * 16 + cc];
            Ws[r * 17 + cc] = w;
            __syncthreads();
            float t2 = 0.f;
#pragma unroll
            for (int m = 0; m < 16; m++)
                t2 += Tm[(bi * 16 + r) * 66 + bi * 16 + m] * Ws[m * 17 + cc];
            Tm[(bi * 16 + r) * 66 + bj * 16 + cc] = -t2;
            __syncthreads();
        }
    }

    {
        unsigned short* Th = (unsigned short*)ThG;
        unsigned short* Tl = (unsigned short*)TlG;
        for (int e = tid; e < 2048; e += 256) {
            const int t = e >> 5, j = (e & 31) * 2;
            *(uint32_t*)&Th[gbase + t * 64 + j] =
                pack2(Tm[t * 66 + j], Tm[t * 66 + j + 1], true);
            *(uint32_t*)&Tl[gbase + t * 64 + j] =
                pack2(Tm[t * 66 + j], Tm[t * 66 + j + 1], false);
        }
    }
}

// ---------------- chunked delta-rule scan: all-mma ----------------
__global__ __launch_bounds__(256) void scan_kernel(
    const __nv_bfloat16* __restrict__ KhG, const __nv_bfloat16* __restrict__ KlG,
    const __nv_bfloat16* __restrict__ QhG, const __nv_bfloat16* __restrict__ QlG,
    const __nv_bfloat16* __restrict__ ThG, const __nv_bfloat16* __restrict__ TlG,
    const __nv_bfloat16* __restrict__ GhG, const __nv_bfloat16* __restrict__ GlG,
    const float* __restrict__ Vd, const float* __restrict__ Betad,
    __nv_bfloat16* __restrict__ OhG, __nv_bfloat16* __restrict__ OlG)
{
    extern __shared__ char sraw[];
    float* S     = (float*)(sraw + OFF_S);
    float* Um    = (float*)(sraw + OFF_UM);
    float* QSm   = (float*)(sraw + OFF_QS);
    float* Vb    = (float*)(sraw + OFF_VB);
    float* betas = (float*)(sraw + OFF_BETA);
    char* pKh = sraw + OFF_KH;  char* pKl = sraw + OFF_KL;
    char* pQh = sraw + OFF_QH;  char* pQl = sraw + OFF_QL;
    char* pSh = sraw + OFF_SH;  char* pSl = sraw + OFF_SL;
    char* pUh = sraw + OFF_UH;  char* pUl = sraw + OFF_UL;
    char* pTh = sraw + OFF_TH;  char* pTl = sraw + OFF_TL;
    char* pGh = sraw + OFF_GH;  char* pGl = sraw + OFF_GL;
    const uint32_t khB = smem_u32(pKh), klB = smem_u32(pKl);
    const uint32_t qhB = smem_u32(pQh), qlB = smem_u32(pQl);
    const uint32_t shB = smem_u32(pSh), slB = smem_u32(pSl);
    const uint32_t uhB = smem_u32(pUh), ulB = smem_u32(pUl);
    const uint32_t thB = smem_u32(pTh), tlB = smem_u32(pTl);
    const uint32_t ghB = smem_u32(pGh), glB = smem_u32(pGl);

    const int b = blockIdx.y;
    const int i0 = blockIdx.x * DV;
    const int tid = threadIdx.x;
    const int lane = tid & 31, wid = tid >> 5;
    const int fr = lane >> 2, fc = 2 * (lane & 3);

    for (int e = tid; e < 32 * 520; e += 256) S[e] = 0.f;
    __syncthreads();

    for (int c = 0; c < NCH; c++) {
        const int r0g = b * Tt + c * CH;
        const size_t gbase = ((size_t)(b * NCH) + c) * (CH * CH);

        // stage T/G via cp.async; V, beta scalar
#pragma unroll
        for (int n = 0; n < 2; n++) {
            const int e = tid + n * 256;
            const int r = e >> 3, cc = e & 7;
            const uint32_t off = (uint32_t)r * 144u
                + ((uint32_t)(cc ^ ((r >> 3) & 1)) << 4);
            const size_t g = gbase + r * 64 + cc * 8;
            cp16(thB + off, ThG + g);
            cp16(tlB + off, TlG + g);
            cp16(ghB + off, GhG + g);
            cp16(glB + off, GlG + g);
        }
        asm volatile("cp.async.commit_group;");
        for (int e = tid; e < CH * DV; e += 256) {
            const int t = e >> 5, i = e & 31;
            Vb[t * 34 + i] = Vd[(size_t)(r0g + t) * Dd + i0 + i];
        }
        if (tid < 64) betas[tid] = Betad[r0g + tid];
        asm volatile("cp.async.wait_group 0;");
        __syncthreads();

        // ---- Phase A ----
        const int mat = wid >> 2;
        const int mb  = wid & 3;
        float cacc[4][4];
#pragma unroll
        for (int nb = 0; nb < 4; nb++)
#pragma unroll
            for (int e = 0; e < 4; e++) cacc[nb][e] = 0.f;

#pragma unroll 1
        for (int jt = 0; jt < 4; jt++) {
#pragma unroll
            for (int n = 0; n < 4; n++) {
                const int e = tid + n * 256;
                const int t = e >> 4, cc = e & 15;
                const uint32_t off = (uint32_t)t * 272u
                    + ((uint32_t)(cc ^ ((t >> 3) & 1)) << 4);
                const size_t g = (size_t)(r0g + t) * Dd + jt * 128 + cc * 8;
                cp16(khB + off, KhG + g);
                cp16(klB + off, KlG + g);
                cp16(qhB + off, QhG + g);
                cp16(qlB + off, QlG + g);
            }
            asm volatile("cp.async.commit_group;");
#pragma unroll
            for (int n = 0; n < 4; n++) {
                const int e = tid + n * 256;
                const int i = e >> 5, d4 = (e & 31) * 4;
                float4 v = *(const float4*)&S[i * 520 + jt * 128 + d4];
                ull hw, lw; split4(v, hw, lw);
                const uint32_t off = (uint32_t)i * 272u
                    + ((uint32_t)((d4 >> 3) ^ ((i >> 3) & 1)) << 4) + (d4 & 7) * 2;
                *(ull*)(pSh + off) = hw;
                *(ull*)(pSl + off) = lw;
            }
            asm volatile("cp.async.wait_group 0;");
            __syncthreads();
#pragma unroll
            for (int p = 0; p < 3; p++) {
                const uint32_t aT = mat ? (p < 2 ? qhB : qlB) : (p < 2 ? khB : klB);
                const uint32_t bT = (p == 1) ? slB : shB;
#pragma unroll
                for (int k = 0; k < 8; k++) {
                    uint32_t a[4], b0[4], b1[4];
                    {
                        const int r = mb * 16 + (lane & 15);
                        const int cc = k * 2 + (lane >> 4);
                        ldsm_x4(a, aT + r * 272u + ((uint32_t)(cc ^ ((r >> 3) & 1)) << 4));
                    }
                    {
                        const int r = (lane & 7) + ((lane >> 4) << 3);
                        const int cc = k * 2 + ((lane >> 3) & 1);
                        ldsm_x4(b0, bT + r * 272u + ((uint32_t)(cc ^ ((r >> 3) & 1)) << 4));
                        const int r2 = r + 16;
                        ldsm_x4(b1, bT + r2 * 272u + ((uint32_t)(cc ^ ((r2 >> 3) & 1)) << 4));
                    }
                    mma_bf16(cacc[0], a, b0[0], b0[1]);
                    mma_bf16(cacc[1], a, b0[2], b0[3]);
                    mma_bf16(cacc[2], a, b1[0], b1[1]);
                    mma_bf16(cacc[3], a, b1[2], b1[3]);
                }
            }
            __syncthreads();
        }

        {
            const int t0r = mb * 16 + fr, t1r = t0r + 8;
            if (mat == 0) {
                const float b0v = betas[t0r], b1v = betas[t1r];
#pragma unroll
                for (int nb = 0; nb < 4; nb++) {
                    const int i = nb * 8 + fc;
                    float2 v0 = *(float2*)&Vb[t0r * 34 + i];
                    float2 v1 = *(float2*)&Vb[t1r * 34 + i];
                    *(float2*)&Um[t0r * 34 + i] =
                        make_float2(b0v * (v0.x - cacc[nb][0]), b0v * (v0.y - cacc[nb][1]));
                    *(float2*)&Um[t1r * 34 + i] =
                        make_float2(b1v * (v1.x - cacc[nb][2]), b1v * (v1.y - cacc[nb][3]));
                }
            } else {
#pragma unroll
                for (int nb = 0; nb < 4; nb++) {
                    const int i = nb * 8 + fc;
                    *(float2*)&QSm[t0r * 34 + i] = make_float2(cacc[nb][0], cacc[nb][1]);
                    *(float2*)&QSm[t1r * 34 + i] = make_float2(cacc[nb][2], cacc[nb][3]);
                }
            }
        }
        __syncthreads();

        // split rhs -> UH/UL transposed
        for (int e = tid; e < 2048; e += 256) {
            const int t = e >> 5, i = e & 31;
            unsigned short uh, ul; split2(Um[t * 34 + i], uh, ul);
            const uint32_t off = (uint32_t)i * 144u
                + ((uint32_t)((t >> 3) ^ ((i >> 3) & 1)) << 4) + (t & 7) * 2;
            *(unsigned short*)(pUh + off) = uh;
            *(unsigned short*)(pUl + off) = ul;
        }
        __syncthreads();

        // Phase B': U = T @ rhs
        {
            const int mb2 = wid >> 1, nh = wid & 1;
            float du[2][4];
#pragma unroll
            for (int n8 = 0; n8 < 2; n8++)
#pragma unroll
                for (int e = 0; e < 4; e++) du[n8][e] = 0.f;
#pragma unroll
            for (int p = 0; p < 3; p++) {
                const uint32_t aT = (p < 2) ? thB : tlB;
                const uint32_t bT = (p == 1) ? ulB : uhB;
#pragma unroll
                for (int k = 0; k < 4; k++) {
                    uint32_t a[4], bb[4];
                    {
                        const int r = mb2 * 16 + (lane & 15);
                        const int cc = k * 2 + (lane >> 4);
                        ldsm_x4(a, aT + r * 144u + ((uint32_t)(cc ^ ((r >> 3) & 1)) << 4));
                    }
                    {
                        const int rr = nh * 16 + (lane & 7) + ((lane >> 4) << 3);
                        const int cc = k * 2 + ((lane >> 3) & 1);
                        ldsm_x4(bb, bT + rr * 144u + ((uint32_t)(cc ^ ((rr >> 3) & 1)) << 4));
                    }
                    mma_bf16(du[0], a, bb[0], bb[1]);
                    mma_bf16(du[1], a, bb[2], bb[3]);
                }
            }
            __syncthreads();
            const int t0r = mb2 * 16 + fr, t1r = t0r + 8;
#pragma unroll
            for (int n8 = 0; n8 < 2; n8++) {
                const int i = nh * 16 + n8 * 8 + fc;
                *(float2*)&Um[t0r * 34 + i] = make_float2(du[n8][0], du[n8][1]);
                *(float2*)&Um[t1r * 34 + i] = make_float2(du[n8][2], du[n8][3]);
            }
        }
        __syncthreads();

        // split U -> UH/UL transposed
        for (int e = tid; e < 2048; e += 256) {
            const int t = e >> 5, i = e & 31;
            unsigned short uh, ul; split2(Um[t * 34 + i], uh, ul);
            const uint32_t off = (uint32_t)i * 144u
                + ((uint32_t)((t >> 3) ^ ((i >> 3) & 1)) << 4) + (t & 7) * 2;
            *(unsigned short*)(pUh + off) = uh;
            *(unsigned short*)(pUl + off) = ul;
        }
        __syncthreads();

        // Phase C': O = QS + G @ U (write split bf16 output)
        {
            const int mb2 = wid >> 1, nh = wid & 1;
            const int t0r = mb2 * 16 + fr, t1r = t0r + 8;
            float du[2][4];
#pragma unroll
            for (int n8 = 0; n8 < 2; n8++) {
                const int i = nh * 16 + n8 * 8 + fc;
                float2 q0 = *(float2*)&QSm[t0r * 34 + i];
                float2 q1 = *(float2*)&QSm[t1r * 34 + i];
                du[n8][0] = q0.x; du[n8][1] = q0.y;
                du[n8][2] = q1.x; du[n8][3] = q1.y;
            }
#pragma unroll
            for (int p = 0; p < 3; p++) {
                const uint32_t aT = (p < 2) ? ghB : glB;
                const uint32_t bT = (p == 1) ? ulB : uhB;
#pragma unroll
                for (int k = 0; k < 4; k++) {
                    uint32_t a[4], bb[4];
                    {
                        const int r = mb2 * 16 + (lane & 15);
                        const int cc = k * 2 + (lane >> 4);
                        ldsm_x4(a, aT + r * 144u + ((uint32_t)(cc ^ ((r >> 3) & 1)) << 4));
                    }
                    {
                        const int rr = nh * 16 + (lane & 7) + ((lane >> 4) << 3);
                        const int cc = k * 2 + ((lane >> 3) & 1);
                        ldsm_x4(bb, bT + rr * 144u + ((uint32_t)(cc ^ ((rr >> 3) & 1)) << 4));
                    }
                    mma_bf16(du[0], a, bb[0], bb[1]);
                    mma_bf16(du[1], a, bb[2], bb[3]);
                }
            }
            unsigned short* oh = (unsigned short*)OhG;
            unsigned short* ol = (unsigned short*)OlG;
#pragma unroll
            for (int n8 = 0; n8 < 2; n8++) {
                const int i = nh * 16 + n8 * 8 + fc;
                const size_t g0 = (size_t)(r0g + t0r) * Dd + i0 + i;
                const size_t g1 = (size_t)(r0g + t1r) * Dd + i0 + i;
                *(uint32_t*)&oh[g0] = pack2(du[n8][0], du[n8][1], true);
                *(uint32_t*)&ol[g0] = pack2(du[n8][0], du[n8][1], false);
                *(uint32_t*)&oh[g1] = pack2(du[n8][2], du[n8][3], true);
                *(uint32_t*)&ol[g1] = pack2(du[n8][2], du[n8][3], false);
            }
        }

        // Phase D: S += U^T @ K
#pragma unroll 1
        for (int jt = 0; jt < 4; jt++) {
            __syncthreads();
#pragma unroll
            for (int n = 0; n < 4; n++) {
                const int e = tid + n * 256;          // 1024 chunks each array
                const int t = e >> 4, cc = e & 15;
                const uint32_t off = (uint32_t)t * 272u
                    + ((uint32_t)(cc ^ ((t >> 3) & 1)) << 4);
                const size_t g = (size_t)(r0g + t) * Dd + jt * 128 + cc * 8;
                cp16(khB + off, KhG + g);
                cp16(klB + off, KlG + g);
            }
            asm volatile("cp.async.commit_group;");
            asm volatile("cp.async.wait_group 0;");
            __syncthreads();

            float cf[2][2][4];
            const int dbase = jt * 128 + wid * 16;
#pragma unroll
            for (int mi = 0; mi < 2; mi++)
#pragma unroll
                for (int n8 = 0; n8 < 2; n8++) {
                    const int i0r = mi * 16 + fr;
                    const int col = dbase + n8 * 8 + fc;
                    float2 x0 = *(float2*)&S[i0r * 520 + col];
                    float2 x1 = *(float2*)&S[(i0r + 8) * 520 + col];
                    cf[mi][n8][0] = x0.x; cf[mi][n8][1] = x0.y;
                    cf[mi][n8][2] = x1.x; cf[mi][n8][3] = x1.y;
                }
#pragma unroll
            for (int p = 0; p < 3; p++) {
                const uint32_t aT = (p < 2) ? uhB : ulB;
                const uint32_t bT = (p == 1) ? klB : khB;
#pragma unroll
                for (int k = 0; k < 4; k++) {
                    uint32_t a0[4], a1[4], bb[4];
                    {
                        const int r = lane & 15;
                        const int cc = k * 2 + (lane >> 4);
                        ldsm_x4(a0, aT + r * 144u + ((uint32_t)(cc ^ ((r >> 3) & 1)) << 4));
                        const int r2 = 16 + (lane & 15);
                        ldsm_x4(a1, aT + r2 * 144u + ((uint32_t)(cc ^ ((r2 >> 3) & 1)) << 4));
                    }
                    {
                        const int tr = k * 16 + (lane & 15);
                        const int cc = wid * 2 + (lane >> 4);
                        ldsm_x4t(bb, bT + tr * 272u + ((uint32_t)(cc ^ ((tr >> 3) & 1)) << 4));
                    }
                    mma_bf16(cf[0][0], a0, bb[0], bb[1]);
                    mma_bf16(cf[0][1], a0, bb[2], bb[3]);
                    mma_bf16(cf[1][0], a1, bb[0], bb[1]);
                    mma_bf16(cf[1][1], a1, bb[2], bb[3]);
                }
            }
#pragma unroll
            for (int mi = 0; mi < 2; mi++)
#pragma unroll
                for (int n8 = 0; n8 < 2; n8++) {
                    const int i0r = mi * 16 + fr;
                    const int col = dbase + n8 * 8 + fc;
                    *(float2*)&S[i0r * 520 + col] =
                        make_float2(cf[mi][n8][0], cf[mi][n8][1]);
                    *(float2*)&S[(i0r + 8) * 520 + col] =
                        make_float2(cf[mi][n8][2], cf[mi][n8][3]);
                }
        }
        __syncthreads();
    }
}

extern "C" void kernel_launch(void* const* d_in, const int* in_sizes, int n_in,
                              void* d_out, int out_size)
{
    const float* x     = (const float*)d_in[0];
    const float* Wq    = (const float*)d_in[1];
    const float* bq    = (const float*)d_in[2];
    const float* Wk    = (const float*)d_in[3];
    const float* bk    = (const float*)d_in[4];
    const float* Wv    = (const float*)d_in[5];
    const float* bv    = (const float*)d_in[6];
    const float* Wbeta = (const float*)d_in[7];
    const float* bbeta = (const float*)d_in[8];
    const float* Wo    = (const float*)d_in[9];
    const float* bo    = (const float*)d_in[10];
    float* out = (float*)d_out;

    float *pK, *pV, *pBeta;
    cudaGetSymbolAddress((void**)&pK, g_K);
    cudaGetSymbolAddress((void**)&pV, g_V);
    cudaGetSymbolAddress((void**)&pBeta, g_Beta);

    __nv_bfloat16 *pxh, *pxl, *poh, *pol, *pkh, *pkl, *pqh, *pql;
    __nv_bfloat16 *pTh, *pTl, *pGh, *pGl;
    __nv_bfloat16 *pwqh, *pwql, *pwkh, *pwkl, *pwvh, *pwvl, *pwoh, *pwol;
    cudaGetSymbolAddress((void**)&pxh, g_xh);
    cudaGetSymbolAddress((void**)&pxl, g_xl);
    cudaGetSymbolAddress((void**)&poh, g_oh);
    cudaGetSymbolAddress((void**)&pol, g_ol);
    cudaGetSymbolAddress((void**)&pkh, g_kh);
    cudaGetSymbolAddress((void**)&pkl, g_kl);
    cudaGetSymbolAddress((void**)&pqh, g_qh);
    cudaGetSymbolAddress((void**)&pql, g_ql);
    cudaGetSymbolAddress((void**)&pTh, g_Th);
    cudaGetSymbolAddress((void**)&pTl, g_Tl);
    cudaGetSymbolAddress((void**)&pGh, g_Gh);
    cudaGetSymbolAddress((void**)&pGl, g_Gl);
    cudaGetSymbolAddress((void**)&pwqh, g_wqh);
    cudaGetSymbolAddress((void**)&pwql, g_wql);
    cudaGetSymbolAddress((void**)&pwkh, g_wkh);
    cudaGetSymbolAddress((void**)&pwkl, g_wkl);
    cudaGetSymbolAddress((void**)&pwvh, g_wvh);
    cudaGetSymbolAddress((void**)&pwvl, g_wvl);
    cudaGetSymbolAddress((void**)&pwoh, g_woh);
    cudaGetSymbolAddress((void**)&pwol, g_wol);

    cudaFuncSetAttribute(scan_kernel,
                         cudaFuncAttributeMaxDynamicSharedMemorySize, SCAN_SMEM);
    cudaFuncSetAttribute(tgemm_mma_kernel,
                         cudaFuncAttributeMaxDynamicSharedMemorySize, TG_SMEM);
    cudaFuncSetAttribute(tgemm_qkv_kernel,
                         cudaFuncAttributeMaxDynamicSharedMemorySize, TG_SMEM);
    cudaFuncSetAttribute(chunk_ag_mma_kernel,
                         cudaFuncAttributeMaxDynamicSharedMemorySize, AG_SMEM);

    const int nx4 = BT * Dd / 4;
    const int nw4 = Dd * Dd / 4;
    split_kernel<<<(nx4 + 255) / 256, 256>>>(x, pxh, pxl, nx4);
    split_kernel<<<(nw4 + 255) / 256, 256>>>(Wq, pwqh, pwql, nw4);
    split_kernel<<<(nw4 + 255) / 256, 256>>>(Wk, pwkh, pwkl, nw4);
    split_kernel<<<(nw4 + 255) / 256, 256>>>(Wv, pwvh, pwvl, nw4);
    split_kernel<<<(nw4 + 255) / 256, 256>>>(Wo, pwoh, pwol, nw4);

    tgemm_qkv_kernel<<<dim3(12, BT / 128), 256, TG_SMEM>>>(
        pxh, pxl, pwqh, pwql, pwkh, pwkl, pwvh, pwvl, bq, bk, bv,
        pqh, pql, pK, pV);

    norm_beta_kernel<<<BT, 128>>>(pK, Wbeta, bbeta, pBeta, pkh, pkl);

    chunk_ag_mma_kernel<<<dim3(NCH, Bb), 256, AG_SMEM>>>(
        pkh, pkl, pqh, pql, pBeta, pTh, pTl, pGh, pGl);

    scan_kernel<<<dim3(NVT, Bb), 256, SCAN_SMEM>>>(
        pkh, pkl, pqh, pql, pTh, pTl, pGh, pGl, pV, pBeta, poh, pol);

    tgemm_mma_kernel<<<dim3(4, BT / 128), 256, TG_SMEM>>>(
        poh, pol, pwoh, pwol, bo, out);
}

// round 13
// speedup vs baseline: 4.3561x; 1.0274x over previous
#include <cuda_runtime.h>
#include <cuda_bf16.h>
#include <math.h>
#include <stdint.h>

namespace {
constexpr int Bb  = 8;
constexpr int Tt  = 2048;
constexpr int Dd  = 512;
constexpr int BT  = Bb * Tt;
constexpr int CH  = 64;
constexpr int NCH = Tt / CH;   // 32
constexpr int DV  = 32;
constexpr int NVT = Dd / DV;   // 16

// ---- scan smem layout (byte offsets) ----
constexpr int OFF_S    = 0;              // float [32][520]
constexpr int OFF_UM   = 66560;          // float [64][34]
constexpr int OFF_QS   = 75264;          // float [64][34]
constexpr int OFF_VB   = 83968;          // float [64][34]
constexpr int OFF_BETA = 92672;          // float [64]
constexpr int OFF_KH   = 92928;          // bf16 [64][136]
constexpr int OFF_KL   = 110336;
constexpr int OFF_QH   = 127744;
constexpr int OFF_QL   = 145152;
constexpr int OFF_SH   = 162560;         // bf16 [32][136]
constexpr int OFF_SL   = 171264;
constexpr int OFF_UH   = 179968;         // bf16 [32][72]
constexpr int OFF_UL   = 184576;
constexpr int OFF_TH   = 189184;         // bf16 [64][72]
constexpr int OFF_TL   = 198400;
constexpr int OFF_GH   = 207616;         // bf16 [64][72]
constexpr int OFF_GL   = 216832;
constexpr int SCAN_SMEM = 226048;

// tgemm: 2 slots x (Ah|Al|Bh|Bl) each 128x40 halves = 10240 B
constexpr int TG_TILE  = 10240;
constexpr int TG_SLOT  = 4 * TG_TILE;          // 40960
constexpr int TG_SMEM  = 2 * TG_SLOT;          // 81920 -> 2 CTAs/SM

// chunk_ag smem
constexpr int AG_TILE  = 17408;
constexpr int AG_AS    = 4 * AG_TILE;          // 69632
constexpr int AG_TM    = AG_AS + 64 * 66 * 4;  // 86528
constexpr int AG_WS    = AG_TM + 64 * 66 * 4;  // 103424
constexpr int AG_SMEM  = AG_WS + 16 * 17 * 4;  // 104512
}

using ull = unsigned long long;

// ---------------- device scratch ----------------
__device__ float g_K[BT * Dd];
__device__ float g_V[BT * Dd];
__device__ float g_Beta[BT];
__device__ __nv_bfloat16 g_xh[BT * Dd];
__device__ __nv_bfloat16 g_xl[BT * Dd];
__device__ __nv_bfloat16 g_oh[BT * Dd];
__device__ __nv_bfloat16 g_ol[BT * Dd];
__device__ __nv_bfloat16 g_kh[BT * Dd];
__device__ __nv_bfloat16 g_kl[BT * Dd];
__device__ __nv_bfloat16 g_qh[BT * Dd];
__device__ __nv_bfloat16 g_ql[BT * Dd];
__device__ __nv_bfloat16 g_Th[Bb * NCH * CH * CH];
__device__ __nv_bfloat16 g_Tl[Bb * NCH * CH * CH];
__device__ __nv_bfloat16 g_Gh[Bb * NCH * CH * CH];
__device__ __nv_bfloat16 g_Gl[Bb * NCH * CH * CH];
__device__ __nv_bfloat16 g_wqh[Dd * Dd];
__device__ __nv_bfloat16 g_wql[Dd * Dd];
__device__ __nv_bfloat16 g_wkh[Dd * Dd];
__device__ __nv_bfloat16 g_wkl[Dd * Dd];
__device__ __nv_bfloat16 g_wvh[Dd * Dd];
__device__ __nv_bfloat16 g_wvl[Dd * Dd];
__device__ __nv_bfloat16 g_woh[Dd * Dd];
__device__ __nv_bfloat16 g_wol[Dd * Dd];

__device__ __forceinline__ uint32_t smem_u32(const void* p) {
    uint32_t a;
    asm("{ .reg .u64 t; cvta.to.shared.u64 t,%1; cvt.u32.u64 %0,t; }" : "=r"(a) : "l"(p));
    return a;
}
__device__ __forceinline__ void ldsm_x4(uint32_t* r, uint32_t addr) {
    asm volatile("ldmatrix.sync.aligned.m8n8.x4.shared.b16 {%0,%1,%2,%3}, [%4];"
                 : "=r"(r[0]), "=r"(r[1]), "=r"(r[2]), "=r"(r[3]) : "r"(addr));
}
__device__ __forceinline__ void ldsm_x4t(uint32_t* r, uint32_t addr) {
    asm volatile("ldmatrix.sync.aligned.m8n8.x4.trans.shared.b16 {%0,%1,%2,%3}, [%4];"
                 : "=r"(r[0]), "=r"(r[1]), "=r"(r[2]), "=r"(r[3]) : "r"(addr));
}
__device__ __forceinline__ void mma_bf16(float* d, const uint32_t* a,
                                         uint32_t b0, uint32_t b1) {
    asm volatile(
        "mma.sync.aligned.m16n8k16.row.col.f32.bf16.bf16.f32 "
        "{%0,%1,%2,%3}, {%4,%5,%6,%7}, {%8,%9}, {%0,%1,%2,%3};"
        : "+f"(d[0]), "+f"(d[1]), "+f"(d[2]), "+f"(d[3])
        : "r"(a[0]), "r"(a[1]), "r"(a[2]), "r"(a[3]), "r"(b0), "r"(b1));
}
__device__ __forceinline__ void cp16(uint32_t dst, const void* src) {
    asm volatile("cp.async.ca.shared.global [%0], [%1], 16;" :: "r"(dst), "l"(src));
}
__device__ __forceinline__ void split2(float x, unsigned short& h, unsigned short& l) {
    __nv_bfloat16 hh = __float2bfloat16(x);
    __nv_bfloat16 ll = __float2bfloat16(x - __bfloat162float(hh));
    h = __bfloat16_as_ushort(hh); l = __bfloat16_as_ushort(ll);
}
__device__ __forceinline__ void split4(float4 v, ull& h, ull& l) {
    unsigned short h0, h1, h2, h3, l0, l1, l2, l3;
    split2(v.x, h0, l0); split2(v.y, h1, l1);
    split2(v.z, h2, l2); split2(v.w, h3, l3);
    h = (ull)h0 | ((ull)h1 << 16) | ((ull)h2 << 32) | ((ull)h3 << 48);
    l = (ull)l0 | ((ull)l1 << 16) | ((ull)l2 << 32) | ((ull)l3 << 48);
}
__device__ __forceinline__ uint32_t pack2(float a, float b, bool hi) {
    unsigned short ha, la, hb, lb;
    split2(a, ha, la); split2(b, hb, lb);
    return hi ? ((uint32_t)ha | ((uint32_t)hb << 16))
              : ((uint32_t)la | ((uint32_t)lb << 16));
}

// ---------------- split fp32 -> bf16 hi/lo ----------------
__global__ __launch_bounds__(256) void split_kernel(
    const float* __restrict__ x, __nv_bfloat16* __restrict__ h,
    __nv_bfloat16* __restrict__ l, int n4)
{
    int i = blockIdx.x * 256 + threadIdx.x;
    if (i >= n4) return;
    float4 v = ((const float4*)x)[i];
    ull hw, lw; split4(v, hw, lw);
    ((ull*)h)[i] = hw;
    ((ull*)l)[i] = lw;
}

// ---------------- merged weight split (4 matrices, one launch) ----------------
__global__ __launch_bounds__(256) void split_w_kernel(
    const float* __restrict__ Wq, const float* __restrict__ Wk,
    const float* __restrict__ Wv, const float* __restrict__ Wo,
    __nv_bfloat16* __restrict__ qh, __nv_bfloat16* __restrict__ ql,
    __nv_bfloat16* __restrict__ kh, __nv_bfloat16* __restrict__ kl,
    __nv_bfloat16* __restrict__ vh, __nv_bfloat16* __restrict__ vl,
    __nv_bfloat16* __restrict__ oh, __nv_bfloat16* __restrict__ ol,
    int n4)
{
    int i = blockIdx.x * 256 + threadIdx.x;
    if (i >= n4) return;
    const int w = blockIdx.y;
    const float* src = (w == 0) ? Wq : (w == 1) ? Wk : (w == 2) ? Wv : Wo;
    __nv_bfloat16* h = (w == 0) ? qh : (w == 1) ? kh : (w == 2) ? vh : oh;
    __nv_bfloat16* l = (w == 0) ? ql : (w == 1) ? kl : (w == 2) ? vl : ol;
    float4 v = ((const float4*)src)[i];
    ull hw, lw; split4(v, hw, lw);
    ((ull*)h)[i] = hw;
    ((ull*)l)[i] = lw;
}

// ---------------- HMMA split-bf16 GEMM body (2-slot cp.async) ----------------
__device__ __forceinline__ void tgemm_body(
    const __nv_bfloat16* __restrict__ Ah, const __nv_bfloat16* __restrict__ Al,
    const __nv_bfloat16* __restrict__ Bh, const __nv_bfloat16* __restrict__ Bl,
    const float* __restrict__ bias, float* __restrict__ C,
    __nv_bfloat16* __restrict__ Ch, __nv_bfloat16* __restrict__ Cl,
    int bm, int bn, char* tgs)
{
    const uint32_t sBase = smem_u32(tgs);
    const int tid = threadIdx.x, lane = tid & 31, wid = tid >> 5;
    const int wm = wid & 1, wn = wid >> 1;

    float d[4][4][4];
#pragma unroll
    for (int mt = 0; mt < 4; mt++)
#pragma unroll
        for (int nt = 0; nt < 4; nt++)
#pragma unroll
            for (int e = 0; e < 4; e++) d[mt][nt][e] = 0.f;

    uint32_t a_rel[4], b_rel[2];
    {
        const int ar = lane & 15, akoff = (lane >> 4) * 8;
#pragma unroll
        for (int mt = 0; mt < 4; mt++)
            a_rel[mt] = ((wm * 64 + mt * 16 + ar) * 40 + akoff) * 2;
        const int nrow = wn * 32 + ((lane >> 4) << 3) + (lane & 7);
        const int khalf = (lane >> 3) & 1;
#pragma unroll
        for (int np = 0; np < 2; np++)
            b_rel[np] = ((nrow + np * 16) * 40 + khalf * 8) * 2;
    }

    const int srow0 = tid >> 2,         sc0 = tid & 3;
    const int srow1 = (tid + 256) >> 2, sc1 = (tid + 256) & 3;
    const uint32_t st0 = srow0 * 80 + sc0 * 16;
    const uint32_t st1 = srow1 * 80 + sc1 * 16;

    auto issue = [&](int kt, int slot) {
        const uint32_t b0 = sBase + slot * TG_SLOT;
        const size_t ga0 = (size_t)(bm + srow0) * Dd + kt * 32 + sc0 * 8;
        const size_t ga1 = (size_t)(bm + srow1) * Dd + kt * 32 + sc1 * 8;
        const size_t gb0 = (size_t)(bn + srow0) * Dd + kt * 32 + sc0 * 8;
        const size_t gb1 = (size_t)(bn + srow1) * Dd + kt * 32 + sc1 * 8;
        cp16(b0 + st0,               Ah + ga0);
        cp16(b0 + st1,               Ah + ga1);
        cp16(b0 + TG_TILE + st0,     Al + ga0);
        cp16(b0 + TG_TILE + st1,     Al + ga1);
        cp16(b0 + 2 * TG_TILE + st0, Bh + gb0);
        cp16(b0 + 2 * TG_TILE + st1, Bh + gb1);
        cp16(b0 + 3 * TG_TILE + st0, Bl + gb0);
        cp16(b0 + 3 * TG_TILE + st1, Bl + gb1);
        asm volatile("cp.async.commit_group;");
    };

    issue(0, 0);
#pragma unroll 1
    for (int s = 0; s < 16; s++) {
        if (s + 1 < 16) {
            issue(s + 1, (s + 1) & 1);
            asm volatile("cp.async.wait_group 1;");
        } else {
            asm volatile("cp.async.wait_group 0;");
        }
        __syncthreads();
        const uint32_t slotB = sBase + (s & 1) * TG_SLOT;
#pragma unroll
        for (int p = 0; p < 3; p++) {
            const uint32_t aO = slotB + (p == 2 ? TG_TILE : 0);
            const uint32_t bO = slotB + 2 * TG_TILE + (p == 1 ? TG_TILE : 0);
#pragma unroll
            for (int ks = 0; ks < 2; ks++) {
                uint32_t a[4][4], b[2][4];
#pragma unroll
                for (int mt = 0; mt < 4; mt++) ldsm_x4(a[mt], aO + a_rel[mt] + ks * 32);
#pragma unroll
                for (int np = 0; np < 2; np++) ldsm_x4(b[np], bO + b_rel[np] + ks * 32);
#pragma unroll
                for (int mt = 0; mt < 4; mt++)
#pragma unroll
                    for (int nt = 0; nt < 4; nt++)
                        mma_bf16(d[mt][nt], a[mt],
                                 b[nt >> 1][(nt & 1) * 2], b[nt >> 1][(nt & 1) * 2 + 1]);
            }
        }
        __syncthreads();
    }

#pragma unroll
    for (int mt = 0; mt < 4; mt++) {
        const int r0 = bm + wm * 64 + mt * 16 + (lane >> 2);
#pragma unroll
        for (int nt = 0; nt < 4; nt++) {
            const int c0 = bn + wn * 32 + nt * 8 + (lane & 3) * 2;
            const float b0 = bias[c0], b1 = bias[c0 + 1];
            const float o00 = d[mt][nt][0] + b0, o01 = d[mt][nt][1] + b1;
            const float o10 = d[mt][nt][2] + b0, o11 = d[mt][nt][3] + b1;
            if (C) {
                *(float2*)&C[(size_t)r0 * Dd + c0] = make_float2(o00, o01);
                *(float2*)&C[(size_t)(r0 + 8) * Dd + c0] = make_float2(o10, o11);
            } else {
                unsigned short* ch = (unsigned short*)Ch;
                unsigned short* cl = (unsigned short*)Cl;
                *(uint32_t*)&ch[(size_t)r0 * Dd + c0] = pack2(o00, o01, true);
                *(uint32_t*)&cl[(size_t)r0 * Dd + c0] = pack2(o00, o01, false);
                *(uint32_t*)&ch[(size_t)(r0 + 8) * Dd + c0] = pack2(o10, o11, true);
                *(uint32_t*)&cl[(size_t)(r0 + 8) * Dd + c0] = pack2(o10, o11, false);
            }
        }
    }
}

__global__ __launch_bounds__(256, 2) void tgemm_mma_kernel(
    const __nv_bfloat16* __restrict__ Ah, const __nv_bfloat16* __restrict__ Al,
    const __nv_bfloat16* __restrict__ Bh, const __nv_bfloat16* __restrict__ Bl,
    const float* __restrict__ bias, float* __restrict__ C)
{
    extern __shared__ char tgs[];
    tgemm_body(Ah, Al, Bh, Bl, bias, C, nullptr, nullptr,
               blockIdx.y * 128, blockIdx.x * 128, tgs);
}

__global__ __launch_bounds__(256, 2) void tgemm_qkv_kernel(
    const __nv_bfloat16* __restrict__ Ah, const __nv_bfloat16* __restrict__ Al,
    const __nv_bfloat16* __restrict__ Bqh, const __nv_bfloat16* __restrict__ Bql,
    const __nv_bfloat16* __restrict__ Bkh, const __nv_bfloat16* __restrict__ Bkl,
    const __nv_bfloat16* __restrict__ Bvh, const __nv_bfloat16* __restrict__ Bvl,
    const float* __restrict__ bq, const float* __restrict__ bk,
    const float* __restrict__ bv,
    __nv_bfloat16* __restrict__ Qh, __nv_bfloat16* __restrict__ Ql,
    float* __restrict__ Ck, float* __restrict__ Cv)
{
    extern __shared__ char tgs[];
    const int gsel = blockIdx.x >> 2;
    const int bn = (blockIdx.x & 3) * 128;
    const __nv_bfloat16* Bh = (gsel == 0) ? Bqh : (gsel == 1) ? Bkh : Bvh;
    const __nv_bfloat16* Bl = (gsel == 0) ? Bql : (gsel == 1) ? Bkl : Bvl;
    const float* bias = (gsel == 0) ? bq : (gsel == 1) ? bk : bv;
    float* C = (gsel == 0) ? nullptr : (gsel == 1) ? Ck : Cv;
    tgemm_body(Ah, Al, Bh, Bl, bias, C,
               (gsel == 0) ? Qh : nullptr, (gsel == 0) ? Ql : nullptr,
               blockIdx.y * 128, bn, tgs);
}

// ---------------- l2norm + beta -> split K directly ----------------
__global__ __launch_bounds__(128) void norm_beta_kernel(
    const float* __restrict__ Kd, const float* __restrict__ wb,
    const float* __restrict__ bb, float* __restrict__ Beta,
    __nv_bfloat16* __restrict__ Kh, __nv_bfloat16* __restrict__ Kl)
{
    const int row = blockIdx.x, tid = threadIdx.x;
    float4 v = ((const float4*)(Kd + (size_t)row * Dd))[tid];
    float ss = v.x * v.x + v.y * v.y + v.z * v.z + v.w * v.w;
#pragma unroll
    for (int o = 16; o; o >>= 1) ss += __shfl_xor_sync(0xffffffffu, ss, o);
    __shared__ float red1[4];
    if ((tid & 31) == 0) red1[tid >> 5] = ss;
    __syncthreads();
    const float inv = 1.0f / fmaxf(sqrtf(red1[0] + red1[1] + red1[2] + red1[3]), 1e-12f);
    float4 w = ((const float4*)wb)[tid];
    float bd = v.x * w.x + v.y * w.y + v.z * w.z + v.w * w.w;
#pragma unroll
    for (int o = 16; o; o >>= 1) bd += __shfl_xor_sync(0xffffffffu, bd, o);
    __shared__ float red2[4];
    if ((tid & 31) == 0) red2[tid >> 5] = bd;
    __syncthreads();
    v.x *= inv; v.y *= inv; v.z *= inv; v.w *= inv;
    ull hw, lw; split4(v, hw, lw);
    ((ull*)(Kh + (size_t)row * Dd))[tid] = hw;
    ((ull*)(Kl + (size_t)row * Dd))[tid] = lw;
    if (tid == 0) {
        const float z = (red2[0] + red2[1] + red2[2] + red2[3]) * inv + bb[0];
        Beta[row] = 1.0f / (1.0f + expf(-z));
    }
}

// ---------------- chunk_ag: A,G via mma + T = (I+A)^-1 ----------------
__global__ __launch_bounds__(256) void chunk_ag_mma_kernel(
    const __nv_bfloat16* __restrict__ KhG, const __nv_bfloat16* __restrict__ KlG,
    const __nv_bfloat16* __restrict__ QhG, const __nv_bfloat16* __restrict__ QlG,
    const float* __restrict__ Betad,
    __nv_bfloat16* __restrict__ ThG, __nv_bfloat16* __restrict__ TlG,
    __nv_bfloat16* __restrict__ GhG, __nv_bfloat16* __restrict__ GlG)
{
    extern __shared__ char ags[];
    char* pKh = ags;               char* pKl = ags + AG_TILE;
    char* pQh = ags + 2 * AG_TILE; char* pQl = ags + 3 * AG_TILE;
    float* As = (float*)(ags + AG_AS);
    float* Tm = (float*)(ags + AG_TM);
    float* Ws = (float*)(ags + AG_WS);
    const uint32_t khB = smem_u32(pKh), klB = smem_u32(pKl);
    const uint32_t qhB = smem_u32(pQh), qlB = smem_u32(pQl);

    const int c = blockIdx.x, b = blockIdx.y;
    const int r0g = b * Tt + c * CH;
    const int tid = threadIdx.x, lane = tid & 31, wid = tid >> 5;
    const int mat = wid >> 2, mb = wid & 3;
    const int fr = lane >> 2, fc = 2 * (lane & 3);

    float cacc[8][4];
#pragma unroll
    for (int nb = 0; nb < 8; nb++)
#pragma unroll
        for (int e = 0; e < 4; e++) cacc[nb][e] = 0.f;

#pragma unroll 1
    for (int jt = 0; jt < 4; jt++) {
        if (jt) __syncthreads();
#pragma unroll
        for (int n = 0; n < 4; n++) {
            const int e = tid + n * 256;
            const int t = e >> 4, cc = e & 15;
            const uint32_t off = (uint32_t)t * 272u
                + ((uint32_t)(cc ^ ((t >> 3) & 1)) << 4);
            const size_t g = (size_t)(r0g + t) * Dd + jt * 128 + cc * 8;
            cp16(khB + off, KhG + g);
            cp16(klB + off, KlG + g);
            cp16(qhB + off, QhG + g);
            cp16(qlB + off, QlG + g);
        }
        asm volatile("cp.async.commit_group;");
        asm volatile("cp.async.wait_group 0;");
        __syncthreads();
#pragma unroll
        for (int p = 0; p < 3; p++) {
            const uint32_t aT = mat ? (p < 2 ? qhB : qlB) : (p < 2 ? khB : klB);
            const uint32_t bT = (p == 1) ? klB : khB;
#pragma unroll
            for (int k = 0; k < 8; k++) {
                uint32_t a[4];
                {
                    const int r = mb * 16 + (lane & 15);
                    const int cc = k * 2 + (lane >> 4);
                    ldsm_x4(a, aT + r * 272u + ((uint32_t)(cc ^ ((r >> 3) & 1)) << 4));
                }
#pragma unroll
                for (int nb4 = 0; nb4 < 4; nb4++) {
                    uint32_t bb[4];
                    const int r = nb4 * 16 + (lane & 7) + ((lane >> 4) << 3);
                    const int cc = k * 2 + ((lane >> 3) & 1);
                    ldsm_x4(bb, bT + r * 272u + ((uint32_t)(cc ^ ((r >> 3) & 1)) << 4));
                    mma_bf16(cacc[nb4 * 2 + 0], a, bb[0], bb[1]);
                    mma_bf16(cacc[nb4 * 2 + 1], a, bb[2], bb[3]);
                }
            }
        }
    }
    __syncthreads();

    const size_t gbase = ((size_t)(b * NCH) + c) * (CH * CH);
    const int t0r = mb * 16 + fr, t1r = t0r + 8;
    if (mat == 0) {
        const float bt0 = Betad[r0g + t0r], bt1 = Betad[r0g + t1r];
#pragma unroll
        for (int nb = 0; nb < 8; nb++) {
            const int j = nb * 8 + fc;
            float2 o0, o1;
            o0.x = (j     < t0r) ? bt0 * cacc[nb][0] : 0.f;
            o0.y = (j + 1 < t0r) ? bt0 * cacc[nb][1] : 0.f;
            o1.x = (j     < t1r) ? bt1 * cacc[nb][2] : 0.f;
            o1.y = (j + 1 < t1r) ? bt1 * cacc[nb][3] : 0.f;
            *(float2*)&As[t0r * 66 + j] = o0;
            *(float2*)&As[t1r * 66 + j] = o1;
        }
    } else {
        unsigned short* Gh = (unsigned short*)GhG;
        unsigned short* Gl = (unsigned short*)GlG;
#pragma unroll
        for (int nb = 0; nb < 8; nb++) {
            const int j = nb * 8 + fc;
            float v00 = (j     <= t0r) ? cacc[nb][0] : 0.f;
            float v01 = (j + 1 <= t0r) ? cacc[nb][1] : 0.f;
            float v10 = (j     <= t1r) ? cacc[nb][2] : 0.f;
            float v11 = (j + 1 <= t1r) ? cacc[nb][3] : 0.f;
            *(uint32_t*)&Gh[gbase + t0r * 64 + j] = pack2(v00, v01, true);
            *(uint32_t*)&Gl[gbase + t0r * 64 + j] = pack2(v00, v01, false);
            *(uint32_t*)&Gh[gbase + t1r * 64 + j] = pack2(v10, v11, true);
            *(uint32_t*)&Gl[gbase + t1r * 64 + j] = pack2(v10, v11, false);
        }
    }
    for (int e = tid; e < 64 * 66; e += 256) Tm[e] = 0.f;
    __syncthreads();

    // diagonal 16x16 inversions
    if (wid < 4) {
        const int r = lane & 15;
        float Lr[16], val[16];
#pragma unroll
        for (int j = 0; j < 16; j++) Lr[j] = As[(wid * 16 + r) * 66 + wid * 16 + j];
#pragma unroll
        for (int cc = 0; cc < 16; cc++) val[cc] = (r == cc) ? 1.f : 0.f;
#pragma unroll
        for (int j = 0; j < 15; j++) {
#pragma unroll
            for (int cc = 0; cc < 16; cc++) {
                if (cc <= j) {
                    float tjc = __shfl_sync(0xffffffffu, val[cc], j);
                    if (r > j) val[cc] -= Lr[j] * tjc;
                }
            }
        }
        if (lane < 16) {
#pragma unroll
            for (int cc = 0; cc < 16; cc++)
                Tm[(wid * 16 + r) * 66 + wid * 16 + cc] = val[cc];
        }
    }
    __syncthreads();

    // off-diagonal blocks
    {
        const int oi[6] = {1, 2, 3, 2, 3, 3};
        const int oj[6] = {0, 0, 0, 1, 1, 2};
        const int r = tid >> 4, cc = tid & 15;
#pragma unroll 1
        for (int s6 = 0; s6 < 6; s6++) {
            const int bi = oi[s6], bj = oj[s6];
            float w = 0.f;
            for (int k = bj; k < bi; k++)
#pragma unroll
                for (int m = 0; m < 16; m++)
                    w += As[(bi * 16 + r) * 66 + k * 16 + m] *
                         Tm[(k * 16 + m) * 66 + bj * 16 + cc];
            Ws[r * 17 + cc] = w;
            __syncthreads();
            float t2 = 0.f;
#pragma unroll
            for (int m = 0; m < 16; m++)
                t2 += Tm[(bi * 16 + r) * 66 + bi * 16 + m] * Ws[m * 17 + cc];
            Tm[(bi * 16 + r) * 66 + bj * 16 + cc] = -t2;
            __syncthreads();
        }
    }

    {
        unsigned short* Th = (unsigned short*)ThG;
        unsigned short* Tl = (unsigned short*)TlG;
        for (int e = tid; e < 2048; e += 256) {
            const int t = e >> 5, j = (e & 31) * 2;
            *(uint32_t*)&Th[gbase + t * 64 + j] =
                pack2(Tm[t * 66 + j], Tm[t * 66 + j + 1], true);
            *(uint32_t*)&Tl[gbase + t * 64 + j] =
                pack2(Tm[t * 66 + j], Tm[t * 66 + j + 1], false);
        }
    }
}

// ---------------- chunked delta-rule scan: all-mma ----------------
__global__ __launch_bounds__(256) void scan_kernel(
    const __nv_bfloat16* __restrict__ KhG, const __nv_bfloat16* __restrict__ KlG,
    const __nv_bfloat16* __restrict__ QhG, const __nv_bfloat16* __restrict__ QlG,
    const __nv_bfloat16* __restrict__ ThG, const __nv_bfloat16* __restrict__ TlG,
    const __nv_bfloat16* __restrict__ GhG, const __nv_bfloat16* __restrict__ GlG,
    const float* __restrict__ Vd, const float* __restrict__ Betad,
    __nv_bfloat16* __restrict__ OhG, __nv_bfloat16* __restrict__ OlG)
{
    extern __shared__ char sraw[];
    float* S     = (float*)(sraw + OFF_S);
    float* Um    = (float*)(sraw + OFF_UM);
    float* QSm   = (float*)(sraw + OFF_QS);
    float* Vb    = (float*)(sraw + OFF_VB);
    float* betas = (float*)(sraw + OFF_BETA);
    char* pKh = sraw + OFF_KH;  char* pKl = sraw + OFF_KL;
    char* pQh = sraw + OFF_QH;  char* pQl = sraw + OFF_QL;
    char* pSh = sraw + OFF_SH;  char* pSl = sraw + OFF_SL;
    char* pUh = sraw + OFF_UH;  char* pUl = sraw + OFF_UL;
    char* pTh = sraw + OFF_TH;  char* pTl = sraw + OFF_TL;
    char* pGh = sraw + OFF_GH;  char* pGl = sraw + OFF_GL;
    const uint32_t khB = smem_u32(pKh), klB = smem_u32(pKl);
    const uint32_t qhB = smem_u32(pQh), qlB = smem_u32(pQl);
    const uint32_t shB = smem_u32(pSh), slB = smem_u32(pSl);
    const uint32_t uhB = smem_u32(pUh), ulB = smem_u32(pUl);
    const uint32_t thB = smem_u32(pTh), tlB = smem_u32(pTl);
    const uint32_t ghB = smem_u32(pGh), glB = smem_u32(pGl);

    const int b = blockIdx.y;
    const int i0 = blockIdx.x * DV;
    const int tid = threadIdx.x;
    const int lane = tid & 31, wid = tid >> 5;
    const int fr = lane >> 2, fc = 2 * (lane & 3);

    for (int e = tid; e < 32 * 520; e += 256) S[e] = 0.f;
    __syncthreads();

    for (int c = 0; c < NCH; c++) {
        const int r0g = b * Tt + c * CH;
        const size_t gbase = ((size_t)(b * NCH) + c) * (CH * CH);

        // issue T/G staging (group) and phase-A jt=0 K/Q staging (group)
#pragma unroll
        for (int n = 0; n < 2; n++) {
            const int e = tid + n * 256;
            const int r = e >> 3, cc = e & 7;
            const uint32_t off = (uint32_t)r * 144u
                + ((uint32_t)(cc ^ ((r >> 3) & 1)) << 4);
            const size_t g = gbase + r * 64 + cc * 8;
            cp16(thB + off, ThG + g);
            cp16(tlB + off, TlG + g);
            cp16(ghB + off, GhG + g);
            cp16(glB + off, GlG + g);
        }
        asm volatile("cp.async.commit_group;");
#pragma unroll
        for (int n = 0; n < 4; n++) {
            const int e = tid + n * 256;
            const int t = e >> 4, cc = e & 15;
            const uint32_t off = (uint32_t)t * 272u
                + ((uint32_t)(cc ^ ((t >> 3) & 1)) << 4);
            const size_t g = (size_t)(r0g + t) * Dd + cc * 8;   // jt = 0
            cp16(khB + off, KhG + g);
            cp16(klB + off, KlG + g);
            cp16(qhB + off, QhG + g);
            cp16(qlB + off, QlG + g);
        }
        asm volatile("cp.async.commit_group;");
        // V slice, beta (scalar loads, consumed after phase-A syncs)
        for (int e = tid; e < CH * DV; e += 256) {
            const int t = e >> 5, i = e & 31;
            Vb[t * 34 + i] = Vd[(size_t)(r0g + t) * Dd + i0 + i];
        }
        if (tid < 64) betas[tid] = Betad[r0g + tid];

        // ---- Phase A ----
        const int mat = wid >> 2;
        const int mb  = wid & 3;
        float cacc[4][4];
#pragma unroll
        for (int nb = 0; nb < 4; nb++)
#pragma unroll
            for (int e = 0; e < 4; e++) cacc[nb][e] = 0.f;

#pragma unroll 1
        for (int jt = 0; jt < 4; jt++) {
            if (jt > 0) {
#pragma unroll
                for (int n = 0; n < 4; n++) {
                    const int e = tid + n * 256;
                    const int t = e >> 4, cc = e & 15;
                    const uint32_t off = (uint32_t)t * 272u
                        + ((uint32_t)(cc ^ ((t >> 3) & 1)) << 4);
                    const size_t g = (size_t)(r0g + t) * Dd + jt * 128 + cc * 8;
                    cp16(khB + off, KhG + g);
                    cp16(klB + off, KlG + g);
                    cp16(qhB + off, QhG + g);
                    cp16(qlB + off, QlG + g);
                }
                asm volatile("cp.async.commit_group;");
            }
            // convert S tile fp32 -> bf16 hi/lo (overlaps cp.async)
#pragma unroll
            for (int n = 0; n < 4; n++) {
                const int e = tid + n * 256;
                const int i = e >> 5, d4 = (e & 31) * 4;
                float4 v = *(const float4*)&S[i * 520 + jt * 128 + d4];
                ull hw, lw; split4(v, hw, lw);
                const uint32_t off = (uint32_t)i * 272u
                    + ((uint32_t)((d4 >> 3) ^ ((i >> 3) & 1)) << 4) + (d4 & 7) * 2;
                *(ull*)(pSh + off) = hw;
                *(ull*)(pSl + off) = lw;
            }
            asm volatile("cp.async.wait_group 0;");
            __syncthreads();
#pragma unroll
            for (int p = 0; p < 3; p++) {
                const uint32_t aT = mat ? (p < 2 ? qhB : qlB) : (p < 2 ? khB : klB);
                const uint32_t bT = (p == 1) ? slB : shB;
#pragma unroll
                for (int k = 0; k < 8; k++) {
                    uint32_t a[4], b0[4], b1[4];
                    {
                        const int r = mb * 16 + (lane & 15);
                        const int cc = k * 2 + (lane >> 4);
                        ldsm_x4(a, aT + r * 272u + ((uint32_t)(cc ^ ((r >> 3) & 1)) << 4));
                    }
                    {
                        const int r = (lane & 7) + ((lane >> 4) << 3);
                        const int cc = k * 2 + ((lane >> 3) & 1);
                        ldsm_x4(b0, bT + r * 272u + ((uint32_t)(cc ^ ((r >> 3) & 1)) << 4));
                        const int r2 = r + 16;
                        ldsm_x4(b1, bT + r2 * 272u + ((uint32_t)(cc ^ ((r2 >> 3) & 1)) << 4));
                    }
                    mma_bf16(cacc[0], a, b0[0], b0[1]);
                    mma_bf16(cacc[1], a, b0[2], b0[3]);
                    mma_bf16(cacc[2], a, b1[0], b1[1]);
                    mma_bf16(cacc[3], a, b1[2], b1[3]);
                }
            }
            __syncthreads();
        }

        {
            const int t0r = mb * 16 + fr, t1r = t0r + 8;
            if (mat == 0) {
                const float b0v = betas[t0r], b1v = betas[t1r];
#pragma unroll
                for (int nb = 0; nb < 4; nb++) {
                    const int i = nb * 8 + fc;
                    float2 v0 = *(float2*)&Vb[t0r * 34 + i];
                    float2 v1 = *(float2*)&Vb[t1r * 34 + i];
                    *(float2*)&Um[t0r * 34 + i] =
                        make_float2(b0v * (v0.x - cacc[nb][0]), b0v * (v0.y - cacc[nb][1]));
                    *(float2*)&Um[t1r * 34 + i] =
                        make_float2(b1v * (v1.x - cacc[nb][2]), b1v * (v1.y - cacc[nb][3]));
                }
            } else {
#pragma unroll
                for (int nb = 0; nb < 4; nb++) {
                    const int i = nb * 8 + fc;
                    *(float2*)&QSm[t0r * 34 + i] = make_float2(cacc[nb][0], cacc[nb][1]);
                    *(float2*)&QSm[t1r * 34 + i] = make_float2(cacc[nb][2], cacc[nb][3]);
                }
            }
        }
        __syncthreads();

        // split rhs -> UH/UL transposed
        for (int e = tid; e < 2048; e += 256) {
            const int t = e >> 5, i = e & 31;
            unsigned short uh, ul; split2(Um[t * 34 + i], uh, ul);
            const uint32_t off = (uint32_t)i * 144u
                + ((uint32_t)((t >> 3) ^ ((i >> 3) & 1)) << 4) + (t & 7) * 2;
            *(unsigned short*)(pUh + off) = uh;
            *(unsigned short*)(pUl + off) = ul;
        }
        __syncthreads();

        // Phase B': U = T @ rhs
        {
            const int mb2 = wid >> 1, nh = wid & 1;
            float du[2][4];
#pragma unroll
            for (int n8 = 0; n8 < 2; n8++)
#pragma unroll
                for (int e = 0; e < 4; e++) du[n8][e] = 0.f;
#pragma unroll
            for (int p = 0; p < 3; p++) {
                const uint32_t aT = (p < 2) ? thB : tlB;
                const uint32_t bT = (p == 1) ? ulB : uhB;
#pragma unroll
                for (int k = 0; k < 4; k++) {
                    uint32_t a[4], bb[4];
                    {
                        const int r = mb2 * 16 + (lane & 15);
                        const int cc = k * 2 + (lane >> 4);
                        ldsm_x4(a, aT + r * 144u + ((uint32_t)(cc ^ ((r >> 3) & 1)) << 4));
                    }
                    {
                        const int rr = nh * 16 + (lane & 7) + ((lane >> 4) << 3);
                        const int cc = k * 2 + ((lane >> 3) & 1);
                        ldsm_x4(bb, bT + rr * 144u + ((uint32_t)(cc ^ ((rr >> 3) & 1)) << 4));
                    }
                    mma_bf16(du[0], a, bb[0], bb[1]);
                    mma_bf16(du[1], a, bb[2], bb[3]);
                }
            }
            __syncthreads();
            const int t0r = mb2 * 16 + fr, t1r = t0r + 8;
#pragma unroll
            for (int n8 = 0; n8 < 2; n8++) {
                const int i = nh * 16 + n8 * 8 + fc;
                *(float2*)&Um[t0r * 34 + i] = make_float2(du[n8][0], du[n8][1]);
                *(float2*)&Um[t1r * 34 + i] = make_float2(du[n8][2], du[n8][3]);
            }
        }
        __syncthreads();

        // split U -> UH/UL transposed
        for (int e = tid; e < 2048; e += 256) {
            const int t = e >> 5, i = e & 31;
            unsigned short uh, ul; split2(Um[t * 34 + i], uh, ul);
            const uint32_t off = (uint32_t)i * 144u
                + ((uint32_t)((t >> 3) ^ ((i >> 3) & 1)) << 4) + (t & 7) * 2;
            *(unsigned short*)(pUh + off) = uh;
            *(unsigned short*)(pUl + off) = ul;
        }
        __syncthreads();

        // issue phase-D jt=0 K staging into K slot (overlaps phase C')
#pragma unroll
        for (int n = 0; n < 4; n++) {
            const int e = tid + n * 256;
            const int t = e >> 4, cc = e & 15;
            const uint32_t off = (uint32_t)t * 272u
                + ((uint32_t)(cc ^ ((t >> 3) & 1)) << 4);
            const size_t g = (size_t)(r0g + t) * Dd + cc * 8;    // jt = 0
            cp16(khB + off, KhG + g);
            cp16(klB + off, KlG + g);
        }
        asm volatile("cp.async.commit_group;");

        // Phase C': O = QS + G @ U (write split bf16 output)
        {
            const int mb2 = wid >> 1, nh = wid & 1;
            const int t0r = mb2 * 16 + fr, t1r = t0r + 8;
            float du[2][4];
#pragma unroll
            for (int n8 = 0; n8 < 2; n8++) {
                const int i = nh * 16 + n8 * 8 + fc;
                float2 q0 = *(float2*)&QSm[t0r * 34 + i];
                float2 q1 = *(float2*)&QSm[t1r * 34 + i];
                du[n8][0] = q0.x; du[n8][1] = q0.y;
                du[n8][2] = q1.x; du[n8][3] = q1.y;
            }
#pragma unroll
            for (int p = 0; p < 3; p++) {
                const uint32_t aT = (p < 2) ? ghB : glB;
                const uint32_t bT = (p == 1) ? ulB : uhB;
#pragma unroll
                for (int k = 0; k < 4; k++) {
                    uint32_t a[4], bb[4];
                    {
                        const int r = mb2 * 16 + (lane & 15);
                        const int cc = k * 2 + (lane >> 4);
                        ldsm_x4(a, aT + r * 144u + ((uint32_t)(cc ^ ((r >> 3) & 1)) << 4));
                    }
                    {
                        const int rr = nh * 16 + (lane & 7) + ((lane >> 4) << 3);
                        const int cc = k * 2 + ((lane >> 3) & 1);
                        ldsm_x4(bb, bT + rr * 144u + ((uint32_t)(cc ^ ((rr >> 3) & 1)) << 4));
                    }
                    mma_bf16(du[0], a, bb[0], bb[1]);
                    mma_bf16(du[1], a, bb[2], bb[3]);
                }
            }
            unsigned short* oh = (unsigned short*)OhG;
            unsigned short* ol = (unsigned short*)OlG;
#pragma unroll
            for (int n8 = 0; n8 < 2; n8++) {
                const int i = nh * 16 + n8 * 8 + fc;
                const size_t g0 = (size_t)(r0g + t0r) * Dd + i0 + i;
                const size_t g1 = (size_t)(r0g + t1r) * Dd + i0 + i;
                *(uint32_t*)&oh[g0] = pack2(du[n8][0], du[n8][1], true);
                *(uint32_t*)&ol[g0] = pack2(du[n8][0], du[n8][1], false);
                *(uint32_t*)&oh[g1] = pack2(du[n8][2], du[n8][3], true);
                *(uint32_t*)&ol[g1] = pack2(du[n8][2], du[n8][3], false);
            }
        }

        // Phase D: S += U^T @ K  (double-buffered staging: K slot <-> Q slot)
#pragma unroll 1
        for (int jt = 0; jt < 4; jt++) {
            const uint32_t curH = (jt & 1) ? qhB : khB;
            const uint32_t curL = (jt & 1) ? qlB : klB;
            if (jt + 1 < 4) {
                const uint32_t nxtH = ((jt + 1) & 1) ? qhB : khB;
                const uint32_t nxtL = ((jt + 1) & 1) ? qlB : klB;
#pragma unroll
                for (int n = 0; n < 4; n++) {
                    const int e = tid + n * 256;
                    const int t = e >> 4, cc = e & 15;
                    const uint32_t off = (uint32_t)t * 272u
                        + ((uint32_t)(cc ^ ((t >> 3) & 1)) << 4);
                    const size_t g = (size_t)(r0g + t) * Dd + (jt + 1) * 128 + cc * 8;
                    cp16(nxtH + off, KhG + g);
                    cp16(nxtL + off, KlG + g);
                }
                asm volatile("cp.async.commit_group;");
                asm volatile("cp.async.wait_group 1;");
            } else {
                asm volatile("cp.async.wait_group 0;");
            }
            __syncthreads();

            float cf[2][2][4];
            const int dbase = jt * 128 + wid * 16;
#pragma unroll
            for (int mi = 0; mi < 2; mi++)
#pragma unroll
                for (int n8 = 0; n8 < 2; n8++) {
                    const int i0r = mi * 16 + fr;
                    const int col = dbase + n8 * 8 + fc;
                    float2 x0 = *(float2*)&S[i0r * 520 + col];
                    float2 x1 = *(float2*)&S[(i0r + 8) * 520 + col];
                    cf[mi][n8][0] = x0.x; cf[mi][n8][1] = x0.y;
                    cf[mi][n8][2] = x1.x; cf[mi][n8][3] = x1.y;
                }
#pragma unroll
            for (int p = 0; p < 3; p++) {
                const uint32_t aT = (p < 2) ? uhB : ulB;
                const uint32_t bT = (p == 1) ? curL : curH;
#pragma unroll
                for (int k = 0; k < 4; k++) {
                    uint32_t a0[4], a1[4], bb[4];
                    {
                        const int r = lane & 15;
                        const int cc = k * 2 + (lane >> 4);
                        ldsm_x4(a0, aT + r * 144u + ((uint32_t)(cc ^ ((r >> 3) & 1)) << 4));
                        const int r2 = 16 + (lane & 15);
                        ldsm_x4(a1, aT + r2 * 144u + ((uint32_t)(cc ^ ((r2 >> 3) & 1)) << 4));
                    }
                    {
                        const int tr = k * 16 + (lane & 15);
                        const int cc = wid * 2 + (lane >> 4);
                        ldsm_x4t(bb, bT + tr * 272u + ((uint32_t)(cc ^ ((tr >> 3) & 1)) << 4));
                    }
                    mma_bf16(cf[0][0], a0, bb[0], bb[1]);
                    mma_bf16(cf[0][1], a0, bb[2], bb[3]);
                    mma_bf16(cf[1][0], a1, bb[0], bb[1]);
                    mma_bf16(cf[1][1], a1, bb[2], bb[3]);
                }
            }
#pragma unroll
            for (int mi = 0; mi < 2; mi++)
#pragma unroll
                for (int n8 = 0; n8 < 2; n8++) {
                    const int i0r = mi * 16 + fr;
                    const int col = dbase + n8 * 8 + fc;
                    *(float2*)&S[i0r * 520 + col] =
                        make_float2(cf[mi][n8][0], cf[mi][n8][1]);
                    *(float2*)&S[(i0r + 8) * 520 + col] =
                        make_float2(cf[mi][n8][2], cf[mi][n8][3]);
                }
            __syncthreads();
        }
    }
}

extern "C" void kernel_launch(void* const* d_in, const int* in_sizes, int n_in,
                              void* d_out, int out_size)
{
    const float* x     = (const float*)d_in[0];
    const float* Wq    = (const float*)d_in[1];
    const float* bq    = (const float*)d_in[2];
    const float* Wk    = (const float*)d_in[3];
    const float* bk    = (const float*)d_in[4];
    const float* Wv    = (const float*)d_in[5];
    const float* bv    = (const float*)d_in[6];
    const float* Wbeta = (const float*)d_in[7];
    const float* bbeta = (const float*)d_in[8];
    const float* Wo    = (const float*)d_in[9];
    const float* bo    = (const float*)d_in[10];
    float* out = (float*)d_out;

    float *pK, *pV, *pBeta;
    cudaGetSymbolAddress((void**)&pK, g_K);
    cudaGetSymbolAddress((void**)&pV, g_V);
    cudaGetSymbolAddress((void**)&pBeta, g_Beta);

    __nv_bfloat16 *pxh, *pxl, *poh, *pol, *pkh, *pkl, *pqh, *pql;
    __nv_bfloat16 *pTh, *pTl, *pGh, *pGl;
    __nv_bfloat16 *pwqh, *pwql, *pwkh, *pwkl, *pwvh, *pwvl, *pwoh, *pwol;
    cudaGetSymbolAddress((void**)&pxh, g_xh);
    cudaGetSymbolAddress((void**)&pxl, g_xl);
    cudaGetSymbolAddress((void**)&poh, g_oh);
    cudaGetSymbolAddress((void**)&pol, g_ol);
    cudaGetSymbolAddress((void**)&pkh, g_kh);
    cudaGetSymbolAddress((void**)&pkl, g_kl);
    cudaGetSymbolAddress((void**)&pqh, g_qh);
    cudaGetSymbolAddress((void**)&pql, g_ql);
    cudaGetSymbolAddress((void**)&pTh, g_Th);
    cudaGetSymbolAddress((void**)&pTl, g_Tl);
    cudaGetSymbolAddress((void**)&pGh, g_Gh);
    cudaGetSymbolAddress((void**)&pGl, g_Gl);
    cudaGetSymbolAddress((void**)&pwqh, g_wqh);
    cudaGetSymbolAddress((void**)&pwql, g_wql);
    cudaGetSymbolAddress((void**)&pwkh, g_wkh);
    cudaGetSymbolAddress((void**)&pwkl, g_wkl);
    cudaGetSymbolAddress((void**)&pwvh, g_wvh);
    cudaGetSymbolAddress((void**)&pwvl, g_wvl);
    cudaGetSymbolAddress((void**)&pwoh, g_woh);
    cudaGetSymbolAddress((void**)&pwol, g_wol);

    cudaFuncSetAttribute(scan_kernel,
                         cudaFuncAttributeMaxDynamicSharedMemorySize, SCAN_SMEM);
    cudaFuncSetAttribute(tgemm_mma_kernel,
                         cudaFuncAttributeMaxDynamicSharedMemorySize, TG_SMEM);
    cudaFuncSetAttribute(tgemm_qkv_kernel,
                         cudaFuncAttributeMaxDynamicSharedMemorySize, TG_SMEM);
    cudaFuncSetAttribute(chunk_ag_mma_kernel,
                         cudaFuncAttributeMaxDynamicSharedMemorySize, AG_SMEM);

    const int nx4 = BT * Dd / 4;
    const int nw4 = Dd * Dd / 4;
    split_kernel<<<(nx4 + 255) / 256, 256>>>(x, pxh, pxl, nx4);
    split_w_kernel<<<dim3((nw4 + 255) / 256, 4), 256>>>(
        Wq, Wk, Wv, Wo, pwqh, pwql, pwkh, pwkl, pwvh, pwvl, pwoh, pwol, nw4);

    tgemm_qkv_kernel<<<dim3(12, BT / 128), 256, TG_SMEM>>>(
        pxh, pxl, pwqh, pwql, pwkh, pwkl, pwvh, pwvl, bq, bk, bv,
        pqh, pql, pK, pV);

    norm_beta_kernel<<<BT, 128>>>(pK, Wbeta, bbeta, pBeta, pkh, pkl);

    chunk_ag_mma_kernel<<<dim3(NCH, Bb), 256, AG_SMEM>>>(
        pkh, pkl, pqh, pql, pBeta, pTh, pTl, pGh, pGl);

    scan_kernel<<<dim3(NVT, Bb), 256, SCAN_SMEM>>>(
        pkh, pkl, pqh, pql, pTh, pTl, pGh, pGl, pV, pBeta, poh, pol);

    tgemm_mma_kernel<<<dim3(4, BT / 128), 256, TG_SMEM>>>(
        poh, pol, pwoh, pwol, bo, out);
}

// round 14
// speedup vs baseline: 4.6708x; 1.0722x over previous
#include <cuda_runtime.h>
#include <cuda_bf16.h>
#include <math.h>
#include <stdint.h>

namespace {
constexpr int Bb  = 8;
constexpr int Tt  = 2048;
constexpr int Dd  = 512;
constexpr int BT  = Bb * Tt;
constexpr int CH  = 64;
constexpr int NCH = Tt / CH;   // 32
constexpr int DV  = 32;
constexpr int NVT = Dd / DV;   // 16

// ---- scan smem layout (byte offsets) ----
constexpr int OFF_S    = 0;              // float [32][520]
constexpr int OFF_UM   = 66560;          // float [64][34]
constexpr int OFF_QS   = 75264;          // float [64][34]
constexpr int OFF_VB   = 83968;          // float [64][34]
constexpr int OFF_BETA = 92672;          // float [64]
constexpr int OFF_KH   = 92928;          // bf16 [64][136]
constexpr int OFF_KL   = 110336;
constexpr int OFF_QH   = 127744;
constexpr int OFF_QL   = 145152;
constexpr int OFF_SH   = 162560;         // bf16 [32][136]
constexpr int OFF_SL   = 171264;
constexpr int OFF_UH   = 179968;         // bf16 [32][72]
constexpr int OFF_UL   = 184576;
constexpr int OFF_TH   = 189184;         // bf16 [64][72]
constexpr int OFF_TL   = 198400;
constexpr int OFF_GH   = 207616;         // bf16 [64][72]
constexpr int OFF_GL   = 216832;
constexpr int SCAN_SMEM = 226048;

// tgemm: 2 slots x (Ah|Al|Bh|Bl) each 128x40 halves = 10240 B
constexpr int TG_TILE  = 10240;
constexpr int TG_SLOT  = 4 * TG_TILE;          // 40960
constexpr int TG_SMEM  = 2 * TG_SLOT;          // 81920 -> 2 CTAs/SM

// chunk_ag smem
constexpr int AG_TILE  = 17408;
constexpr int AG_AS    = 4 * AG_TILE;          // 69632
constexpr int AG_TM    = AG_AS + 64 * 66 * 4;  // 86528
constexpr int AG_WS    = AG_TM + 64 * 66 * 4;  // 103424
constexpr int AG_SMEM  = AG_WS + 16 * 17 * 4;  // 104512
}

using ull = unsigned long long;

// ---------------- device scratch ----------------
__device__ float g_K[BT * Dd];
__device__ float g_V[BT * Dd];
__device__ float g_Beta[BT];
__device__ __nv_bfloat16 g_xh[BT * Dd];
__device__ __nv_bfloat16 g_xl[BT * Dd];
__device__ __nv_bfloat16 g_oh[BT * Dd];
__device__ __nv_bfloat16 g_ol[BT * Dd];
__device__ __nv_bfloat16 g_kh[BT * Dd];
__device__ __nv_bfloat16 g_kl[BT * Dd];
__device__ __nv_bfloat16 g_qh[BT * Dd];
__device__ __nv_bfloat16 g_ql[BT * Dd];
__device__ __nv_bfloat16 g_Th[Bb * NCH * CH * CH];
__device__ __nv_bfloat16 g_Tl[Bb * NCH * CH * CH];
__device__ __nv_bfloat16 g_Gh[Bb * NCH * CH * CH];
__device__ __nv_bfloat16 g_Gl[Bb * NCH * CH * CH];
__device__ __nv_bfloat16 g_wqh[Dd * Dd];
__device__ __nv_bfloat16 g_wql[Dd * Dd];
__device__ __nv_bfloat16 g_wkh[Dd * Dd];
__device__ __nv_bfloat16 g_wkl[Dd * Dd];
__device__ __nv_bfloat16 g_wvh[Dd * Dd];
__device__ __nv_bfloat16 g_wvl[Dd * Dd];
__device__ __nv_bfloat16 g_woh[Dd * Dd];
__device__ __nv_bfloat16 g_wol[Dd * Dd];

__device__ __forceinline__ uint32_t smem_u32(const void* p) {
    uint32_t a;
    asm("{ .reg .u64 t; cvta.to.shared.u64 t,%1; cvt.u32.u64 %0,t; }" : "=r"(a) : "l"(p));
    return a;
}
__device__ __forceinline__ void ldsm_x4(uint32_t* r, uint32_t addr) {
    asm volatile("ldmatrix.sync.aligned.m8n8.x4.shared.b16 {%0,%1,%2,%3}, [%4];"
                 : "=r"(r[0]), "=r"(r[1]), "=r"(r[2]), "=r"(r[3]) : "r"(addr));
}
__device__ __forceinline__ void ldsm_x4t(uint32_t* r, uint32_t addr) {
    asm volatile("ldmatrix.sync.aligned.m8n8.x4.trans.shared.b16 {%0,%1,%2,%3}, [%4];"
                 : "=r"(r[0]), "=r"(r[1]), "=r"(r[2]), "=r"(r[3]) : "r"(addr));
}
__device__ __forceinline__ void mma_bf16(float* d, const uint32_t* a,
                                         uint32_t b0, uint32_t b1) {
    asm volatile(
        "mma.sync.aligned.m16n8k16.row.col.f32.bf16.bf16.f32 "
        "{%0,%1,%2,%3}, {%4,%5,%6,%7}, {%8,%9}, {%0,%1,%2,%3};"
        : "+f"(d[0]), "+f"(d[1]), "+f"(d[2]), "+f"(d[3])
        : "r"(a[0]), "r"(a[1]), "r"(a[2]), "r"(a[3]), "r"(b0), "r"(b1));
}
__device__ __forceinline__ void cp16(uint32_t dst, const void* src) {
    asm volatile("cp.async.ca.shared.global [%0], [%1], 16;" :: "r"(dst), "l"(src));
}
__device__ __forceinline__ void split2(float x, unsigned short& h, unsigned short& l) {
    __nv_bfloat16 hh = __float2bfloat16(x);
    __nv_bfloat16 ll = __float2bfloat16(x - __bfloat162float(hh));
    h = __bfloat16_as_ushort(hh); l = __bfloat16_as_ushort(ll);
}
__device__ __forceinline__ void split4(float4 v, ull& h, ull& l) {
    unsigned short h0, h1, h2, h3, l0, l1, l2, l3;
    split2(v.x, h0, l0); split2(v.y, h1, l1);
    split2(v.z, h2, l2); split2(v.w, h3, l3);
    h = (ull)h0 | ((ull)h1 << 16) | ((ull)h2 << 32) | ((ull)h3 << 48);
    l = (ull)l0 | ((ull)l1 << 16) | ((ull)l2 << 32) | ((ull)l3 << 48);
}
__device__ __forceinline__ uint32_t pack2(float a, float b, bool hi) {
    unsigned short ha, la, hb, lb;
    split2(a, ha, la); split2(b, hb, lb);
    return hi ? ((uint32_t)ha | ((uint32_t)hb << 16))
              : ((uint32_t)la | ((uint32_t)lb << 16));
}

// ---------------- split fp32 -> bf16 hi/lo ----------------
__global__ __launch_bounds__(256) void split_kernel(
    const float* __restrict__ x, __nv_bfloat16* __restrict__ h,
    __nv_bfloat16* __restrict__ l, int n4)
{
    int i = blockIdx.x * 256 + threadIdx.x;
    if (i >= n4) return;
    float4 v = ((const float4*)x)[i];
    ull hw, lw; split4(v, hw, lw);
    ((ull*)h)[i] = hw;
    ((ull*)l)[i] = lw;
}

// ---------------- merged weight split (4 matrices, one launch) ----------------
__global__ __launch_bounds__(256) void split_w_kernel(
    const float* __restrict__ Wq, const float* __restrict__ Wk,
    const float* __restrict__ Wv, const float* __restrict__ Wo,
    __nv_bfloat16* __restrict__ qh, __nv_bfloat16* __restrict__ ql,
    __nv_bfloat16* __restrict__ kh, __nv_bfloat16* __restrict__ kl,
    __nv_bfloat16* __restrict__ vh, __nv_bfloat16* __restrict__ vl,
    __nv_bfloat16* __restrict__ oh, __nv_bfloat16* __restrict__ ol,
    int n4)
{
    int i = blockIdx.x * 256 + threadIdx.x;
    if (i >= n4) return;
    const int w = blockIdx.y;
    const float* src = (w == 0) ? Wq : (w == 1) ? Wk : (w == 2) ? Wv : Wo;
    __nv_bfloat16* h = (w == 0) ? qh : (w == 1) ? kh : (w == 2) ? vh : oh;
    __nv_bfloat16* l = (w == 0) ? ql : (w == 1) ? kl : (w == 2) ? vl : ol;
    float4 v = ((const float4*)src)[i];
    ull hw, lw; split4(v, hw, lw);
    ((ull*)h)[i] = hw;
    ((ull*)l)[i] = lw;
}

// ---------------- HMMA split-bf16 GEMM body (2-slot cp.async, frag reuse) ----
__device__ __forceinline__ void tgemm_body(
    const __nv_bfloat16* __restrict__ Ah, const __nv_bfloat16* __restrict__ Al,
    const __nv_bfloat16* __restrict__ Bh, const __nv_bfloat16* __restrict__ Bl,
    const float* __restrict__ bias, float* __restrict__ C,
    __nv_bfloat16* __restrict__ Ch, __nv_bfloat16* __restrict__ Cl,
    int bm, int bn, char* tgs)
{
    const uint32_t sBase = smem_u32(tgs);
    const int tid = threadIdx.x, lane = tid & 31, wid = tid >> 5;
    const int wm = wid & 1, wn = wid >> 1;

    float d[4][4][4];
#pragma unroll
    for (int mt = 0; mt < 4; mt++)
#pragma unroll
        for (int nt = 0; nt < 4; nt++)
#pragma unroll
            for (int e = 0; e < 4; e++) d[mt][nt][e] = 0.f;

    uint32_t a_rel[4], b_rel[2];
    {
        const int ar = lane & 15, akoff = (lane >> 4) * 8;
#pragma unroll
        for (int mt = 0; mt < 4; mt++)
            a_rel[mt] = ((wm * 64 + mt * 16 + ar) * 40 + akoff) * 2;
        const int nrow = wn * 32 + ((lane >> 4) << 3) + (lane & 7);
        const int khalf = (lane >> 3) & 1;
#pragma unroll
        for (int np = 0; np < 2; np++)
            b_rel[np] = ((nrow + np * 16) * 40 + khalf * 8) * 2;
    }

    const int srow0 = tid >> 2,         sc0 = tid & 3;
    const int srow1 = (tid + 256) >> 2, sc1 = (tid + 256) & 3;
    const uint32_t st0 = srow0 * 80 + sc0 * 16;
    const uint32_t st1 = srow1 * 80 + sc1 * 16;

    auto issue = [&](int kt, int slot) {
        const uint32_t b0 = sBase + slot * TG_SLOT;
        const size_t ga0 = (size_t)(bm + srow0) * Dd + kt * 32 + sc0 * 8;
        const size_t ga1 = (size_t)(bm + srow1) * Dd + kt * 32 + sc1 * 8;
        const size_t gb0 = (size_t)(bn + srow0) * Dd + kt * 32 + sc0 * 8;
        const size_t gb1 = (size_t)(bn + srow1) * Dd + kt * 32 + sc1 * 8;
        cp16(b0 + st0,               Ah + ga0);
        cp16(b0 + st1,               Ah + ga1);
        cp16(b0 + TG_TILE + st0,     Al + ga0);
        cp16(b0 + TG_TILE + st1,     Al + ga1);
        cp16(b0 + 2 * TG_TILE + st0, Bh + gb0);
        cp16(b0 + 2 * TG_TILE + st1, Bh + gb1);
        cp16(b0 + 3 * TG_TILE + st0, Bl + gb0);
        cp16(b0 + 3 * TG_TILE + st1, Bl + gb1);
        asm volatile("cp.async.commit_group;");
    };

    issue(0, 0);
#pragma unroll 1
    for (int s = 0; s < 16; s++) {
        if (s + 1 < 16) {
            issue(s + 1, (s + 1) & 1);
            asm volatile("cp.async.wait_group 1;");
        } else {
            asm volatile("cp.async.wait_group 0;");
        }
        __syncthreads();
        const uint32_t slotB = sBase + (s & 1) * TG_SLOT;
#pragma unroll
        for (int ks = 0; ks < 2; ks++) {
            uint32_t aH[4][4], aL[4][4], bH[2][4], bX[2][4];
            // pass 0: Ah x Bh
#pragma unroll
            for (int mt = 0; mt < 4; mt++)
                ldsm_x4(aH[mt], slotB + a_rel[mt] + ks * 32);
#pragma unroll
            for (int np = 0; np < 2; np++)
                ldsm_x4(bH[np], slotB + 2 * TG_TILE + b_rel[np] + ks * 32);
#pragma unroll
            for (int mt = 0; mt < 4; mt++)
#pragma unroll
                for (int nt = 0; nt < 4; nt++)
                    mma_bf16(d[mt][nt], aH[mt],
                             bH[nt >> 1][(nt & 1) * 2], bH[nt >> 1][(nt & 1) * 2 + 1]);
            // pass 1: Ah x Bl (reuse aH)
#pragma unroll
            for (int np = 0; np < 2; np++)
                ldsm_x4(bX[np], slotB + 3 * TG_TILE + b_rel[np] + ks * 32);
#pragma unroll
            for (int mt = 0; mt < 4; mt++)
#pragma unroll
                for (int nt = 0; nt < 4; nt++)
                    mma_bf16(d[mt][nt], aH[mt],
                             bX[nt >> 1][(nt & 1) * 2], bX[nt >> 1][(nt & 1) * 2 + 1]);
            // pass 2: Al x Bh (reuse bH)
#pragma unroll
            for (int mt = 0; mt < 4; mt++)
                ldsm_x4(aL[mt], slotB + TG_TILE + a_rel[mt] + ks * 32);
#pragma unroll
            for (int mt = 0; mt < 4; mt++)
#pragma unroll
                for (int nt = 0; nt < 4; nt++)
                    mma_bf16(d[mt][nt], aL[mt],
                             bH[nt >> 1][(nt & 1) * 2], bH[nt >> 1][(nt & 1) * 2 + 1]);
        }
        __syncthreads();
    }

#pragma unroll
    for (int mt = 0; mt < 4; mt++) {
        const int r0 = bm + wm * 64 + mt * 16 + (lane >> 2);
#pragma unroll
        for (int nt = 0; nt < 4; nt++) {
            const int c0 = bn + wn * 32 + nt * 8 + (lane & 3) * 2;
            const float b0 = bias[c0], b1 = bias[c0 + 1];
            const float o00 = d[mt][nt][0] + b0, o01 = d[mt][nt][1] + b1;
            const float o10 = d[mt][nt][2] + b0, o11 = d[mt][nt][3] + b1;
            if (C) {
                *(float2*)&C[(size_t)r0 * Dd + c0] = make_float2(o00, o01);
                *(float2*)&C[(size_t)(r0 + 8) * Dd + c0] = make_float2(o10, o11);
            } else {
                unsigned short* ch = (unsigned short*)Ch;
                unsigned short* cl = (unsigned short*)Cl;
                *(uint32_t*)&ch[(size_t)r0 * Dd + c0] = pack2(o00, o01, true);
                *(uint32_t*)&cl[(size_t)r0 * Dd + c0] = pack2(o00, o01, false);
                *(uint32_t*)&ch[(size_t)(r0 + 8) * Dd + c0] = pack2(o10, o11, true);
                *(uint32_t*)&cl[(size_t)(r0 + 8) * Dd + c0] = pack2(o10, o11, false);
            }
        }
    }
}

__global__ __launch_bounds__(256, 2) void tgemm_mma_kernel(
    const __nv_bfloat16* __restrict__ Ah, const __nv_bfloat16* __restrict__ Al,
    const __nv_bfloat16* __restrict__ Bh, const __nv_bfloat16* __restrict__ Bl,
    const float* __restrict__ bias, float* __restrict__ C)
{
    extern __shared__ char tgs[];
    tgemm_body(Ah, Al, Bh, Bl, bias, C, nullptr, nullptr,
               blockIdx.y * 128, blockIdx.x * 128, tgs);
}

__global__ __launch_bounds__(256, 2) void tgemm_qkv_kernel(
    const __nv_bfloat16* __restrict__ Ah, const __nv_bfloat16* __restrict__ Al,
    const __nv_bfloat16* __restrict__ Bqh, const __nv_bfloat16* __restrict__ Bql,
    const __nv_bfloat16* __restrict__ Bkh, const __nv_bfloat16* __restrict__ Bkl,
    const __nv_bfloat16* __restrict__ Bvh, const __nv_bfloat16* __restrict__ Bvl,
    const float* __restrict__ bq, const float* __restrict__ bk,
    const float* __restrict__ bv,
    __nv_bfloat16* __restrict__ Qh, __nv_bfloat16* __restrict__ Ql,
    float* __restrict__ Ck, float* __restrict__ Cv)
{
    extern __shared__ char tgs[];
    const int gsel = blockIdx.x >> 2;
    const int bn = (blockIdx.x & 3) * 128;
    const __nv_bfloat16* Bh = (gsel == 0) ? Bqh : (gsel == 1) ? Bkh : Bvh;
    const __nv_bfloat16* Bl = (gsel == 0) ? Bql : (gsel == 1) ? Bkl : Bvl;
    const float* bias = (gsel == 0) ? bq : (gsel == 1) ? bk : bv;
    float* C = (gsel == 0) ? nullptr : (gsel == 1) ? Ck : Cv;
    tgemm_body(Ah, Al, Bh, Bl, bias, C,
               (gsel == 0) ? Qh : nullptr, (gsel == 0) ? Ql : nullptr,
               blockIdx.y * 128, bn, tgs);
}

// ---------------- l2norm + beta -> split K directly ----------------
__global__ __launch_bounds__(128) void norm_beta_kernel(
    const float* __restrict__ Kd, const float* __restrict__ wb,
    const float* __restrict__ bb, float* __restrict__ Beta,
    __nv_bfloat16* __restrict__ Kh, __nv_bfloat16* __restrict__ Kl)
{
    const int row = blockIdx.x, tid = threadIdx.x;
    float4 v = ((const float4*)(Kd + (size_t)row * Dd))[tid];
    float ss = v.x * v.x + v.y * v.y + v.z * v.z + v.w * v.w;
#pragma unroll
    for (int o = 16; o; o >>= 1) ss += __shfl_xor_sync(0xffffffffu, ss, o);
    __shared__ float red1[4];
    if ((tid & 31) == 0) red1[tid >> 5] = ss;
    __syncthreads();
    const float inv = 1.0f / fmaxf(sqrtf(red1[0] + red1[1] + red1[2] + red1[3]), 1e-12f);
    float4 w = ((const float4*)wb)[tid];
    float bd = v.x * w.x + v.y * w.y + v.z * w.z + v.w * w.w;
#pragma unroll
    for (int o = 16; o; o >>= 1) bd += __shfl_xor_sync(0xffffffffu, bd, o);
    __shared__ float red2[4];
    if ((tid & 31) == 0) red2[tid >> 5] = bd;
    __syncthreads();
    v.x *= inv; v.y *= inv; v.z *= inv; v.w *= inv;
    ull hw, lw; split4(v, hw, lw);
    ((ull*)(Kh + (size_t)row * Dd))[tid] = hw;
    ((ull*)(Kl + (size_t)row * Dd))[tid] = lw;
    if (tid == 0) {
        const float z = (red2[0] + red2[1] + red2[2] + red2[3]) * inv + bb[0];
        Beta[row] = 1.0f / (1.0f + expf(-z));
    }
}

// ---------------- chunk_ag: A,G via mma + T = (I+A)^-1 ----------------
__global__ __launch_bounds__(256) void chunk_ag_mma_kernel(
    const __nv_bfloat16* __restrict__ KhG, const __nv_bfloat16* __restrict__ KlG,
    const __nv_bfloat16* __restrict__ QhG, const __nv_bfloat16* __restrict__ QlG,
    const float* __restrict__ Betad,
    __nv_bfloat16* __restrict__ ThG, __nv_bfloat16* __restrict__ TlG,
    __nv_bfloat16* __restrict__ GhG, __nv_bfloat16* __restrict__ GlG)
{
    extern __shared__ char ags[];
    char* pKh = ags;               char* pKl = ags + AG_TILE;
    char* pQh = ags + 2 * AG_TILE; char* pQl = ags + 3 * AG_TILE;
    float* As = (float*)(ags + AG_AS);
    float* Tm = (float*)(ags + AG_TM);
    float* Ws = (float*)(ags + AG_WS);
    const uint32_t khB = smem_u32(pKh), klB = smem_u32(pKl);
    const uint32_t qhB = smem_u32(pQh), qlB = smem_u32(pQl);

    const int c = blockIdx.x, b = blockIdx.y;
    const int r0g = b * Tt + c * CH;
    const int tid = threadIdx.x, lane = tid & 31, wid = tid >> 5;
    const int mat = wid >> 2, mb = wid & 3;
    const int fr = lane >> 2, fc = 2 * (lane & 3);

    float cacc[8][4];
#pragma unroll
    for (int nb = 0; nb < 8; nb++)
#pragma unroll
        for (int e = 0; e < 4; e++) cacc[nb][e] = 0.f;

#pragma unroll 1
    for (int jt = 0; jt < 4; jt++) {
        if (jt) __syncthreads();
#pragma unroll
        for (int n = 0; n < 4; n++) {
            const int e = tid + n * 256;
            const int t = e >> 4, cc = e & 15;
            const uint32_t off = (uint32_t)t * 272u
                + ((uint32_t)(cc ^ ((t >> 3) & 1)) << 4);
            const size_t g = (size_t)(r0g + t) * Dd + jt * 128 + cc * 8;
            cp16(khB + off, KhG + g);
            cp16(klB + off, KlG + g);
            cp16(qhB + off, QhG + g);
            cp16(qlB + off, QlG + g);
        }
        asm volatile("cp.async.commit_group;");
        asm volatile("cp.async.wait_group 0;");
        __syncthreads();
#pragma unroll
        for (int p = 0; p < 3; p++) {
            const uint32_t aT = mat ? (p < 2 ? qhB : qlB) : (p < 2 ? khB : klB);
            const uint32_t bT = (p == 1) ? klB : khB;
#pragma unroll
            for (int k = 0; k < 8; k++) {
                uint32_t a[4];
                {
                    const int r = mb * 16 + (lane & 15);
                    const int cc = k * 2 + (lane >> 4);
                    ldsm_x4(a, aT + r * 272u + ((uint32_t)(cc ^ ((r >> 3) & 1)) << 4));
                }
#pragma unroll
                for (int nb4 = 0; nb4 < 4; nb4++) {
                    uint32_t bb[4];
                    const int r = nb4 * 16 + (lane & 7) + ((lane >> 4) << 3);
                    const int cc = k * 2 + ((lane >> 3) & 1);
                    ldsm_x4(bb, bT + r * 272u + ((uint32_t)(cc ^ ((r >> 3) & 1)) << 4));
                    mma_bf16(cacc[nb4 * 2 + 0], a, bb[0], bb[1]);
                    mma_bf16(cacc[nb4 * 2 + 1], a, bb[2], bb[3]);
                }
            }
        }
    }
    __syncthreads();

    const size_t gbase = ((size_t)(b * NCH) + c) * (CH * CH);
    const int t0r = mb * 16 + fr, t1r = t0r + 8;
    if (mat == 0) {
        const float bt0 = Betad[r0g + t0r], bt1 = Betad[r0g + t1r];
#pragma unroll
        for (int nb = 0; nb < 8; nb++) {
            const int j = nb * 8 + fc;
            float2 o0, o1;
            o0.x = (j     < t0r) ? bt0 * cacc[nb][0] : 0.f;
            o0.y = (j + 1 < t0r) ? bt0 * cacc[nb][1] : 0.f;
            o1.x = (j     < t1r) ? bt1 * cacc[nb][2] : 0.f;
            o1.y = (j + 1 < t1r) ? bt1 * cacc[nb][3] : 0.f;
            *(float2*)&As[t0r * 66 + j] = o0;
            *(float2*)&As[t1r * 66 + j] = o1;
        }
    } else {
        unsigned short* Gh = (unsigned short*)GhG;
        unsigned short* Gl = (unsigned short*)GlG;
#pragma unroll
        for (int nb = 0; nb < 8; nb++) {
            const int j = nb * 8 + fc;
            float v00 = (j     <= t0r) ? cacc[nb][0] : 0.f;
            float v01 = (j + 1 <= t0r) ? cacc[nb][1] : 0.f;
            float v10 = (j     <= t1r) ? cacc[nb][2] : 0.f;
            float v11 = (j + 1 <= t1r) ? cacc[nb][3] : 0.f;
            *(uint32_t*)&Gh[gbase + t0r * 64 + j] = pack2(v00, v01, true);
            *(uint32_t*)&Gl[gbase + t0r * 64 + j] = pack2(v00, v01, false);
            *(uint32_t*)&Gh[gbase + t1r * 64 + j] = pack2(v10, v11, true);
            *(uint32_t*)&Gl[gbase + t1r * 64 + j] = pack2(v10, v11, false);
        }
    }
    for (int e = tid; e < 64 * 66; e += 256) Tm[e] = 0.f;
    __syncthreads();

    // diagonal 16x16 inversions
    if (wid < 4) {
        const int r = lane & 15;
        float Lr[16], val[16];
#pragma unroll
        for (int j = 0; j < 16; j++) Lr[j] = As[(wid * 16 + r) * 66 + wid * 16 + j];
#pragma unroll
        for (int cc = 0; cc < 16; cc++) val[cc] = (r == cc) ? 1.f : 0.f;
#pragma unroll
        for (int j = 0; j < 15; j++) {
#pragma unroll
            for (int cc = 0; cc < 16; cc++) {
                if (cc <= j) {
                    float tjc = __shfl_sync(0xffffffffu, val[cc], j);
                    if (r > j) val[cc] -= Lr[j] * tjc;
                }
            }
        }
        if (lane < 16) {
#pragma unroll
            for (int cc = 0; cc < 16; cc++)
                Tm[(wid * 16 + r) * 66 + wid * 16 + cc] = val[cc];
        }
    }
    __syncthreads();

    // off-diagonal blocks
    {
        const int oi[6] = {1, 2, 3, 2, 3, 3};
        const int oj[6] = {0, 0, 0, 1, 1, 2};
        const int r = tid >> 4, cc = tid & 15;
#pragma unroll 1
        for (int s6 = 0; s6 < 6; s6++) {
            const int bi = oi[s6], bj = oj[s6];
            float w = 0.f;
            for (int k = bj; k < bi; k++)
#pragma unroll
                for (int m = 0; m < 16; m++)
                    w += As[(bi * 16 + r) * 66 + k * 16 + m] *
                         Tm[(k * 16 + m) * 66 + bj * 16 + cc];
            Ws[r * 17 + cc] = w;
            __syncthreads();
            float t2 = 0.f;
#pragma unroll
            for (int m = 0; m < 16; m++)
                t2 += Tm[(bi * 16 + r) * 66 + bi * 16 + m] * Ws[m * 17 + cc];
            Tm[(bi * 16 + r) * 66 + bj * 16 + cc] = -t2;
            __syncthreads();
        }
    }

    {
        unsigned short* Th = (unsigned short*)ThG;
        unsigned short* Tl = (unsigned short*)TlG;
        for (int e = tid; e < 2048; e += 256) {
            const int t = e >> 5, j = (e & 31) * 2;
            *(uint32_t*)&Th[gbase + t * 64 + j] =
                pack2(Tm[t * 66 + j], Tm[t * 66 + j + 1], true);
            *(uint32_t*)&Tl[gbase + t * 64 + j] =
                pack2(Tm[t * 66 + j], Tm[t * 66 + j + 1], false);
        }
    }
}

// ---------------- chunked delta-rule scan: all-mma, frag reuse ----------------
__global__ __launch_bounds__(256) void scan_kernel(
    const __nv_bfloat16* __restrict__ KhG, const __nv_bfloat16* __restrict__ KlG,
    const __nv_bfloat16* __restrict__ QhG, const __nv_bfloat16* __restrict__ QlG,
    const __nv_bfloat16* __restrict__ ThG, const __nv_bfloat16* __restrict__ TlG,
    const __nv_bfloat16* __restrict__ GhG, const __nv_bfloat16* __restrict__ GlG,
    const float* __restrict__ Vd, const float* __restrict__ Betad,
    __nv_bfloat16* __restrict__ OhG, __nv_bfloat16* __restrict__ OlG)
{
    extern __shared__ char sraw[];
    float* S     = (float*)(sraw + OFF_S);
    float* Um    = (float*)(sraw + OFF_UM);
    float* QSm   = (float*)(sraw + OFF_QS);
    float* Vb    = (float*)(sraw + OFF_VB);
    float* betas = (float*)(sraw + OFF_BETA);
    char* pKh = sraw + OFF_KH;  char* pKl = sraw + OFF_KL;
    char* pQh = sraw + OFF_QH;  char* pQl = sraw + OFF_QL;
    char* pSh = sraw + OFF_SH;  char* pSl = sraw + OFF_SL;
    char* pUh = sraw + OFF_UH;  char* pUl = sraw + OFF_UL;
    char* pTh = sraw + OFF_TH;  char* pTl = sraw + OFF_TL;
    char* pGh = sraw + OFF_GH;  char* pGl = sraw + OFF_GL;
    const uint32_t khB = smem_u32(pKh), klB = smem_u32(pKl);
    const uint32_t qhB = smem_u32(pQh), qlB = smem_u32(pQl);
    const uint32_t shB = smem_u32(pSh), slB = smem_u32(pSl);
    const uint32_t uhB = smem_u32(pUh), ulB = smem_u32(pUl);
    const uint32_t thB = smem_u32(pTh), tlB = smem_u32(pTl);
    const uint32_t ghB = smem_u32(pGh), glB = smem_u32(pGl);

    const int b = blockIdx.y;
    const int i0 = blockIdx.x * DV;
    const int tid = threadIdx.x;
    const int lane = tid & 31, wid = tid >> 5;
    const int fr = lane >> 2, fc = 2 * (lane & 3);

    for (int e = tid; e < 32 * 520; e += 256) S[e] = 0.f;
    __syncthreads();

    for (int c = 0; c < NCH; c++) {
        const int r0g = b * Tt + c * CH;
        const size_t gbase = ((size_t)(b * NCH) + c) * (CH * CH);

        // issue T/G staging (group) and phase-A jt=0 K/Q staging (group)
#pragma unroll
        for (int n = 0; n < 2; n++) {
            const int e = tid + n * 256;
            const int r = e >> 3, cc = e & 7;
            const uint32_t off = (uint32_t)r * 144u
                + ((uint32_t)(cc ^ ((r >> 3) & 1)) << 4);
            const size_t g = gbase + r * 64 + cc * 8;
            cp16(thB + off, ThG + g);
            cp16(tlB + off, TlG + g);
            cp16(ghB + off, GhG + g);
            cp16(glB + off, GlG + g);
        }
        asm volatile("cp.async.commit_group;");
#pragma unroll
        for (int n = 0; n < 4; n++) {
            const int e = tid + n * 256;
            const int t = e >> 4, cc = e & 15;
            const uint32_t off = (uint32_t)t * 272u
                + ((uint32_t)(cc ^ ((t >> 3) & 1)) << 4);
            const size_t g = (size_t)(r0g + t) * Dd + cc * 8;   // jt = 0
            cp16(khB + off, KhG + g);
            cp16(klB + off, KlG + g);
            cp16(qhB + off, QhG + g);
            cp16(qlB + off, QlG + g);
        }
        asm volatile("cp.async.commit_group;");
        for (int e = tid; e < CH * DV; e += 256) {
            const int t = e >> 5, i = e & 31;
            Vb[t * 34 + i] = Vd[(size_t)(r0g + t) * Dd + i0 + i];
        }
        if (tid < 64) betas[tid] = Betad[r0g + tid];

        // ---- Phase A ----
        const int mat = wid >> 2;
        const int mb  = wid & 3;
        float cacc[4][4];
#pragma unroll
        for (int nb = 0; nb < 4; nb++)
#pragma unroll
            for (int e = 0; e < 4; e++) cacc[nb][e] = 0.f;

#pragma unroll 1
        for (int jt = 0; jt < 4; jt++) {
            if (jt > 0) {
#pragma unroll
                for (int n = 0; n < 4; n++) {
                    const int e = tid + n * 256;
                    const int t = e >> 4, cc = e & 15;
                    const uint32_t off = (uint32_t)t * 272u
                        + ((uint32_t)(cc ^ ((t >> 3) & 1)) << 4);
                    const size_t g = (size_t)(r0g + t) * Dd + jt * 128 + cc * 8;
                    cp16(khB + off, KhG + g);
                    cp16(klB + off, KlG + g);
                    cp16(qhB + off, QhG + g);
                    cp16(qlB + off, QlG + g);
                }
                asm volatile("cp.async.commit_group;");
            }
#pragma unroll
            for (int n = 0; n < 4; n++) {
                const int e = tid + n * 256;
                const int i = e >> 5, d4 = (e & 31) * 4;
                float4 v = *(const float4*)&S[i * 520 + jt * 128 + d4];
                ull hw, lw; split4(v, hw, lw);
                const uint32_t off = (uint32_t)i * 272u
                    + ((uint32_t)((d4 >> 3) ^ ((i >> 3) & 1)) << 4) + (d4 & 7) * 2;
                *(ull*)(pSh + off) = hw;
                *(ull*)(pSl + off) = lw;
            }
            asm volatile("cp.async.wait_group 0;");
            __syncthreads();
            const uint32_t aHi = mat ? qhB : khB;
            const uint32_t aLo = mat ? qlB : klB;
#pragma unroll
            for (int k = 0; k < 8; k++) {
                uint32_t aH[4], aL[4], bH0[4], bH1[4], bX0[4], bX1[4];
                const int ra = mb * 16 + (lane & 15);
                const int ca = k * 2 + (lane >> 4);
                const uint32_t aoff = ra * 272u + ((uint32_t)(ca ^ ((ra >> 3) & 1)) << 4);
                const int rb = (lane & 7) + ((lane >> 4) << 3);
                const int cb = k * 2 + ((lane >> 3) & 1);
                const uint32_t boff0 = rb * 272u + ((uint32_t)(cb ^ ((rb >> 3) & 1)) << 4);
                const int rb2 = rb + 16;
                const uint32_t boff1 = rb2 * 272u + ((uint32_t)(cb ^ ((rb2 >> 3) & 1)) << 4);
                // p0: hi-a x Sh
                ldsm_x4(aH, aHi + aoff);
                ldsm_x4(bH0, shB + boff0);
                ldsm_x4(bH1, shB + boff1);
                mma_bf16(cacc[0], aH, bH0[0], bH0[1]);
                mma_bf16(cacc[1], aH, bH0[2], bH0[3]);
                mma_bf16(cacc[2], aH, bH1[0], bH1[1]);
                mma_bf16(cacc[3], aH, bH1[2], bH1[3]);
                // p1: hi-a x Sl (reuse aH)
                ldsm_x4(bX0, slB + boff0);
                ldsm_x4(bX1, slB + boff1);
                mma_bf16(cacc[0], aH, bX0[0], bX0[1]);
                mma_bf16(cacc[1], aH, bX0[2], bX0[3]);
                mma_bf16(cacc[2], aH, bX1[0], bX1[1]);
                mma_bf16(cacc[3], aH, bX1[2], bX1[3]);
                // p2: lo-a x Sh (reuse bH)
                ldsm_x4(aL, aLo + aoff);
                mma_bf16(cacc[0], aL, bH0[0], bH0[1]);
                mma_bf16(cacc[1], aL, bH0[2], bH0[3]);
                mma_bf16(cacc[2], aL, bH1[0], bH1[1]);
                mma_bf16(cacc[3], aL, bH1[2], bH1[3]);
            }
            __syncthreads();
        }

        {
            const int t0r = mb * 16 + fr, t1r = t0r + 8;
            if (mat == 0) {
                const float b0v = betas[t0r], b1v = betas[t1r];
#pragma unroll
                for (int nb = 0; nb < 4; nb++) {
                    const int i = nb * 8 + fc;
                    float2 v0 = *(float2*)&Vb[t0r * 34 + i];
                    float2 v1 = *(float2*)&Vb[t1r * 34 + i];
                    *(float2*)&Um[t0r * 34 + i] =
                        make_float2(b0v * (v0.x - cacc[nb][0]), b0v * (v0.y - cacc[nb][1]));
                    *(float2*)&Um[t1r * 34 + i] =
                        make_float2(b1v * (v1.x - cacc[nb][2]), b1v * (v1.y - cacc[nb][3]));
                }
            } else {
#pragma unroll
                for (int nb = 0; nb < 4; nb++) {
                    const int i = nb * 8 + fc;
                    *(float2*)&QSm[t0r * 34 + i] = make_float2(cacc[nb][0], cacc[nb][1]);
                    *(float2*)&QSm[t1r * 34 + i] = make_float2(cacc[nb][2], cacc[nb][3]);
                }
            }
        }
        __syncthreads();

        // split rhs -> UH/UL transposed
        for (int e = tid; e < 2048; e += 256) {
            const int t = e >> 5, i = e & 31;
            unsigned short uh, ul; split2(Um[t * 34 + i], uh, ul);
            const uint32_t off = (uint32_t)i * 144u
                + ((uint32_t)((t >> 3) ^ ((i >> 3) & 1)) << 4) + (t & 7) * 2;
            *(unsigned short*)(pUh + off) = uh;
            *(unsigned short*)(pUl + off) = ul;
        }
        __syncthreads();

        // Phase B': U = T @ rhs (frag reuse)
        {
            const int mb2 = wid >> 1, nh = wid & 1;
            float du[2][4];
#pragma unroll
            for (int n8 = 0; n8 < 2; n8++)
#pragma unroll
                for (int e = 0; e < 4; e++) du[n8][e] = 0.f;
#pragma unroll
            for (int k = 0; k < 4; k++) {
                uint32_t aH[4], aL[4], bH[4], bX[4];
                const int ra = mb2 * 16 + (lane & 15);
                const int ca = k * 2 + (lane >> 4);
                const uint32_t aoff = ra * 144u + ((uint32_t)(ca ^ ((ra >> 3) & 1)) << 4);
                const int rb = nh * 16 + (lane & 7) + ((lane >> 4) << 3);
                const int cb = k * 2 + ((lane >> 3) & 1);
                const uint32_t boff = rb * 144u + ((uint32_t)(cb ^ ((rb >> 3) & 1)) << 4);
                ldsm_x4(aH, thB + aoff);
                ldsm_x4(bH, uhB + boff);
                mma_bf16(du[0], aH, bH[0], bH[1]);
                mma_bf16(du[1], aH, bH[2], bH[3]);
                ldsm_x4(bX, ulB + boff);
                mma_bf16(du[0], aH, bX[0], bX[1]);
                mma_bf16(du[1], aH, bX[2], bX[3]);
                ldsm_x4(aL, tlB + aoff);
                mma_bf16(du[0], aL, bH[0], bH[1]);
                mma_bf16(du[1], aL, bH[2], bH[3]);
            }
            __syncthreads();
            const int t0r = mb2 * 16 + fr, t1r = t0r + 8;
#pragma unroll
            for (int n8 = 0; n8 < 2; n8++) {
                const int i = nh * 16 + n8 * 8 + fc;
                *(float2*)&Um[t0r * 34 + i] = make_float2(du[n8][0], du[n8][1]);
                *(float2*)&Um[t1r * 34 + i] = make_float2(du[n8][2], du[n8][3]);
            }
        }
        __syncthreads();

        // split U -> UH/UL transposed
        for (int e = tid; e < 2048; e += 256) {
            const int t = e >> 5, i = e & 31;
            unsigned short uh, ul; split2(Um[t * 34 + i], uh, ul);
            const uint32_t off = (uint32_t)i * 144u
                + ((uint32_t)((t >> 3) ^ ((i >> 3) & 1)) << 4) + (t & 7) * 2;
            *(unsigned short*)(pUh + off) = uh;
            *(unsigned short*)(pUl + off) = ul;
        }
        __syncthreads();

        // issue phase-D jt=0 K staging into K slot (overlaps phase C')
#pragma unroll
        for (int n = 0; n < 4; n++) {
            const int e = tid + n * 256;
            const int t = e >> 4, cc = e & 15;
            const uint32_t off = (uint32_t)t * 272u
                + ((uint32_t)(cc ^ ((t >> 3) & 1)) << 4);
            const size_t g = (size_t)(r0g + t) * Dd + cc * 8;    // jt = 0
            cp16(khB + off, KhG + g);
            cp16(klB + off, KlG + g);
        }
        asm volatile("cp.async.commit_group;");

        // Phase C': O = QS + G @ U (frag reuse, split bf16 output)
        {
            const int mb2 = wid >> 1, nh = wid & 1;
            const int t0r = mb2 * 16 + fr, t1r = t0r + 8;
            float du[2][4];
#pragma unroll
            for (int n8 = 0; n8 < 2; n8++) {
                const int i = nh * 16 + n8 * 8 + fc;
                float2 q0 = *(float2*)&QSm[t0r * 34 + i];
                float2 q1 = *(float2*)&QSm[t1r * 34 + i];
                du[n8][0] = q0.x; du[n8][1] = q0.y;
                du[n8][2] = q1.x; du[n8][3] = q1.y;
            }
#pragma unroll
            for (int k = 0; k < 4; k++) {
                uint32_t aH[4], aL[4], bH[4], bX[4];
                const int ra = mb2 * 16 + (lane & 15);
                const int ca = k * 2 + (lane >> 4);
                const uint32_t aoff = ra * 144u + ((uint32_t)(ca ^ ((ra >> 3) & 1)) << 4);
                const int rb = nh * 16 + (lane & 7) + ((lane >> 4) << 3);
                const int cb = k * 2 + ((lane >> 3) & 1);
                const uint32_t boff = rb * 144u + ((uint32_t)(cb ^ ((rb >> 3) & 1)) << 4);
                ldsm_x4(aH, ghB + aoff);
                ldsm_x4(bH, uhB + boff);
                mma_bf16(du[0], aH, bH[0], bH[1]);
                mma_bf16(du[1], aH, bH[2], bH[3]);
                ldsm_x4(bX, ulB + boff);
                mma_bf16(du[0], aH, bX[0], bX[1]);
                mma_bf16(du[1], aH, bX[2], bX[3]);
                ldsm_x4(aL, glB + aoff);
                mma_bf16(du[0], aL, bH[0], bH[1]);
                mma_bf16(du[1], aL, bH[2], bH[3]);
            }
            unsigned short* oh = (unsigned short*)OhG;
            unsigned short* ol = (unsigned short*)OlG;
#pragma unroll
            for (int n8 = 0; n8 < 2; n8++) {
                const int i = nh * 16 + n8 * 8 + fc;
                const size_t g0 = (size_t)(r0g + t0r) * Dd + i0 + i;
                const size_t g1 = (size_t)(r0g + t1r) * Dd + i0 + i;
                *(uint32_t*)&oh[g0] = pack2(du[n8][0], du[n8][1], true);
                *(uint32_t*)&ol[g0] = pack2(du[n8][0], du[n8][1], false);
                *(uint32_t*)&oh[g1] = pack2(du[n8][2], du[n8][3], true);
                *(uint32_t*)&ol[g1] = pack2(du[n8][2], du[n8][3], false);
            }
        }

        // Phase D: S += U^T @ K  (double-buffered staging, frag reuse)
#pragma unroll 1
        for (int jt = 0; jt < 4; jt++) {
            const uint32_t curH = (jt & 1) ? qhB : khB;
            const uint32_t curL = (jt & 1) ? qlB : klB;
            if (jt + 1 < 4) {
                const uint32_t nxtH = ((jt + 1) & 1) ? qhB : khB;
                const uint32_t nxtL = ((jt + 1) & 1) ? qlB : klB;
#pragma unroll
                for (int n = 0; n < 4; n++) {
                    const int e = tid + n * 256;
                    const int t = e >> 4, cc = e & 15;
                    const uint32_t off = (uint32_t)t * 272u
                        + ((uint32_t)(cc ^ ((t >> 3) & 1)) << 4);
                    const size_t g = (size_t)(r0g + t) * Dd + (jt + 1) * 128 + cc * 8;
                    cp16(nxtH + off, KhG + g);
                    cp16(nxtL + off, KlG + g);
                }
                asm volatile("cp.async.commit_group;");
                asm volatile("cp.async.wait_group 1;");
            } else {
                asm volatile("cp.async.wait_group 0;");
            }
            __syncthreads();

            float cf[2][2][4];
            const int dbase = jt * 128 + wid * 16;
#pragma unroll
            for (int mi = 0; mi < 2; mi++)
#pragma unroll
                for (int n8 = 0; n8 < 2; n8++) {
                    const int i0r = mi * 16 + fr;
                    const int col = dbase + n8 * 8 + fc;
                    float2 x0 = *(float2*)&S[i0r * 520 + col];
                    float2 x1 = *(float2*)&S[(i0r + 8) * 520 + col];
                    cf[mi][n8][0] = x0.x; cf[mi][n8][1] = x0.y;
                    cf[mi][n8][2] = x1.x; cf[mi][n8][3] = x1.y;
                }
#pragma unroll
            for (int k = 0; k < 4; k++) {
                uint32_t aH0[4], aH1[4], aL0[4], aL1[4], bH[4], bX[4];
                const int r = lane & 15;
                const int ca = k * 2 + (lane >> 4);
                const uint32_t aoff0 = r * 144u + ((uint32_t)(ca ^ ((r >> 3) & 1)) << 4);
                const int r2 = 16 + (lane & 15);
                const uint32_t aoff1 = r2 * 144u + ((uint32_t)(ca ^ ((r2 >> 3) & 1)) << 4);
                const int tr = k * 16 + (lane & 15);
                const int cb = wid * 2 + (lane >> 4);
                const uint32_t boff = tr * 272u + ((uint32_t)(cb ^ ((tr >> 3) & 1)) << 4);
                // p0: Uh x Kh
                ldsm_x4(aH0, uhB + aoff0);
                ldsm_x4(aH1, uhB + aoff1);
                ldsm_x4t(bH, curH + boff);
                mma_bf16(cf[0][0], aH0, bH[0], bH[1]);
                mma_bf16(cf[0][1], aH0, bH[2], bH[3]);
                mma_bf16(cf[1][0], aH1, bH[0], bH[1]);
                mma_bf16(cf[1][1], aH1, bH[2], bH[3]);
                // p1: Uh x Kl (reuse aH)
                ldsm_x4t(bX, curL + boff);
                mma_bf16(cf[0][0], aH0, bX[0], bX[1]);
                mma_bf16(cf[0][1], aH0, bX[2], bX[3]);
                mma_bf16(cf[1][0], aH1, bX[0], bX[1]);
                mma_bf16(cf[1][1], aH1, bX[2], bX[3]);
                // p2: Ul x Kh (reuse bH)
                ldsm_x4(aL0, ulB + aoff0);
                ldsm_x4(aL1, ulB + aoff1);
                mma_bf16(cf[0][0], aL0, bH[0], bH[1]);
                mma_bf16(cf[0][1], aL0, bH[2], bH[3]);
                mma_bf16(cf[1][0], aL1, bH[0], bH[1]);
                mma_bf16(cf[1][1], aL1, bH[2], bH[3]);
            }
#pragma unroll
            for (int mi = 0; mi < 2; mi++)
#pragma unroll
                for (int n8 = 0; n8 < 2; n8++) {
                    const int i0r = mi * 16 + fr;
                    const int col = dbase + n8 * 8 + fc;
                    *(float2*)&S[i0r * 520 + col] =
                        make_float2(cf[mi][n8][0], cf[mi][n8][1]);
                    *(float2*)&S[(i0r + 8) * 520 + col] =
                        make_float2(cf[mi][n8][2], cf[mi][n8][3]);
                }
            __syncthreads();
        }
    }
}

extern "C" void kernel_launch(void* const* d_in, const int* in_sizes, int n_in,
                              void* d_out, int out_size)
{
    const float* x     = (const float*)d_in[0];
    const float* Wq    = (const float*)d_in[1];
    const float* bq    = (const float*)d_in[2];
    const float* Wk    = (const float*)d_in[3];
    const float* bk    = (const float*)d_in[4];
    const float* Wv    = (const float*)d_in[5];
    const float* bv    = (const float*)d_in[6];
    const float* Wbeta = (const float*)d_in[7];
    const float* bbeta = (const float*)d_in[8];
    const float* Wo    = (const float*)d_in[9];
    const float* bo    = (const float*)d_in[10];
    float* out = (float*)d_out;

    float *pK, *pV, *pBeta;
    cudaGetSymbolAddress((void**)&pK, g_K);
    cudaGetSymbolAddress((void**)&pV, g_V);
    cudaGetSymbolAddress((void**)&pBeta, g_Beta);

    __nv_bfloat16 *pxh, *pxl, *poh, *pol, *pkh, *pkl, *pqh, *pql;
    __nv_bfloat16 *pTh, *pTl, *pGh, *pGl;
    __nv_bfloat16 *pwqh, *pwql, *pwkh, *pwkl, *pwvh, *pwvl, *pwoh, *pwol;
    cudaGetSymbolAddress((void**)&pxh, g_xh);
    cudaGetSymbolAddress((void**)&pxl, g_xl);
    cudaGetSymbolAddress((void**)&poh, g_oh);
    cudaGetSymbolAddress((void**)&pol, g_ol);
    cudaGetSymbolAddress((void**)&pkh, g_kh);
    cudaGetSymbolAddress((void**)&pkl, g_kl);
    cudaGetSymbolAddress((void**)&pqh, g_qh);
    cudaGetSymbolAddress((void**)&pql, g_ql);
    cudaGetSymbolAddress((void**)&pTh, g_Th);
    cudaGetSymbolAddress((void**)&pTl, g_Tl);
    cudaGetSymbolAddress((void**)&pGh, g_Gh);
    cudaGetSymbolAddress((void**)&pGl, g_Gl);
    cudaGetSymbolAddress((void**)&pwqh, g_wqh);
    cudaGetSymbolAddress((void**)&pwql, g_wql);
    cudaGetSymbolAddress((void**)&pwkh, g_wkh);
    cudaGetSymbolAddress((void**)&pwkl, g_wkl);
    cudaGetSymbolAddress((void**)&pwvh, g_wvh);
    cudaGetSymbolAddress((void**)&pwvl, g_wvl);
    cudaGetSymbolAddress((void**)&pwoh, g_woh);
    cudaGetSymbolAddress((void**)&pwol, g_wol);

    cudaFuncSetAttribute(scan_kernel,
                         cudaFuncAttributeMaxDynamicSharedMemorySize, SCAN_SMEM);
    cudaFuncSetAttribute(tgemm_mma_kernel,
                         cudaFuncAttributeMaxDynamicSharedMemorySize, TG_SMEM);
    cudaFuncSetAttribute(tgemm_qkv_kernel,
                         cudaFuncAttributeMaxDynamicSharedMemorySize, TG_SMEM);
    cudaFuncSetAttribute(chunk_ag_mma_kernel,
                         cudaFuncAttributeMaxDynamicSharedMemorySize, AG_SMEM);

    const int nx4 = BT * Dd / 4;
    const int nw4 = Dd * Dd / 4;
    split_kernel<<<(nx4 + 255) / 256, 256>>>(x, pxh, pxl, nx4);
    split_w_kernel<<<dim3((nw4 + 255) / 256, 4), 256>>>(
        Wq, Wk, Wv, Wo, pwqh, pwql, pwkh, pwkl, pwvh, pwvl, pwoh, pwol, nw4);

    tgemm_qkv_kernel<<<dim3(12, BT / 128), 256, TG_SMEM>>>(
        pxh, pxl, pwqh, pwql, pwkh, pwkl, pwvh, pwvl, bq, bk, bv,
        pqh, pql, pK, pV);

    norm_beta_kernel<<<BT, 128>>>(pK, Wbeta, bbeta, pBeta, pkh, pkl);

    chunk_ag_mma_kernel<<<dim3(NCH, Bb), 256, AG_SMEM>>>(
        pkh, pkl, pqh, pql, pBeta, pTh, pTl, pGh, pGl);

    scan_kernel<<<dim3(NVT, Bb), 256, SCAN_SMEM>>>(
        pkh, pkl, pqh, pql, pTh, pTl, pGh, pGl, pV, pBeta, poh, pol);

    tgemm_mma_kernel<<<dim3(4, BT / 128), 256, TG_SMEM>>>(
        poh, pol, pwoh, pwol, bo, out);
}